// round 1
// baseline (speedup 1.0000x reference)
#include <cuda_runtime.h>
#include <math.h>

#define BB 2
#define SS 2048
#define DM 1024
#define NH 16
#define DK 64

// Scratch (device globals; allocation-free)
__device__ float g_q[BB * NH * SS * DK];     // [B,H,S,dk]
__device__ float g_k[BB * NH * SS * DK];
__device__ float g_v[BB * NH * SS * DK];
__device__ float g_ctx[BB * SS * DM];        // [B,S,H*dk]
__device__ float g_bias[NH * (2 * SS - 1)];  // bias per head per relpos

// ---------------------------------------------------------------------------
// Bias table: bias[h][rel + 2047] = rel_bias[bucket(rel)][h]
// ---------------------------------------------------------------------------
__global__ void bias_table_kernel(const float* __restrict__ rel_bias) {
    int h = blockIdx.x;
    for (int idx = threadIdx.x; idx < 2 * SS - 1; idx += blockDim.x) {
        int rel = idx - (SS - 1);          // rel = k - q
        int base = (rel > 0) ? 16 : 0;
        int rp = rel < 0 ? -rel : rel;
        int bucket;
        if (rp < 8) {
            bucket = rp;
        } else {
            // mirror: log(rp/8)/log(16)*8, float32, truncate toward zero
            float v = logf((float)rp * 0.125f) / logf(16.0f) * 8.0f;
            int bb = 8 + (int)v;
            bucket = bb < 15 ? bb : 15;
        }
        g_bias[h * (2 * SS - 1) + idx] = rel_bias[(base + bucket) * NH + h];
    }
}

// ---------------------------------------------------------------------------
// Tiled SGEMM: O = X[M,1024] @ W[1024,1024], BM=BN=128, BK=16, 8x8/thread
// QKV variant scatters into [B,H,S,dk]; out variant writes row-major.
// ---------------------------------------------------------------------------
__global__ void __launch_bounds__(256) gemm_qkv_kernel(
    const float* __restrict__ X,
    const float* __restrict__ Wq,
    const float* __restrict__ Wk,
    const float* __restrict__ Wv)
{
    const float* W = blockIdx.z == 0 ? Wq : (blockIdx.z == 1 ? Wk : Wv);
    float* Out = blockIdx.z == 0 ? g_q : (blockIdx.z == 1 ? g_k : g_v);

    __shared__ float As[16][128];  // As[k][m]
    __shared__ float Bs[16][128];  // Bs[k][n]

    int tid = threadIdx.x;
    int tx = tid & 15, ty = tid >> 4;
    int bm = blockIdx.x * 128, bn = blockIdx.y * 128;

    float acc[8][8] = {};

    for (int k0 = 0; k0 < DM; k0 += 16) {
#pragma unroll
        for (int r = 0; r < 2; r++) {
            int idx4 = tid + 256 * r;
            int m = idx4 >> 2, kq = idx4 & 3;
            float4 va = *(const float4*)(X + (size_t)(bm + m) * DM + k0 + kq * 4);
            As[kq * 4 + 0][m] = va.x;
            As[kq * 4 + 1][m] = va.y;
            As[kq * 4 + 2][m] = va.z;
            As[kq * 4 + 3][m] = va.w;
            int kb = idx4 >> 5, n4 = idx4 & 31;
            *(float4*)&Bs[kb][n4 * 4] =
                *(const float4*)(W + (size_t)(k0 + kb) * DM + bn + n4 * 4);
        }
        __syncthreads();
#pragma unroll
        for (int k = 0; k < 16; k++) {
            float4 a0 = *(const float4*)&As[k][ty * 8];
            float4 a1 = *(const float4*)&As[k][ty * 8 + 4];
            float4 b0 = *(const float4*)&Bs[k][tx * 8];
            float4 b1 = *(const float4*)&Bs[k][tx * 8 + 4];
            float a[8] = {a0.x, a0.y, a0.z, a0.w, a1.x, a1.y, a1.z, a1.w};
            float bv[8] = {b0.x, b0.y, b0.z, b0.w, b1.x, b1.y, b1.z, b1.w};
#pragma unroll
            for (int i = 0; i < 8; i++)
#pragma unroll
                for (int j = 0; j < 8; j++)
                    acc[i][j] = fmaf(a[i], bv[j], acc[i][j]);
        }
        __syncthreads();
    }

#pragma unroll
    for (int i = 0; i < 8; i++) {
        int m = bm + ty * 8 + i;
        int bidx = m >> 11, sRow = m & (SS - 1);
#pragma unroll
        for (int j = 0; j < 8; j++) {
            int n = bn + tx * 8 + j;
            int hh = n >> 6, d = n & 63;
            Out[(((size_t)bidx * NH + hh) * SS + sRow) * DK + d] = acc[i][j];
        }
    }
}

__global__ void __launch_bounds__(256) gemm_out_kernel(
    const float* __restrict__ Wo, float* __restrict__ Out)
{
    const float* X = g_ctx;
    __shared__ float As[16][128];
    __shared__ float Bs[16][128];

    int tid = threadIdx.x;
    int tx = tid & 15, ty = tid >> 4;
    int bm = blockIdx.x * 128, bn = blockIdx.y * 128;

    float acc[8][8] = {};

    for (int k0 = 0; k0 < DM; k0 += 16) {
#pragma unroll
        for (int r = 0; r < 2; r++) {
            int idx4 = tid + 256 * r;
            int m = idx4 >> 2, kq = idx4 & 3;
            float4 va = *(const float4*)(X + (size_t)(bm + m) * DM + k0 + kq * 4);
            As[kq * 4 + 0][m] = va.x;
            As[kq * 4 + 1][m] = va.y;
            As[kq * 4 + 2][m] = va.z;
            As[kq * 4 + 3][m] = va.w;
            int kb = idx4 >> 5, n4 = idx4 & 31;
            *(float4*)&Bs[kb][n4 * 4] =
                *(const float4*)(Wo + (size_t)(k0 + kb) * DM + bn + n4 * 4);
        }
        __syncthreads();
#pragma unroll
        for (int k = 0; k < 16; k++) {
            float4 a0 = *(const float4*)&As[k][ty * 8];
            float4 a1 = *(const float4*)&As[k][ty * 8 + 4];
            float4 b0 = *(const float4*)&Bs[k][tx * 8];
            float4 b1 = *(const float4*)&Bs[k][tx * 8 + 4];
            float a[8] = {a0.x, a0.y, a0.z, a0.w, a1.x, a1.y, a1.z, a1.w};
            float bv[8] = {b0.x, b0.y, b0.z, b0.w, b1.x, b1.y, b1.z, b1.w};
#pragma unroll
            for (int i = 0; i < 8; i++)
#pragma unroll
                for (int j = 0; j < 8; j++)
                    acc[i][j] = fmaf(a[i], bv[j], acc[i][j]);
        }
        __syncthreads();
    }

#pragma unroll
    for (int i = 0; i < 8; i++) {
        int m = bm + ty * 8 + i;
#pragma unroll
        for (int j = 0; j < 8; j++) {
            int n = bn + tx * 8 + j;
            Out[(size_t)m * DM + n] = acc[i][j];
        }
    }
}

// ---------------------------------------------------------------------------
// Flash attention: BQ=BK=64, dk=64, 256 threads (16x16), 4x4 microtiles.
// Smem layouts are k-major transposed so both inner loops are 2x LDS.128.
// ---------------------------------------------------------------------------
#define FST 68  // smem row stride (floats); 68*4B = 272B, 16B aligned

__global__ void __launch_bounds__(256) flash_kernel() {
    extern __shared__ float sm[];
    float* Qt = sm;                 // Qt[d][r]  64 x FST
    float* Kt = sm + 64 * FST;      // Kt[d][c]
    float* Vs = sm + 2 * 64 * FST;  // Vs[c][d]
    float* Pt = sm + 3 * 64 * FST;  // Pt[c][r]
    float* bw = sm + 4 * 64 * FST;  // bias window [127]

    int tid = threadIdx.x;
    int tx = tid & 15, ty = tid >> 4;
    int qt = blockIdx.x, h = blockIdx.y, b = blockIdx.z;
    int bh = b * NH + h;

    const float* Qg = g_q + ((size_t)bh * SS + qt * 64) * DK;
    const float* Kg = g_k + (size_t)bh * SS * DK;
    const float* Vg = g_v + (size_t)bh * SS * DK;

    // Load Q tile transposed: Qt[d][row]
#pragma unroll
    for (int r = 0; r < 4; r++) {
        int idx4 = tid + 256 * r;
        int row = idx4 >> 4, d4 = idx4 & 15;
        float4 v = *(const float4*)(Qg + row * DK + d4 * 4);
        Qt[(d4 * 4 + 0) * FST + row] = v.x;
        Qt[(d4 * 4 + 1) * FST + row] = v.y;
        Qt[(d4 * 4 + 2) * FST + row] = v.z;
        Qt[(d4 * 4 + 3) * FST + row] = v.w;
    }

    float m_[4], l_[4], o[4][4];
#pragma unroll
    for (int i = 0; i < 4; i++) {
        m_[i] = -INFINITY;
        l_[i] = 0.0f;
#pragma unroll
        for (int j = 0; j < 4; j++) o[i][j] = 0.0f;
    }

    for (int kt = 0; kt < SS / 64; kt++) {
        __syncthreads();  // previous tile's consumers done
        // Load K transposed + V natural
#pragma unroll
        for (int r = 0; r < 4; r++) {
            int idx4 = tid + 256 * r;
            int row = idx4 >> 4, d4 = idx4 & 15;
            float4 kv = *(const float4*)(Kg + (size_t)(kt * 64 + row) * DK + d4 * 4);
            Kt[(d4 * 4 + 0) * FST + row] = kv.x;
            Kt[(d4 * 4 + 1) * FST + row] = kv.y;
            Kt[(d4 * 4 + 2) * FST + row] = kv.z;
            Kt[(d4 * 4 + 3) * FST + row] = kv.w;
            *(float4*)(Vs + row * FST + d4 * 4) =
                *(const float4*)(Vg + (size_t)(kt * 64 + row) * DK + d4 * 4);
        }
        // Bias window: rel = (kt-qt)*64 + (c - r), c-r in [-63,63]
        if (tid < 127) {
            int idx = h * (2 * SS - 1) + (kt - qt) * 64 - 63 + tid + (SS - 1);
            bw[tid] = g_bias[idx];
        }
        __syncthreads();

        // S = Q K^T  (4x4 per thread over 64-dim)
        float s[4][4] = {};
#pragma unroll 16
        for (int kk = 0; kk < 64; kk++) {
            float4 a4 = *(const float4*)(Qt + kk * FST + 4 * ty);
            float4 b4 = *(const float4*)(Kt + kk * FST + 4 * tx);
            float a[4] = {a4.x, a4.y, a4.z, a4.w};
            float bv[4] = {b4.x, b4.y, b4.z, b4.w};
#pragma unroll
            for (int i = 0; i < 4; i++)
#pragma unroll
                for (int j = 0; j < 4; j++)
                    s[i][j] = fmaf(a[i], bv[j], s[i][j]);
        }

        // bias + online softmax (rows owned by ty-group, reduce over tx half-warp)
#pragma unroll
        for (int i = 0; i < 4; i++) {
            float mx = -INFINITY;
#pragma unroll
            for (int j = 0; j < 4; j++) {
                s[i][j] += bw[(4 * tx + j) - (4 * ty + i) + 63];
                mx = fmaxf(mx, s[i][j]);
            }
            mx = fmaxf(mx, __shfl_xor_sync(0xffffffffu, mx, 8, 16));
            mx = fmaxf(mx, __shfl_xor_sync(0xffffffffu, mx, 4, 16));
            mx = fmaxf(mx, __shfl_xor_sync(0xffffffffu, mx, 2, 16));
            mx = fmaxf(mx, __shfl_xor_sync(0xffffffffu, mx, 1, 16));
            float mn = fmaxf(m_[i], mx);
            float alpha = __expf(m_[i] - mn);  // exp(-inf)=0 on first tile
            float sum = 0.0f;
#pragma unroll
            for (int j = 0; j < 4; j++) {
                s[i][j] = __expf(s[i][j] - mn);
                sum += s[i][j];
            }
            sum += __shfl_xor_sync(0xffffffffu, sum, 8, 16);
            sum += __shfl_xor_sync(0xffffffffu, sum, 4, 16);
            sum += __shfl_xor_sync(0xffffffffu, sum, 2, 16);
            sum += __shfl_xor_sync(0xffffffffu, sum, 1, 16);
            l_[i] = l_[i] * alpha + sum;
            m_[i] = mn;
#pragma unroll
            for (int j = 0; j < 4; j++) o[i][j] *= alpha;
        }

        // Store P transposed: Pt[c][r]
#pragma unroll
        for (int j = 0; j < 4; j++) {
            float4 pv = make_float4(s[0][j], s[1][j], s[2][j], s[3][j]);
            *(float4*)(Pt + (4 * tx + j) * FST + 4 * ty) = pv;
        }
        __syncthreads();

        // O += P V
#pragma unroll 16
        for (int kk = 0; kk < 64; kk++) {
            float4 p4 = *(const float4*)(Pt + kk * FST + 4 * ty);
            float4 v4 = *(const float4*)(Vs + kk * FST + 4 * tx);
            float p[4] = {p4.x, p4.y, p4.z, p4.w};
            float vv[4] = {v4.x, v4.y, v4.z, v4.w};
#pragma unroll
            for (int i = 0; i < 4; i++)
#pragma unroll
                for (int j = 0; j < 4; j++)
                    o[i][j] = fmaf(p[i], vv[j], o[i][j]);
        }
    }

    // Epilogue: ctx[b][q][h*64 + d] = O / l
    float* Cg = g_ctx + ((size_t)b * SS + qt * 64) * DM + h * DK;
#pragma unroll
    for (int i = 0; i < 4; i++) {
        float inv = 1.0f / l_[i];
        float4 ov = make_float4(o[i][0] * inv, o[i][1] * inv,
                                o[i][2] * inv, o[i][3] * inv);
        *(float4*)(Cg + (size_t)(4 * ty + i) * DM + 4 * tx) = ov;
    }
}

// ---------------------------------------------------------------------------
extern "C" void kernel_launch(void* const* d_in, const int* in_sizes, int n_in,
                              void* d_out, int out_size) {
    const float* hs = (const float*)d_in[0];
    const float* Wq = (const float*)d_in[1];
    const float* Wk = (const float*)d_in[2];
    const float* Wv = (const float*)d_in[3];
    const float* Wo = (const float*)d_in[4];
    const float* rb = (const float*)d_in[5];

    const int FLASH_SMEM = (4 * 64 * FST + 128) * (int)sizeof(float);  // 70144 B
    cudaFuncSetAttribute(flash_kernel,
                         cudaFuncAttributeMaxDynamicSharedMemorySize, FLASH_SMEM);

    bias_table_kernel<<<NH, 256>>>(rb);
    gemm_qkv_kernel<<<dim3((BB * SS) / 128, DM / 128, 3), 256>>>(hs, Wq, Wk, Wv);
    flash_kernel<<<dim3(SS / 64, NH, BB), 256, FLASH_SMEM>>>();
    gemm_out_kernel<<<dim3((BB * SS) / 128, DM / 128), 256>>>(Wo, (float*)d_out);
}

// round 3
// speedup vs baseline: 1.4316x; 1.4316x over previous
#include <cuda_runtime.h>
#include <cuda_bf16.h>
#include <math.h>
#include <stdint.h>

#define BB 2
#define SS 2048
#define DM 1024
#define NH 16
#define DK 64
#define MTOT (BB * SS)  // 4096

// ---------------- device scratch (allocation-free) ----------------
__device__ float g_q[BB * NH * SS * DK];
__device__ float g_k[BB * NH * SS * DK];
__device__ float g_v[BB * NH * SS * DK];
__device__ float g_ctx[MTOT * DM];
__device__ float g_bias[NH * (2 * SS - 1)];
__device__ __nv_bfloat16 g_xh[MTOT * DM];
__device__ __nv_bfloat16 g_xl[MTOT * DM];
__device__ __nv_bfloat16 g_wth[4 * DM * DM];  // W^T hi (K-major, [n][k])
__device__ __nv_bfloat16 g_wtl[4 * DM * DM];  // W^T lo
__device__ __nv_bfloat16 g_ch[MTOT * DM];
__device__ __nv_bfloat16 g_cl[MTOT * DM];

// ---------------- PTX helpers (arch-agnostic: sm_80-era only) ----------------
__device__ __forceinline__ uint32_t smem_u32(const void* p) {
    uint32_t a;
    asm("{ .reg .u64 t; cvta.to.shared.u64 t, %1; cvt.u32.u64 %0, t; }"
        : "=r"(a) : "l"(p));
    return a;
}

__device__ __forceinline__ void cp16(uint32_t dst, const void* src) {
    uint64_t g = __cvta_generic_to_global(src);
    asm volatile("cp.async.cg.shared.global [%0], [%1], 16;" :: "r"(dst), "l"(g));
}
#define CP_COMMIT() asm volatile("cp.async.commit_group;" ::: "memory")
#define CP_WAIT(n)  asm volatile("cp.async.wait_group %0;" :: "n"(n) : "memory")

__device__ __forceinline__ void ldsm_x4(uint32_t* r, uint32_t addr) {
    asm volatile("ldmatrix.sync.aligned.m8n8.x4.shared.b16 {%0,%1,%2,%3}, [%4];"
                 : "=r"(r[0]), "=r"(r[1]), "=r"(r[2]), "=r"(r[3]) : "r"(addr));
}

__device__ __forceinline__ void mma16816(float* c, const uint32_t* a, const uint32_t* b) {
    asm volatile(
        "mma.sync.aligned.m16n8k16.row.col.f32.bf16.bf16.f32 "
        "{%0,%1,%2,%3}, {%4,%5,%6,%7}, {%8,%9}, {%0,%1,%2,%3};"
        : "+f"(c[0]), "+f"(c[1]), "+f"(c[2]), "+f"(c[3])
        : "r"(a[0]), "r"(a[1]), "r"(a[2]), "r"(a[3]), "r"(b[0]), "r"(b[1]));
}

// ---------------------------------------------------------------------------
// Bias table
// ---------------------------------------------------------------------------
__global__ void bias_table_kernel(const float* __restrict__ rel_bias) {
    int h = blockIdx.x;
    for (int idx = threadIdx.x; idx < 2 * SS - 1; idx += blockDim.x) {
        int rel = idx - (SS - 1);
        int base = (rel > 0) ? 16 : 0;
        int rp = rel < 0 ? -rel : rel;
        int bucket;
        if (rp < 8) {
            bucket = rp;
        } else {
            float v = logf((float)rp * 0.125f) / logf(16.0f) * 8.0f;
            int bb = 8 + (int)v;
            bucket = bb < 15 ? bb : 15;
        }
        g_bias[h * (2 * SS - 1) + idx] = rel_bias[(base + bucket) * NH + h];
    }
}

// ---------------------------------------------------------------------------
// Splits: fp32 -> bf16 hi + bf16 lo (residual)
// ---------------------------------------------------------------------------
__global__ void split_kernel(const float4* __restrict__ src_ext, int which) {
    const float4* src = which == 0 ? src_ext : (const float4*)g_ctx;
    __nv_bfloat16* hi = which == 0 ? g_xh : g_ch;
    __nv_bfloat16* lo = which == 0 ? g_xl : g_cl;
    int i = blockIdx.x * blockDim.x + threadIdx.x;
    float4 x = src[i];
    __nv_bfloat16 h0 = __float2bfloat16_rn(x.x);
    __nv_bfloat16 h1 = __float2bfloat16_rn(x.y);
    __nv_bfloat16 h2 = __float2bfloat16_rn(x.z);
    __nv_bfloat16 h3 = __float2bfloat16_rn(x.w);
    __nv_bfloat162 hA, hB, lA, lB;
    hA.x = h0; hA.y = h1; hB.x = h2; hB.y = h3;
    lA.x = __float2bfloat16_rn(x.x - __bfloat162float(h0));
    lA.y = __float2bfloat16_rn(x.y - __bfloat162float(h1));
    lB.x = __float2bfloat16_rn(x.z - __bfloat162float(h2));
    lB.y = __float2bfloat16_rn(x.w - __bfloat162float(h3));
    *(__nv_bfloat162*)(hi + 4 * i) = hA;
    *(__nv_bfloat162*)(hi + 4 * i + 2) = hB;
    *(__nv_bfloat162*)(lo + 4 * i) = lA;
    *(__nv_bfloat162*)(lo + 4 * i + 2) = lB;
}

// transpose + split: Wt[n][k] = split(W[k][n]) for 4 weight matrices (grid.z)
__global__ void tsplit_kernel(const float* __restrict__ W0, const float* __restrict__ W1,
                              const float* __restrict__ W2, const float* __restrict__ W3) {
    __shared__ float t[32][33];
    int z = blockIdx.z;
    const float* W = z == 0 ? W0 : z == 1 ? W1 : z == 2 ? W2 : W3;
    __nv_bfloat16* Th = g_wth + (size_t)z * DM * DM;
    __nv_bfloat16* Tl = g_wtl + (size_t)z * DM * DM;
    int k0 = blockIdx.x * 32, n0 = blockIdx.y * 32;
    int tx = threadIdx.x, ty = threadIdx.y;  // 32 x 8
#pragma unroll
    for (int r = 0; r < 32; r += 8)
        t[ty + r][tx] = W[(size_t)(k0 + ty + r) * DM + n0 + tx];
    __syncthreads();
#pragma unroll
    for (int r = 0; r < 32; r += 8) {
        float x = t[tx][ty + r];
        __nv_bfloat16 h = __float2bfloat16_rn(x);
        size_t o = (size_t)(n0 + ty + r) * DM + k0 + tx;
        Th[o] = h;
        Tl[o] = __float2bfloat16_rn(x - __bfloat162float(h));
    }
}

// ---------------------------------------------------------------------------
// mma.sync bf16x3 GEMM: C[M,N] = A[M,K] @ B^T, A/B split hi+lo bf16, K-major.
// BM=BN=128, BK=32, 8 warps (4x2), warp tile 32x64, cp.async double buffer.
// ---------------------------------------------------------------------------
#define LDK 40                     // smem row pitch in bf16 (80 B; stride 5 x 16B, conflict-free)
#define ABYTES (128 * LDK * 2)     // 10240 per matrix
#define STAGE (4 * ABYTES)         // Ah, Al, Bh, Bl
#define GSMEM (2 * STAGE)          // 81920

__device__ __forceinline__ void gemm_body(
    const __nv_bfloat16* __restrict__ Ah, const __nv_bfloat16* __restrict__ Al,
    const __nv_bfloat16* __restrict__ Bh, const __nv_bfloat16* __restrict__ Bl,
    float* __restrict__ outp, int mode)  // 0/1/2 scatter q/k/v, 3 row-major
{
    extern __shared__ char sm[];
    const uint32_t smb = smem_u32(sm);
    const int tid = threadIdx.x;
    const int wid = tid >> 5, lane = tid & 31;
    const int wm = wid >> 1, wn = wid & 1;
    const int bm = blockIdx.x * 128, bn = blockIdx.y * 128;

    // cp.async source/dst indexing: 512 16B-quads per matrix, 2 per thread
    const int qrow0 = tid >> 1, qk0 = (tid & 1) * 2;  // quads (row, kq) and (row, kq+1)? no:
    // simpler: quad index e = tid + 256*i, row = e>>2, kq = e&3 (kq*8 bf16)
    float acc[2][8][4];
#pragma unroll
    for (int i = 0; i < 2; i++)
#pragma unroll
        for (int j = 0; j < 8; j++)
#pragma unroll
            for (int q = 0; q < 4; q++) acc[i][j][q] = 0.0f;

    // ldmatrix base addresses
    const int rowA = wm * 32 + (lane & 15);
    const int kA = (lane >> 4) * 8;
    const uint32_t aBase = smb + (uint32_t)(rowA * LDK + kA) * 2;
    const int rowB = wn * 64 + ((lane >> 4) & 1) * 8 + (lane & 7);
    const int kB = ((lane >> 3) & 1) * 8;
    const uint32_t bBase = smb + 2 * ABYTES + (uint32_t)(rowB * LDK + kB) * 2;

    // stage loader
    auto load_stage = [&](int c) {
        uint32_t st = smb + (uint32_t)(c & 1) * STAGE;
        int k0 = c * 32;
#pragma unroll
        for (int i = 0; i < 2; i++) {
            int e = tid + 256 * i;
            int row = e >> 2, kq = e & 3;
            uint32_t d = st + (uint32_t)(row * LDK + kq * 8) * 2;
            size_t ga = (size_t)(bm + row) * DM + k0 + kq * 8;
            size_t gb = (size_t)(bn + row) * DM + k0 + kq * 8;
            cp16(d, Ah + ga);
            cp16(d + ABYTES, Al + ga);
            cp16(d + 2 * ABYTES, Bh + gb);
            cp16(d + 3 * ABYTES, Bl + gb);
        }
    };

    load_stage(0);
    CP_COMMIT();

    for (int c = 0; c < 32; ++c) {
        if (c < 31) {
            load_stage(c + 1);
            CP_COMMIT();
            CP_WAIT(1);
        } else {
            CP_WAIT(0);
        }
        __syncthreads();

        uint32_t stoff = (uint32_t)(c & 1) * STAGE;
#pragma unroll
        for (int ks = 0; ks < 2; ++ks) {
            uint32_t koff = stoff + ks * 32;  // 16 bf16 = 32 B
            uint32_t aH[2][4], aL[2][4];
#pragma unroll
            for (int mf = 0; mf < 2; ++mf) {
                ldsm_x4(aH[mf], aBase + koff + mf * (16 * LDK * 2));
                ldsm_x4(aL[mf], aBase + koff + mf * (16 * LDK * 2) + ABYTES);
            }
            uint32_t bH[8][2], bL[8][2];
#pragma unroll
            for (int p = 0; p < 4; ++p) {
                uint32_t t4[4];
                ldsm_x4(t4, bBase + koff + p * (16 * LDK * 2));
                bH[2 * p][0] = t4[0]; bH[2 * p][1] = t4[1];
                bH[2 * p + 1][0] = t4[2]; bH[2 * p + 1][1] = t4[3];
                ldsm_x4(t4, bBase + koff + p * (16 * LDK * 2) + ABYTES);
                bL[2 * p][0] = t4[0]; bL[2 * p][1] = t4[1];
                bL[2 * p + 1][0] = t4[2]; bL[2 * p + 1][1] = t4[3];
            }
#pragma unroll
            for (int mf = 0; mf < 2; ++mf)
#pragma unroll
                for (int nf = 0; nf < 8; ++nf) {
                    mma16816(acc[mf][nf], aH[mf], bH[nf]);
                    mma16816(acc[mf][nf], aH[mf], bL[nf]);
                    mma16816(acc[mf][nf], aL[mf], bH[nf]);
                }
        }
        __syncthreads();
    }

    // Epilogue: c-frag (row g / g+8, cols 2t,2t+1) -> float2 stores
    const int g = lane >> 2, t2 = (lane & 3) * 2;
#pragma unroll
    for (int mf = 0; mf < 2; ++mf) {
#pragma unroll
        for (int nf = 0; nf < 8; ++nf) {
            int n = bn + wn * 64 + nf * 8 + t2;
            int m0 = bm + wm * 32 + mf * 16 + g;
            float2 v0 = make_float2(acc[mf][nf][0], acc[mf][nf][1]);
            float2 v1 = make_float2(acc[mf][nf][2], acc[mf][nf][3]);
            if (mode == 3) {
                *(float2*)(outp + (size_t)m0 * DM + n) = v0;
                *(float2*)(outp + (size_t)(m0 + 8) * DM + n) = v1;
            } else {
                float* Out = mode == 0 ? g_q : (mode == 1 ? g_k : g_v);
                int hh = n >> 6, d = n & 63;
                size_t o0 = (((size_t)(m0 >> 11) * NH + hh) * SS + (m0 & (SS - 1))) * DK + d;
                int m1 = m0 + 8;
                size_t o1 = (((size_t)(m1 >> 11) * NH + hh) * SS + (m1 & (SS - 1))) * DK + d;
                *(float2*)(Out + o0) = v0;
                *(float2*)(Out + o1) = v1;
            }
        }
    }
}

__global__ void __launch_bounds__(256) gemm_qkv_kernel() {
    int z = blockIdx.z;
    gemm_body(g_xh, g_xl, g_wth + (size_t)z * DM * DM, g_wtl + (size_t)z * DM * DM,
              nullptr, z);
}

__global__ void __launch_bounds__(256) gemm_out_kernel(float* __restrict__ out) {
    gemm_body(g_ch, g_cl, g_wth + 3ull * DM * DM, g_wtl + 3ull * DM * DM, out, 3);
}

// ---------------------------------------------------------------------------
// Flash attention (unchanged, known-good): BQ=BK=64, 256 threads, 4x4 tiles
// ---------------------------------------------------------------------------
#define FST 68

__global__ void __launch_bounds__(256) flash_kernel() {
    extern __shared__ float smf[];
    float* Qt = smf;
    float* Kt = smf + 64 * FST;
    float* Vs = smf + 2 * 64 * FST;
    float* Pt = smf + 3 * 64 * FST;
    float* bw = smf + 4 * 64 * FST;

    int tid = threadIdx.x;
    int tx = tid & 15, ty = tid >> 4;
    int qt = blockIdx.x, h = blockIdx.y, b = blockIdx.z;
    int bh = b * NH + h;

    const float* Qg = g_q + ((size_t)bh * SS + qt * 64) * DK;
    const float* Kg = g_k + (size_t)bh * SS * DK;
    const float* Vg = g_v + (size_t)bh * SS * DK;

#pragma unroll
    for (int r = 0; r < 4; r++) {
        int idx4 = tid + 256 * r;
        int row = idx4 >> 4, d4 = idx4 & 15;
        float4 v = *(const float4*)(Qg + row * DK + d4 * 4);
        Qt[(d4 * 4 + 0) * FST + row] = v.x;
        Qt[(d4 * 4 + 1) * FST + row] = v.y;
        Qt[(d4 * 4 + 2) * FST + row] = v.z;
        Qt[(d4 * 4 + 3) * FST + row] = v.w;
    }

    float m_[4], l_[4], o[4][4];
#pragma unroll
    for (int i = 0; i < 4; i++) {
        m_[i] = -INFINITY;
        l_[i] = 0.0f;
#pragma unroll
        for (int j = 0; j < 4; j++) o[i][j] = 0.0f;
    }

    for (int kt = 0; kt < SS / 64; kt++) {
        __syncthreads();
#pragma unroll
        for (int r = 0; r < 4; r++) {
            int idx4 = tid + 256 * r;
            int row = idx4 >> 4, d4 = idx4 & 15;
            float4 kv = *(const float4*)(Kg + (size_t)(kt * 64 + row) * DK + d4 * 4);
            Kt[(d4 * 4 + 0) * FST + row] = kv.x;
            Kt[(d4 * 4 + 1) * FST + row] = kv.y;
            Kt[(d4 * 4 + 2) * FST + row] = kv.z;
            Kt[(d4 * 4 + 3) * FST + row] = kv.w;
            *(float4*)(Vs + row * FST + d4 * 4) =
                *(const float4*)(Vg + (size_t)(kt * 64 + row) * DK + d4 * 4);
        }
        if (tid < 127) {
            int idx = h * (2 * SS - 1) + (kt - qt) * 64 - 63 + tid + (SS - 1);
            bw[tid] = g_bias[idx];
        }
        __syncthreads();

        float s[4][4] = {};
#pragma unroll 16
        for (int kk = 0; kk < 64; kk++) {
            float4 a4 = *(const float4*)(Qt + kk * FST + 4 * ty);
            float4 b4 = *(const float4*)(Kt + kk * FST + 4 * tx);
            float a[4] = {a4.x, a4.y, a4.z, a4.w};
            float bv[4] = {b4.x, b4.y, b4.z, b4.w};
#pragma unroll
            for (int i = 0; i < 4; i++)
#pragma unroll
                for (int j = 0; j < 4; j++)
                    s[i][j] = fmaf(a[i], bv[j], s[i][j]);
        }

#pragma unroll
        for (int i = 0; i < 4; i++) {
            float mx = -INFINITY;
#pragma unroll
            for (int j = 0; j < 4; j++) {
                s[i][j] += bw[(4 * tx + j) - (4 * ty + i) + 63];
                mx = fmaxf(mx, s[i][j]);
            }
            mx = fmaxf(mx, __shfl_xor_sync(0xffffffffu, mx, 8, 16));
            mx = fmaxf(mx, __shfl_xor_sync(0xffffffffu, mx, 4, 16));
            mx = fmaxf(mx, __shfl_xor_sync(0xffffffffu, mx, 2, 16));
            mx = fmaxf(mx, __shfl_xor_sync(0xffffffffu, mx, 1, 16));
            float mn = fmaxf(m_[i], mx);
            float alpha = __expf(m_[i] - mn);
            float sum = 0.0f;
#pragma unroll
            for (int j = 0; j < 4; j++) {
                s[i][j] = __expf(s[i][j] - mn);
                sum += s[i][j];
            }
            sum += __shfl_xor_sync(0xffffffffu, sum, 8, 16);
            sum += __shfl_xor_sync(0xffffffffu, sum, 4, 16);
            sum += __shfl_xor_sync(0xffffffffu, sum, 2, 16);
            sum += __shfl_xor_sync(0xffffffffu, sum, 1, 16);
            l_[i] = l_[i] * alpha + sum;
            m_[i] = mn;
#pragma unroll
            for (int j = 0; j < 4; j++) o[i][j] *= alpha;
        }

#pragma unroll
        for (int j = 0; j < 4; j++) {
            float4 pv = make_float4(s[0][j], s[1][j], s[2][j], s[3][j]);
            *(float4*)(Pt + (4 * tx + j) * FST + 4 * ty) = pv;
        }
        __syncthreads();

#pragma unroll 16
        for (int kk = 0; kk < 64; kk++) {
            float4 p4 = *(const float4*)(Pt + kk * FST + 4 * ty);
            float4 v4 = *(const float4*)(Vs + kk * FST + 4 * tx);
            float p[4] = {p4.x, p4.y, p4.z, p4.w};
            float vv[4] = {v4.x, v4.y, v4.z, v4.w};
#pragma unroll
            for (int i = 0; i < 4; i++)
#pragma unroll
                for (int j = 0; j < 4; j++)
                    o[i][j] = fmaf(p[i], vv[j], o[i][j]);
        }
    }

    float* Cg = g_ctx + ((size_t)b * SS + qt * 64) * DM + h * DK;
#pragma unroll
    for (int i = 0; i < 4; i++) {
        float inv = 1.0f / l_[i];
        float4 ov = make_float4(o[i][0] * inv, o[i][1] * inv,
                                o[i][2] * inv, o[i][3] * inv);
        *(float4*)(Cg + (size_t)(4 * ty + i) * DM + 4 * tx) = ov;
    }
}

// ---------------------------------------------------------------------------
extern "C" void kernel_launch(void* const* d_in, const int* in_sizes, int n_in,
                              void* d_out, int out_size) {
    const float* hs = (const float*)d_in[0];
    const float* Wq = (const float*)d_in[1];
    const float* Wk = (const float*)d_in[2];
    const float* Wv = (const float*)d_in[3];
    const float* Wo = (const float*)d_in[4];
    const float* rb = (const float*)d_in[5];

    const int FLASH_SMEM = (4 * 64 * FST + 128) * (int)sizeof(float);
    cudaFuncSetAttribute(flash_kernel,
                         cudaFuncAttributeMaxDynamicSharedMemorySize, FLASH_SMEM);
    cudaFuncSetAttribute(gemm_qkv_kernel,
                         cudaFuncAttributeMaxDynamicSharedMemorySize, GSMEM);
    cudaFuncSetAttribute(gemm_out_kernel,
                         cudaFuncAttributeMaxDynamicSharedMemorySize, GSMEM);

    bias_table_kernel<<<NH, 256>>>(rb);
    split_kernel<<<(MTOT * DM / 4) / 256, 256>>>((const float4*)hs, 0);
    tsplit_kernel<<<dim3(32, 32, 4), dim3(32, 8)>>>(Wq, Wk, Wv, Wo);
    gemm_qkv_kernel<<<dim3(MTOT / 128, DM / 128, 3), 256, GSMEM>>>();
    flash_kernel<<<dim3(SS / 64, NH, BB), 256, FLASH_SMEM>>>();
    split_kernel<<<(MTOT * DM / 4) / 256, 256>>>(nullptr, 1);
    gemm_out_kernel<<<dim3(MTOT / 128, DM / 128), 256, GSMEM>>>((float*)d_out);
}

// round 4
// speedup vs baseline: 2.9348x; 2.0500x over previous
#include <cuda_runtime.h>
#include <cuda_bf16.h>
#include <math.h>
#include <stdint.h>

#define BB 2
#define SS 2048
#define DM 1024
#define NH 16
#define DK 64
#define MTOT (BB * SS)  // 4096

// ---------------- device scratch (allocation-free) ----------------
__device__ float g_bias[NH * (2 * SS - 1)];
__device__ __nv_bfloat16 g_xh[MTOT * DM];
__device__ __nv_bfloat16 g_xl[MTOT * DM];
__device__ __nv_bfloat16 g_wth[4 * DM * DM];  // W^T hi (K-major, [n][k])
__device__ __nv_bfloat16 g_wtl[4 * DM * DM];  // W^T lo
__device__ __nv_bfloat16 g_ch[MTOT * DM];     // ctx hi/lo (written by flash)
__device__ __nv_bfloat16 g_cl[MTOT * DM];
__device__ __nv_bfloat16 g_qh[BB * NH * SS * DK];
__device__ __nv_bfloat16 g_ql[BB * NH * SS * DK];
__device__ __nv_bfloat16 g_kh[BB * NH * SS * DK];
__device__ __nv_bfloat16 g_kl[BB * NH * SS * DK];
__device__ __nv_bfloat16 g_vh[BB * NH * SS * DK];
__device__ __nv_bfloat16 g_vl[BB * NH * SS * DK];

// ---------------- PTX helpers (arch-agnostic, sm_80-era) ----------------
__device__ __forceinline__ uint32_t smem_u32(const void* p) {
    uint32_t a;
    asm("{ .reg .u64 t; cvta.to.shared.u64 t, %1; cvt.u32.u64 %0, t; }"
        : "=r"(a) : "l"(p));
    return a;
}
__device__ __forceinline__ void cp16(uint32_t dst, const void* src) {
    uint64_t g = __cvta_generic_to_global(src);
    asm volatile("cp.async.cg.shared.global [%0], [%1], 16;" :: "r"(dst), "l"(g));
}
#define CP_COMMIT() asm volatile("cp.async.commit_group;" ::: "memory")
#define CP_WAIT(n)  asm volatile("cp.async.wait_group %0;" :: "n"(n) : "memory")

__device__ __forceinline__ void ldsm_x4(uint32_t* r, uint32_t addr) {
    asm volatile("ldmatrix.sync.aligned.m8n8.x4.shared.b16 {%0,%1,%2,%3}, [%4];"
                 : "=r"(r[0]), "=r"(r[1]), "=r"(r[2]), "=r"(r[3]) : "r"(addr));
}
__device__ __forceinline__ void ldsm_x4_t(uint32_t* r, uint32_t addr) {
    asm volatile("ldmatrix.sync.aligned.m8n8.x4.trans.shared.b16 {%0,%1,%2,%3}, [%4];"
                 : "=r"(r[0]), "=r"(r[1]), "=r"(r[2]), "=r"(r[3]) : "r"(addr));
}
__device__ __forceinline__ void mma16816(float* c, const uint32_t* a, const uint32_t* b) {
    asm volatile(
        "mma.sync.aligned.m16n8k16.row.col.f32.bf16.bf16.f32 "
        "{%0,%1,%2,%3}, {%4,%5,%6,%7}, {%8,%9}, {%0,%1,%2,%3};"
        : "+f"(c[0]), "+f"(c[1]), "+f"(c[2]), "+f"(c[3])
        : "r"(a[0]), "r"(a[1]), "r"(a[2]), "r"(a[3]), "r"(b[0]), "r"(b[1]));
}
__device__ __forceinline__ uint32_t packbf2(float x0, float x1) {
    __nv_bfloat162 t = __floats2bfloat162_rn(x0, x1);
    return *(uint32_t*)&t;
}

// ---------------------------------------------------------------------------
// Bias table
// ---------------------------------------------------------------------------
__global__ void bias_table_kernel(const float* __restrict__ rel_bias) {
    int h = blockIdx.x;
    for (int idx = threadIdx.x; idx < 2 * SS - 1; idx += blockDim.x) {
        int rel = idx - (SS - 1);
        int base = (rel > 0) ? 16 : 0;
        int rp = rel < 0 ? -rel : rel;
        int bucket;
        if (rp < 8) {
            bucket = rp;
        } else {
            float v = logf((float)rp * 0.125f) / logf(16.0f) * 8.0f;
            int bb = 8 + (int)v;
            bucket = bb < 15 ? bb : 15;
        }
        g_bias[h * (2 * SS - 1) + idx] = rel_bias[(base + bucket) * NH + h];
    }
}

// ---------------------------------------------------------------------------
// Split hidden_states: fp32 -> bf16 hi + bf16 lo
// ---------------------------------------------------------------------------
__global__ void split_kernel(const float4* __restrict__ src) {
    int i = blockIdx.x * blockDim.x + threadIdx.x;
    float4 x = src[i];
    __nv_bfloat162 hA = __floats2bfloat162_rn(x.x, x.y);
    __nv_bfloat162 hB = __floats2bfloat162_rn(x.z, x.w);
    __nv_bfloat162 lA = __floats2bfloat162_rn(x.x - __bfloat162float(hA.x),
                                              x.y - __bfloat162float(hA.y));
    __nv_bfloat162 lB = __floats2bfloat162_rn(x.z - __bfloat162float(hB.x),
                                              x.w - __bfloat162float(hB.y));
    *(__nv_bfloat162*)(g_xh + 4 * i) = hA;
    *(__nv_bfloat162*)(g_xh + 4 * i + 2) = hB;
    *(__nv_bfloat162*)(g_xl + 4 * i) = lA;
    *(__nv_bfloat162*)(g_xl + 4 * i + 2) = lB;
}

// transpose + split weights
__global__ void tsplit_kernel(const float* __restrict__ W0, const float* __restrict__ W1,
                              const float* __restrict__ W2, const float* __restrict__ W3) {
    __shared__ float t[32][33];
    int z = blockIdx.z;
    const float* W = z == 0 ? W0 : z == 1 ? W1 : z == 2 ? W2 : W3;
    __nv_bfloat16* Th = g_wth + (size_t)z * DM * DM;
    __nv_bfloat16* Tl = g_wtl + (size_t)z * DM * DM;
    int k0 = blockIdx.x * 32, n0 = blockIdx.y * 32;
    int tx = threadIdx.x, ty = threadIdx.y;
#pragma unroll
    for (int r = 0; r < 32; r += 8)
        t[ty + r][tx] = W[(size_t)(k0 + ty + r) * DM + n0 + tx];
    __syncthreads();
#pragma unroll
    for (int r = 0; r < 32; r += 8) {
        float x = t[tx][ty + r];
        __nv_bfloat16 h = __float2bfloat16_rn(x);
        size_t o = (size_t)(n0 + ty + r) * DM + k0 + tx;
        Th[o] = h;
        Tl[o] = __float2bfloat16_rn(x - __bfloat162float(h));
    }
}

// ---------------------------------------------------------------------------
// mma.sync bf16x3 GEMM: BM=BN=128, BK=32, 8 warps, cp.async double buffer.
// ---------------------------------------------------------------------------
#define LDK 40
#define ABYTES (128 * LDK * 2)
#define STAGE (4 * ABYTES)
#define GSMEM (2 * STAGE)

__device__ __forceinline__ void gemm_body(
    const __nv_bfloat16* __restrict__ Ah, const __nv_bfloat16* __restrict__ Al,
    const __nv_bfloat16* __restrict__ Bh, const __nv_bfloat16* __restrict__ Bl,
    float* __restrict__ outp, int mode)
{
    extern __shared__ char sm[];
    const uint32_t smb = smem_u32(sm);
    const int tid = threadIdx.x;
    const int wid = tid >> 5, lane = tid & 31;
    const int wm = wid >> 1, wn = wid & 1;
    const int bm = blockIdx.x * 128, bn = blockIdx.y * 128;

    float acc[2][8][4];
#pragma unroll
    for (int i = 0; i < 2; i++)
#pragma unroll
        for (int j = 0; j < 8; j++)
#pragma unroll
            for (int q = 0; q < 4; q++) acc[i][j][q] = 0.0f;

    const int rowA = wm * 32 + (lane & 15);
    const uint32_t aBase = smb + (uint32_t)(rowA * LDK + (lane >> 4) * 8) * 2;
    const int rowB = wn * 64 + ((lane >> 4) & 1) * 8 + (lane & 7);
    const uint32_t bBase = smb + 2 * ABYTES +
                           (uint32_t)(rowB * LDK + ((lane >> 3) & 1) * 8) * 2;

    auto load_stage = [&](int c) {
        uint32_t st = smb + (uint32_t)(c & 1) * STAGE;
        int k0 = c * 32;
#pragma unroll
        for (int i = 0; i < 2; i++) {
            int e = tid + 256 * i;
            int row = e >> 2, kq = e & 3;
            uint32_t d = st + (uint32_t)(row * LDK + kq * 8) * 2;
            size_t ga = (size_t)(bm + row) * DM + k0 + kq * 8;
            size_t gb = (size_t)(bn + row) * DM + k0 + kq * 8;
            cp16(d, Ah + ga);
            cp16(d + ABYTES, Al + ga);
            cp16(d + 2 * ABYTES, Bh + gb);
            cp16(d + 3 * ABYTES, Bl + gb);
        }
    };

    load_stage(0);
    CP_COMMIT();

    for (int c = 0; c < 32; ++c) {
        if (c < 31) {
            load_stage(c + 1);
            CP_COMMIT();
            CP_WAIT(1);
        } else {
            CP_WAIT(0);
        }
        __syncthreads();

        uint32_t stoff = (uint32_t)(c & 1) * STAGE;
#pragma unroll
        for (int ks = 0; ks < 2; ++ks) {
            uint32_t koff = stoff + ks * 32;
            uint32_t aH[2][4], aL[2][4];
#pragma unroll
            for (int mf = 0; mf < 2; ++mf) {
                ldsm_x4(aH[mf], aBase + koff + mf * (16 * LDK * 2));
                ldsm_x4(aL[mf], aBase + koff + mf * (16 * LDK * 2) + ABYTES);
            }
            uint32_t bH[8][2], bL[8][2];
#pragma unroll
            for (int p = 0; p < 4; ++p) {
                uint32_t t4[4];
                ldsm_x4(t4, bBase + koff + p * (16 * LDK * 2));
                bH[2 * p][0] = t4[0]; bH[2 * p][1] = t4[1];
                bH[2 * p + 1][0] = t4[2]; bH[2 * p + 1][1] = t4[3];
                ldsm_x4(t4, bBase + koff + p * (16 * LDK * 2) + ABYTES);
                bL[2 * p][0] = t4[0]; bL[2 * p][1] = t4[1];
                bL[2 * p + 1][0] = t4[2]; bL[2 * p + 1][1] = t4[3];
            }
#pragma unroll
            for (int mf = 0; mf < 2; ++mf)
#pragma unroll
                for (int nf = 0; nf < 8; ++nf) {
                    mma16816(acc[mf][nf], aH[mf], bH[nf]);
                    mma16816(acc[mf][nf], aH[mf], bL[nf]);
                    mma16816(acc[mf][nf], aL[mf], bH[nf]);
                }
        }
        __syncthreads();
    }

    const int g = lane >> 2, t2 = (lane & 3) * 2;
#pragma unroll
    for (int mf = 0; mf < 2; ++mf) {
#pragma unroll
        for (int nf = 0; nf < 8; ++nf) {
            int n = bn + wn * 64 + nf * 8 + t2;
            int m0 = bm + wm * 32 + mf * 16 + g;
            int m1 = m0 + 8;
            if (mode == 3) {
                *(float2*)(outp + (size_t)m0 * DM + n) =
                    make_float2(acc[mf][nf][0], acc[mf][nf][1]);
                *(float2*)(outp + (size_t)m1 * DM + n) =
                    make_float2(acc[mf][nf][2], acc[mf][nf][3]);
            } else {
                __nv_bfloat16* Oh = mode == 0 ? g_qh : (mode == 1 ? g_kh : g_vh);
                __nv_bfloat16* Ol = mode == 0 ? g_ql : (mode == 1 ? g_kl : g_vl);
                int hh = n >> 6, d = n & 63;
                size_t o0 = (((size_t)(m0 >> 11) * NH + hh) * SS + (m0 & (SS - 1))) * DK + d;
                size_t o1 = (((size_t)(m1 >> 11) * NH + hh) * SS + (m1 & (SS - 1))) * DK + d;
                float v0 = acc[mf][nf][0], v1 = acc[mf][nf][1];
                float v2 = acc[mf][nf][2], v3 = acc[mf][nf][3];
                __nv_bfloat162 h0 = __floats2bfloat162_rn(v0, v1);
                __nv_bfloat162 l0 = __floats2bfloat162_rn(v0 - __bfloat162float(h0.x),
                                                          v1 - __bfloat162float(h0.y));
                __nv_bfloat162 h1 = __floats2bfloat162_rn(v2, v3);
                __nv_bfloat162 l1 = __floats2bfloat162_rn(v2 - __bfloat162float(h1.x),
                                                          v3 - __bfloat162float(h1.y));
                *(__nv_bfloat162*)(Oh + o0) = h0;
                *(__nv_bfloat162*)(Ol + o0) = l0;
                *(__nv_bfloat162*)(Oh + o1) = h1;
                *(__nv_bfloat162*)(Ol + o1) = l1;
            }
        }
    }
}

__global__ void __launch_bounds__(256, 2) gemm_qkv_kernel() {
    int z = blockIdx.z;
    gemm_body(g_xh, g_xl, g_wth + (size_t)z * DM * DM, g_wtl + (size_t)z * DM * DM,
              nullptr, z);
}
__global__ void __launch_bounds__(256, 2) gemm_out_kernel(float* __restrict__ out) {
    gemm_body(g_ch, g_cl, g_wth + 3ull * DM * DM, g_wtl + 3ull * DM * DM, out, 3);
}

// ---------------------------------------------------------------------------
// Flash attention on mma.sync: BQ=128, BK=64, 8 warps, bf16x3 everywhere.
// ---------------------------------------------------------------------------
#define FPB 144                      // smem pitch bytes (72 bf16); 9x16B -> conflict-free
#define Q_BYTES (128 * FPB)          // 18432
#define KV_BYTES (64 * FPB)          // 9216
#define STG_OFF (2 * Q_BYTES)        // 36864
#define STG_SZ (4 * KV_BYTES)        // 36864
#define BIAS_OFF (STG_OFF + 2 * STG_SZ)  // 110592
#define FSMEM (BIAS_OFF + 2 * 192 * 4)   // 112128

__global__ void __launch_bounds__(256) flash_kernel() {
    extern __shared__ char sm[];
    const uint32_t smb = smem_u32(sm);
    const int tid = threadIdx.x, wid = tid >> 5, lane = tid & 31;
    const int g = lane >> 2, tq = lane & 3;
    const int qt = blockIdx.x, h = blockIdx.y, b = blockIdx.z;
    const int bh = b * NH + h;

    const __nv_bfloat16* Qh = g_qh + ((size_t)bh * SS + qt * 128) * DK;
    const __nv_bfloat16* Ql = g_ql + ((size_t)bh * SS + qt * 128) * DK;
    const __nv_bfloat16* Kh = g_kh + (size_t)bh * SS * DK;
    const __nv_bfloat16* Kl = g_kl + (size_t)bh * SS * DK;
    const __nv_bfloat16* Vh = g_vh + (size_t)bh * SS * DK;
    const __nv_bfloat16* Vl = g_vl + (size_t)bh * SS * DK;
    float* bw = (float*)(sm + BIAS_OFF);

    // Q tile (once): 128 rows x 64 bf16, hi+lo
#pragma unroll
    for (int i = 0; i < 4; i++) {
        int e = tid + 256 * i;
        int row = e >> 3, qd = e & 7;
        uint32_t d = smb + row * FPB + qd * 16;
        cp16(d, Qh + row * DK + qd * 8);
        cp16(d + Q_BYTES, Ql + row * DK + qd * 8);
    }

    auto load_kv = [&](int c) {
        uint32_t st = smb + STG_OFF + (uint32_t)(c & 1) * STG_SZ;
#pragma unroll
        for (int i = 0; i < 2; i++) {
            int e = tid + 256 * i;
            int row = e >> 3, qd = e & 7;
            uint32_t d = st + row * FPB + qd * 16;
            size_t src = (size_t)(c * 64 + row) * DK + qd * 8;
            cp16(d, Kh + src);
            cp16(d + KV_BYTES, Kl + src);
            cp16(d + 2 * KV_BYTES, Vh + src);
            cp16(d + 3 * KV_BYTES, Vl + src);
        }
    };
    auto load_bias = [&](int c) {
        if (tid < 191) {
            int base = h * (2 * SS - 1) + c * 64 - qt * 128 + 1920;
            bw[(c & 1) * 192 + tid] = g_bias[base + tid];
        }
    };

    load_kv(0);
    CP_COMMIT();
    load_bias(0);

    float m_[2] = {-INFINITY, -INFINITY};
    float l_[2] = {0.0f, 0.0f};
    float o[8][4];
#pragma unroll
    for (int j = 0; j < 8; j++)
#pragma unroll
        for (int q = 0; q < 4; q++) o[j][q] = 0.0f;

    const uint32_t aAddr = smb + (uint32_t)(wid * 16 + (lane & 15)) * FPB + (lane >> 4) * 16;
    const uint32_t bRel = (uint32_t)((((lane >> 4) & 1) * 8 + (lane & 7)) * FPB +
                                     ((lane >> 3) & 1) * 16);
    const uint32_t vRel = (uint32_t)((lane & 15) * FPB + (lane >> 4) * 16);
    const int r0 = wid * 16 + g;

    for (int kt = 0; kt < 32; ++kt) {
        CP_WAIT(0);
        __syncthreads();
        if (kt < 31) {
            load_kv(kt + 1);
            CP_COMMIT();
            load_bias(kt + 1);
        }
        uint32_t stg = smb + STG_OFF + (uint32_t)(kt & 1) * STG_SZ;
        const float* bwc = bw + (kt & 1) * 192;

        // ---- S = Qh Kh^T + Qh Kl^T + Ql Kh^T ----
        float s[8][4];
#pragma unroll
        for (int j = 0; j < 8; j++)
#pragma unroll
            for (int q = 0; q < 4; q++) s[j][q] = 0.0f;
#pragma unroll
        for (int kk = 0; kk < 4; ++kk) {
            uint32_t aH[4], aL[4];
            ldsm_x4(aH, aAddr + kk * 32);
            ldsm_x4(aL, aAddr + kk * 32 + Q_BYTES);
#pragma unroll
            for (int p = 0; p < 4; ++p) {
                uint32_t bH[4], bL[4];
                uint32_t ba = stg + bRel + p * (16 * FPB) + kk * 32;
                ldsm_x4(bH, ba);
                ldsm_x4(bL, ba + KV_BYTES);
                mma16816(s[2 * p], aH, &bH[0]);
                mma16816(s[2 * p + 1], aH, &bH[2]);
                mma16816(s[2 * p], aH, &bL[0]);
                mma16816(s[2 * p + 1], aH, &bL[2]);
                mma16816(s[2 * p], aL, &bH[0]);
                mma16816(s[2 * p + 1], aL, &bH[2]);
            }
        }

        // ---- bias + online softmax ----
        float mx0 = -INFINITY, mx1 = -INFINITY;
#pragma unroll
        for (int j = 0; j < 8; j++) {
            int c = 8 * j + 2 * tq;
            s[j][0] += bwc[c - r0 + 127];
            s[j][1] += bwc[c + 1 - r0 + 127];
            s[j][2] += bwc[c - (r0 + 8) + 127];
            s[j][3] += bwc[c + 1 - (r0 + 8) + 127];
            mx0 = fmaxf(mx0, fmaxf(s[j][0], s[j][1]));
            mx1 = fmaxf(mx1, fmaxf(s[j][2], s[j][3]));
        }
        mx0 = fmaxf(mx0, __shfl_xor_sync(0xffffffffu, mx0, 1));
        mx0 = fmaxf(mx0, __shfl_xor_sync(0xffffffffu, mx0, 2));
        mx1 = fmaxf(mx1, __shfl_xor_sync(0xffffffffu, mx1, 1));
        mx1 = fmaxf(mx1, __shfl_xor_sync(0xffffffffu, mx1, 2));
        float mn0 = fmaxf(m_[0], mx0), mn1 = fmaxf(m_[1], mx1);
        float al0 = __expf(m_[0] - mn0), al1 = __expf(m_[1] - mn1);

        uint32_t pH[8][2], pL[8][2];
        float sum0 = 0.0f, sum1 = 0.0f;
#pragma unroll
        for (int j = 0; j < 8; j++) {
            float e0 = __expf(s[j][0] - mn0), e1 = __expf(s[j][1] - mn0);
            float e2 = __expf(s[j][2] - mn1), e3 = __expf(s[j][3] - mn1);
            sum0 += e0 + e1;
            sum1 += e2 + e3;
            __nv_bfloat162 h01 = __floats2bfloat162_rn(e0, e1);
            __nv_bfloat162 h23 = __floats2bfloat162_rn(e2, e3);
            pH[j][0] = *(uint32_t*)&h01;
            pH[j][1] = *(uint32_t*)&h23;
            pL[j][0] = packbf2(e0 - __bfloat162float(h01.x), e1 - __bfloat162float(h01.y));
            pL[j][1] = packbf2(e2 - __bfloat162float(h23.x), e3 - __bfloat162float(h23.y));
        }
        sum0 += __shfl_xor_sync(0xffffffffu, sum0, 1);
        sum0 += __shfl_xor_sync(0xffffffffu, sum0, 2);
        sum1 += __shfl_xor_sync(0xffffffffu, sum1, 1);
        sum1 += __shfl_xor_sync(0xffffffffu, sum1, 2);
        l_[0] = l_[0] * al0 + sum0;
        l_[1] = l_[1] * al1 + sum1;
        m_[0] = mn0;
        m_[1] = mn1;
#pragma unroll
        for (int j = 0; j < 8; j++) {
            o[j][0] *= al0; o[j][1] *= al0;
            o[j][2] *= al1; o[j][3] *= al1;
        }

        // ---- O += P V  (P frags straight from registers) ----
        uint32_t vstg = stg + 2 * KV_BYTES;
#pragma unroll
        for (int kk = 0; kk < 4; ++kk) {
            uint32_t aPh[4] = {pH[2 * kk][0], pH[2 * kk][1],
                               pH[2 * kk + 1][0], pH[2 * kk + 1][1]};
            uint32_t aPl[4] = {pL[2 * kk][0], pL[2 * kk][1],
                               pL[2 * kk + 1][0], pL[2 * kk + 1][1]};
#pragma unroll
            for (int p = 0; p < 4; ++p) {
                uint32_t vh[4], vl[4];
                uint32_t va = vstg + vRel + kk * (16 * FPB) + p * 32;
                ldsm_x4_t(vh, va);
                ldsm_x4_t(vl, va + KV_BYTES);
                mma16816(o[2 * p], aPh, &vh[0]);
                mma16816(o[2 * p + 1], aPh, &vh[2]);
                mma16816(o[2 * p], aPh, &vl[0]);
                mma16816(o[2 * p + 1], aPh, &vl[2]);
                mma16816(o[2 * p], aPl, &vh[0]);
                mma16816(o[2 * p + 1], aPl, &vh[2]);
            }
        }
        __syncthreads();
    }

    // ---- epilogue: ctx = O / l, write bf16 hi/lo ----
    float inv0 = 1.0f / l_[0], inv1 = 1.0f / l_[1];
    size_t rbase = (size_t)b * SS + qt * 128 + wid * 16 + g;
#pragma unroll
    for (int j = 0; j < 8; j++) {
        int col = h * DK + 8 * j + 2 * tq;
        float x0 = o[j][0] * inv0, x1 = o[j][1] * inv0;
        float x2 = o[j][2] * inv1, x3 = o[j][3] * inv1;
        __nv_bfloat162 h0 = __floats2bfloat162_rn(x0, x1);
        __nv_bfloat162 l0 = __floats2bfloat162_rn(x0 - __bfloat162float(h0.x),
                                                  x1 - __bfloat162float(h0.y));
        __nv_bfloat162 h1 = __floats2bfloat162_rn(x2, x3);
        __nv_bfloat162 l1 = __floats2bfloat162_rn(x2 - __bfloat162float(h1.x),
                                                  x3 - __bfloat162float(h1.y));
        *(__nv_bfloat162*)(g_ch + rbase * DM + col) = h0;
        *(__nv_bfloat162*)(g_cl + rbase * DM + col) = l0;
        *(__nv_bfloat162*)(g_ch + (rbase + 8) * DM + col) = h1;
        *(__nv_bfloat162*)(g_cl + (rbase + 8) * DM + col) = l1;
    }
}

// ---------------------------------------------------------------------------
extern "C" void kernel_launch(void* const* d_in, const int* in_sizes, int n_in,
                              void* d_out, int out_size) {
    const float* hs = (const float*)d_in[0];
    const float* Wq = (const float*)d_in[1];
    const float* Wk = (const float*)d_in[2];
    const float* Wv = (const float*)d_in[3];
    const float* Wo = (const float*)d_in[4];
    const float* rb = (const float*)d_in[5];

    cudaFuncSetAttribute(flash_kernel,
                         cudaFuncAttributeMaxDynamicSharedMemorySize, FSMEM);
    cudaFuncSetAttribute(gemm_qkv_kernel,
                         cudaFuncAttributeMaxDynamicSharedMemorySize, GSMEM);
    cudaFuncSetAttribute(gemm_out_kernel,
                         cudaFuncAttributeMaxDynamicSharedMemorySize, GSMEM);

    bias_table_kernel<<<NH, 256>>>(rb);
    split_kernel<<<(MTOT * DM / 4) / 256, 256>>>((const float4*)hs);
    tsplit_kernel<<<dim3(32, 32, 4), dim3(32, 8)>>>(Wq, Wk, Wv, Wo);
    gemm_qkv_kernel<<<dim3(MTOT / 128, DM / 128, 3), 256, GSMEM>>>();
    flash_kernel<<<dim3(SS / 128, NH, BB), 256, FSMEM>>>();
    gemm_out_kernel<<<dim3(MTOT / 128, DM / 128), 256, GSMEM>>>((float*)d_out);
}

// round 5
// speedup vs baseline: 3.0236x; 1.0303x over previous
#include <cuda_runtime.h>
#include <cuda_bf16.h>
#include <math.h>
#include <stdint.h>

#define BB 2
#define SS 2048
#define DM 1024
#define NH 16
#define DK 64
#define MTOT (BB * SS)  // 4096

// ---------------- device scratch (allocation-free) ----------------
__device__ float g_bias[NH * (2 * SS - 1)];
__device__ __nv_bfloat16 g_xh[MTOT * DM];
__device__ __nv_bfloat16 g_xl[MTOT * DM];
__device__ __nv_bfloat16 g_wth[4 * DM * DM];  // W^T hi (K-major, [n][k])
__device__ __nv_bfloat16 g_wtl[4 * DM * DM];  // W^T lo
__device__ __nv_bfloat16 g_ch[MTOT * DM];     // ctx hi/lo (written by flash)
__device__ __nv_bfloat16 g_cl[MTOT * DM];
__device__ __nv_bfloat16 g_qh[BB * NH * SS * DK];
__device__ __nv_bfloat16 g_ql[BB * NH * SS * DK];
__device__ __nv_bfloat16 g_kh[BB * NH * SS * DK];
__device__ __nv_bfloat16 g_kl[BB * NH * SS * DK];
__device__ __nv_bfloat16 g_vh[BB * NH * SS * DK];
__device__ __nv_bfloat16 g_vl[BB * NH * SS * DK];

// ---------------- PTX helpers (arch-agnostic, sm_80-era) ----------------
__device__ __forceinline__ uint32_t smem_u32(const void* p) {
    uint32_t a;
    asm("{ .reg .u64 t; cvta.to.shared.u64 t, %1; cvt.u32.u64 %0, t; }"
        : "=r"(a) : "l"(p));
    return a;
}
__device__ __forceinline__ void cp16(uint32_t dst, const void* src) {
    uint64_t g = __cvta_generic_to_global(src);
    asm volatile("cp.async.cg.shared.global [%0], [%1], 16;" :: "r"(dst), "l"(g));
}
#define CP_COMMIT() asm volatile("cp.async.commit_group;" ::: "memory")
#define CP_WAIT(n)  asm volatile("cp.async.wait_group %0;" :: "n"(n) : "memory")

__device__ __forceinline__ void ldsm_x4(uint32_t* r, uint32_t addr) {
    asm volatile("ldmatrix.sync.aligned.m8n8.x4.shared.b16 {%0,%1,%2,%3}, [%4];"
                 : "=r"(r[0]), "=r"(r[1]), "=r"(r[2]), "=r"(r[3]) : "r"(addr));
}
__device__ __forceinline__ void ldsm_x4_t(uint32_t* r, uint32_t addr) {
    asm volatile("ldmatrix.sync.aligned.m8n8.x4.trans.shared.b16 {%0,%1,%2,%3}, [%4];"
                 : "=r"(r[0]), "=r"(r[1]), "=r"(r[2]), "=r"(r[3]) : "r"(addr));
}
__device__ __forceinline__ void mma16816(float* c, const uint32_t* a, const uint32_t* b) {
    asm volatile(
        "mma.sync.aligned.m16n8k16.row.col.f32.bf16.bf16.f32 "
        "{%0,%1,%2,%3}, {%4,%5,%6,%7}, {%8,%9}, {%0,%1,%2,%3};"
        : "+f"(c[0]), "+f"(c[1]), "+f"(c[2]), "+f"(c[3])
        : "r"(a[0]), "r"(a[1]), "r"(a[2]), "r"(a[3]), "r"(b[0]), "r"(b[1]));
}
__device__ __forceinline__ uint32_t packbf2(float x0, float x1) {
    __nv_bfloat162 t = __floats2bfloat162_rn(x0, x1);
    return *(uint32_t*)&t;
}

// ---------------------------------------------------------------------------
// Bias table
// ---------------------------------------------------------------------------
__global__ void bias_table_kernel(const float* __restrict__ rel_bias) {
    int h = blockIdx.x;
    for (int idx = threadIdx.x; idx < 2 * SS - 1; idx += blockDim.x) {
        int rel = idx - (SS - 1);
        int base = (rel > 0) ? 16 : 0;
        int rp = rel < 0 ? -rel : rel;
        int bucket;
        if (rp < 8) {
            bucket = rp;
        } else {
            float v = logf((float)rp * 0.125f) / logf(16.0f) * 8.0f;
            int bb = 8 + (int)v;
            bucket = bb < 15 ? bb : 15;
        }
        g_bias[h * (2 * SS - 1) + idx] = rel_bias[(base + bucket) * NH + h];
    }
}

// ---------------------------------------------------------------------------
// Split hidden_states: fp32 -> bf16 hi + bf16 lo
// ---------------------------------------------------------------------------
__global__ void split_kernel(const float4* __restrict__ src) {
    int i = blockIdx.x * blockDim.x + threadIdx.x;
    float4 x = src[i];
    __nv_bfloat162 hA = __floats2bfloat162_rn(x.x, x.y);
    __nv_bfloat162 hB = __floats2bfloat162_rn(x.z, x.w);
    __nv_bfloat162 lA = __floats2bfloat162_rn(x.x - __bfloat162float(hA.x),
                                              x.y - __bfloat162float(hA.y));
    __nv_bfloat162 lB = __floats2bfloat162_rn(x.z - __bfloat162float(hB.x),
                                              x.w - __bfloat162float(hB.y));
    *(__nv_bfloat162*)(g_xh + 4 * i) = hA;
    *(__nv_bfloat162*)(g_xh + 4 * i + 2) = hB;
    *(__nv_bfloat162*)(g_xl + 4 * i) = lA;
    *(__nv_bfloat162*)(g_xl + 4 * i + 2) = lB;
}

// transpose + split weights
__global__ void tsplit_kernel(const float* __restrict__ W0, const float* __restrict__ W1,
                              const float* __restrict__ W2, const float* __restrict__ W3) {
    __shared__ float t[32][33];
    int z = blockIdx.z;
    const float* W = z == 0 ? W0 : z == 1 ? W1 : z == 2 ? W2 : W3;
    __nv_bfloat16* Th = g_wth + (size_t)z * DM * DM;
    __nv_bfloat16* Tl = g_wtl + (size_t)z * DM * DM;
    int k0 = blockIdx.x * 32, n0 = blockIdx.y * 32;
    int tx = threadIdx.x, ty = threadIdx.y;
#pragma unroll
    for (int r = 0; r < 32; r += 8)
        t[ty + r][tx] = W[(size_t)(k0 + ty + r) * DM + n0 + tx];
    __syncthreads();
#pragma unroll
    for (int r = 0; r < 32; r += 8) {
        float x = t[tx][ty + r];
        __nv_bfloat16 h = __float2bfloat16_rn(x);
        size_t o = (size_t)(n0 + ty + r) * DM + k0 + tx;
        Th[o] = h;
        Tl[o] = __float2bfloat16_rn(x - __bfloat162float(h));
    }
}

// ---------------------------------------------------------------------------
// mma.sync bf16x3 GEMM: BM=256, BN=128, BK=32, 8 warps (4x2), warp tile 64x64,
// 3-stage cp.async ring, one __syncthreads per chunk.
// ---------------------------------------------------------------------------
#define LDK 40                       // smem pitch bf16 (80 B)
#define A_PER (256 * LDK * 2)        // 20480 per matrix (hi or lo)
#define B_PER (128 * LDK * 2)        // 10240
#define BOFF (2 * A_PER)             // 40960
#define STAGE (2 * A_PER + 2 * B_PER)  // 61440
#define NSTG 3
#define GSMEM (NSTG * STAGE)         // 184320

__device__ __forceinline__ void gemm_body(
    const __nv_bfloat16* __restrict__ Ah, const __nv_bfloat16* __restrict__ Al,
    const __nv_bfloat16* __restrict__ Bh, const __nv_bfloat16* __restrict__ Bl,
    float* __restrict__ outp, int mode)
{
    extern __shared__ char sm[];
    const uint32_t smb = smem_u32(sm);
    const int tid = threadIdx.x;
    const int wid = tid >> 5, lane = tid & 31;
    const int wm = wid >> 1, wn = wid & 1;
    const int bm = blockIdx.x * 256, bn = blockIdx.y * 128;

    float acc[4][8][4];
#pragma unroll
    for (int i = 0; i < 4; i++)
#pragma unroll
        for (int j = 0; j < 8; j++)
#pragma unroll
            for (int q = 0; q < 4; q++) acc[i][j][q] = 0.0f;

    const uint32_t aRel = (uint32_t)((wm * 64 + (lane & 15)) * LDK + (lane >> 4) * 8) * 2;
    const uint32_t bRel = (uint32_t)BOFF +
        (uint32_t)((wn * 64 + ((lane >> 4) & 1) * 8 + (lane & 7)) * LDK +
                   ((lane >> 3) & 1) * 8) * 2;

    auto load_stage = [&](int c) {
        uint32_t st = smb + (uint32_t)(c % NSTG) * STAGE;
        int k0 = c * 32;
        // A: 256 rows x 4 quads (hi+lo)
#pragma unroll
        for (int i = 0; i < 4; i++) {
            int e = tid + 256 * i;
            int row = e >> 2, kq = e & 3;
            uint32_t d = st + (uint32_t)(row * LDK + kq * 8) * 2;
            size_t ga = (size_t)(bm + row) * DM + k0 + kq * 8;
            cp16(d, Ah + ga);
            cp16(d + A_PER, Al + ga);
        }
        // B: 128 rows x 4 quads (hi+lo)
#pragma unroll
        for (int i = 0; i < 2; i++) {
            int e = tid + 256 * i;
            int row = e >> 2, kq = e & 3;
            uint32_t d = st + BOFF + (uint32_t)(row * LDK + kq * 8) * 2;
            size_t gb = (size_t)(bn + row) * DM + k0 + kq * 8;
            cp16(d, Bh + gb);
            cp16(d + B_PER, Bl + gb);
        }
    };

    load_stage(0);
    CP_COMMIT();
    load_stage(1);
    CP_COMMIT();

    for (int c = 0; c < 32; ++c) {
        CP_WAIT(1);
        __syncthreads();
        if (c + 2 < 32) {
            load_stage(c + 2);
            CP_COMMIT();
        }
        uint32_t st = smb + (uint32_t)(c % NSTG) * STAGE;
#pragma unroll
        for (int ks = 0; ks < 2; ++ks) {
            uint32_t koff = ks * 32;
            uint32_t aH[4][4], aL[4][4];
#pragma unroll
            for (int mf = 0; mf < 4; ++mf) {
                ldsm_x4(aH[mf], st + aRel + koff + mf * (16 * LDK * 2));
                ldsm_x4(aL[mf], st + aRel + koff + mf * (16 * LDK * 2) + A_PER);
            }
#pragma unroll
            for (int p = 0; p < 4; ++p) {
                uint32_t bH[4], bL[4];
                uint32_t ba = st + bRel + koff + p * (16 * LDK * 2);
                ldsm_x4(bH, ba);
                ldsm_x4(bL, ba + B_PER);
#pragma unroll
                for (int mf = 0; mf < 4; ++mf) {
                    mma16816(acc[mf][2 * p], aH[mf], &bH[0]);
                    mma16816(acc[mf][2 * p + 1], aH[mf], &bH[2]);
                    mma16816(acc[mf][2 * p], aH[mf], &bL[0]);
                    mma16816(acc[mf][2 * p + 1], aH[mf], &bL[2]);
                    mma16816(acc[mf][2 * p], aL[mf], &bH[0]);
                    mma16816(acc[mf][2 * p + 1], aL[mf], &bH[2]);
                }
            }
        }
        __syncthreads();
    }

    const int g = lane >> 2, t2 = (lane & 3) * 2;
#pragma unroll
    for (int mf = 0; mf < 4; ++mf) {
#pragma unroll
        for (int nf = 0; nf < 8; ++nf) {
            int n = bn + wn * 64 + nf * 8 + t2;
            int m0 = bm + wm * 64 + mf * 16 + g;
            int m1 = m0 + 8;
            if (mode == 3) {
                *(float2*)(outp + (size_t)m0 * DM + n) =
                    make_float2(acc[mf][nf][0], acc[mf][nf][1]);
                *(float2*)(outp + (size_t)m1 * DM + n) =
                    make_float2(acc[mf][nf][2], acc[mf][nf][3]);
            } else {
                __nv_bfloat16* Oh = mode == 0 ? g_qh : (mode == 1 ? g_kh : g_vh);
                __nv_bfloat16* Ol = mode == 0 ? g_ql : (mode == 1 ? g_kl : g_vl);
                int hh = n >> 6, d = n & 63;
                size_t o0 = (((size_t)(m0 >> 11) * NH + hh) * SS + (m0 & (SS - 1))) * DK + d;
                size_t o1 = (((size_t)(m1 >> 11) * NH + hh) * SS + (m1 & (SS - 1))) * DK + d;
                float v0 = acc[mf][nf][0], v1 = acc[mf][nf][1];
                float v2 = acc[mf][nf][2], v3 = acc[mf][nf][3];
                __nv_bfloat162 h0 = __floats2bfloat162_rn(v0, v1);
                __nv_bfloat162 l0 = __floats2bfloat162_rn(v0 - __bfloat162float(h0.x),
                                                          v1 - __bfloat162float(h0.y));
                __nv_bfloat162 h1 = __floats2bfloat162_rn(v2, v3);
                __nv_bfloat162 l1 = __floats2bfloat162_rn(v2 - __bfloat162float(h1.x),
                                                          v3 - __bfloat162float(h1.y));
                *(__nv_bfloat162*)(Oh + o0) = h0;
                *(__nv_bfloat162*)(Ol + o0) = l0;
                *(__nv_bfloat162*)(Oh + o1) = h1;
                *(__nv_bfloat162*)(Ol + o1) = l1;
            }
        }
    }
}

__global__ void __launch_bounds__(256, 1) gemm_qkv_kernel() {
    int z = blockIdx.z;
    gemm_body(g_xh, g_xl, g_wth + (size_t)z * DM * DM, g_wtl + (size_t)z * DM * DM,
              nullptr, z);
}
__global__ void __launch_bounds__(256, 1) gemm_out_kernel(float* __restrict__ out) {
    gemm_body(g_ch, g_cl, g_wth + 3ull * DM * DM, g_wtl + 3ull * DM * DM, out, 3);
}

// ---------------------------------------------------------------------------
// Flash attention on mma.sync (unchanged from round 4).
// ---------------------------------------------------------------------------
#define FPB 144
#define Q_BYTES (128 * FPB)
#define KV_BYTES (64 * FPB)
#define STG_OFF (2 * Q_BYTES)
#define STG_SZ (4 * KV_BYTES)
#define BIAS_OFF (STG_OFF + 2 * STG_SZ)
#define FSMEM (BIAS_OFF + 2 * 192 * 4)

__global__ void __launch_bounds__(256) flash_kernel() {
    extern __shared__ char sm[];
    const uint32_t smb = smem_u32(sm);
    const int tid = threadIdx.x, wid = tid >> 5, lane = tid & 31;
    const int g = lane >> 2, tq = lane & 3;
    const int qt = blockIdx.x, h = blockIdx.y, b = blockIdx.z;
    const int bh = b * NH + h;

    const __nv_bfloat16* Qh = g_qh + ((size_t)bh * SS + qt * 128) * DK;
    const __nv_bfloat16* Ql = g_ql + ((size_t)bh * SS + qt * 128) * DK;
    const __nv_bfloat16* Kh = g_kh + (size_t)bh * SS * DK;
    const __nv_bfloat16* Kl = g_kl + (size_t)bh * SS * DK;
    const __nv_bfloat16* Vh = g_vh + (size_t)bh * SS * DK;
    const __nv_bfloat16* Vl = g_vl + (size_t)bh * SS * DK;
    float* bw = (float*)(sm + BIAS_OFF);

#pragma unroll
    for (int i = 0; i < 4; i++) {
        int e = tid + 256 * i;
        int row = e >> 3, qd = e & 7;
        uint32_t d = smb + row * FPB + qd * 16;
        cp16(d, Qh + row * DK + qd * 8);
        cp16(d + Q_BYTES, Ql + row * DK + qd * 8);
    }

    auto load_kv = [&](int c) {
        uint32_t st = smb + STG_OFF + (uint32_t)(c & 1) * STG_SZ;
#pragma unroll
        for (int i = 0; i < 2; i++) {
            int e = tid + 256 * i;
            int row = e >> 3, qd = e & 7;
            uint32_t d = st + row * FPB + qd * 16;
            size_t src = (size_t)(c * 64 + row) * DK + qd * 8;
            cp16(d, Kh + src);
            cp16(d + KV_BYTES, Kl + src);
            cp16(d + 2 * KV_BYTES, Vh + src);
            cp16(d + 3 * KV_BYTES, Vl + src);
        }
    };
    auto load_bias = [&](int c) {
        if (tid < 191) {
            int base = h * (2 * SS - 1) + c * 64 - qt * 128 + 1920;
            bw[(c & 1) * 192 + tid] = g_bias[base + tid];
        }
    };

    load_kv(0);
    CP_COMMIT();
    load_bias(0);

    float m_[2] = {-INFINITY, -INFINITY};
    float l_[2] = {0.0f, 0.0f};
    float o[8][4];
#pragma unroll
    for (int j = 0; j < 8; j++)
#pragma unroll
        for (int q = 0; q < 4; q++) o[j][q] = 0.0f;

    const uint32_t aAddr = smb + (uint32_t)(wid * 16 + (lane & 15)) * FPB + (lane >> 4) * 16;
    const uint32_t bRel = (uint32_t)((((lane >> 4) & 1) * 8 + (lane & 7)) * FPB +
                                     ((lane >> 3) & 1) * 16);
    const uint32_t vRel = (uint32_t)((lane & 15) * FPB + (lane >> 4) * 16);
    const int r0 = wid * 16 + g;

    for (int kt = 0; kt < 32; ++kt) {
        CP_WAIT(0);
        __syncthreads();
        if (kt < 31) {
            load_kv(kt + 1);
            CP_COMMIT();
            load_bias(kt + 1);
        }
        uint32_t stg = smb + STG_OFF + (uint32_t)(kt & 1) * STG_SZ;
        const float* bwc = bw + (kt & 1) * 192;

        float s[8][4];
#pragma unroll
        for (int j = 0; j < 8; j++)
#pragma unroll
            for (int q = 0; q < 4; q++) s[j][q] = 0.0f;
#pragma unroll
        for (int kk = 0; kk < 4; ++kk) {
            uint32_t aH[4], aL[4];
            ldsm_x4(aH, aAddr + kk * 32);
            ldsm_x4(aL, aAddr + kk * 32 + Q_BYTES);
#pragma unroll
            for (int p = 0; p < 4; ++p) {
                uint32_t bH[4], bL[4];
                uint32_t ba = stg + bRel + p * (16 * FPB) + kk * 32;
                ldsm_x4(bH, ba);
                ldsm_x4(bL, ba + KV_BYTES);
                mma16816(s[2 * p], aH, &bH[0]);
                mma16816(s[2 * p + 1], aH, &bH[2]);
                mma16816(s[2 * p], aH, &bL[0]);
                mma16816(s[2 * p + 1], aH, &bL[2]);
                mma16816(s[2 * p], aL, &bH[0]);
                mma16816(s[2 * p + 1], aL, &bH[2]);
            }
        }

        float mx0 = -INFINITY, mx1 = -INFINITY;
#pragma unroll
        for (int j = 0; j < 8; j++) {
            int c = 8 * j + 2 * tq;
            s[j][0] += bwc[c - r0 + 127];
            s[j][1] += bwc[c + 1 - r0 + 127];
            s[j][2] += bwc[c - (r0 + 8) + 127];
            s[j][3] += bwc[c + 1 - (r0 + 8) + 127];
            mx0 = fmaxf(mx0, fmaxf(s[j][0], s[j][1]));
            mx1 = fmaxf(mx1, fmaxf(s[j][2], s[j][3]));
        }
        mx0 = fmaxf(mx0, __shfl_xor_sync(0xffffffffu, mx0, 1));
        mx0 = fmaxf(mx0, __shfl_xor_sync(0xffffffffu, mx0, 2));
        mx1 = fmaxf(mx1, __shfl_xor_sync(0xffffffffu, mx1, 1));
        mx1 = fmaxf(mx1, __shfl_xor_sync(0xffffffffu, mx1, 2));
        float mn0 = fmaxf(m_[0], mx0), mn1 = fmaxf(m_[1], mx1);
        float al0 = __expf(m_[0] - mn0), al1 = __expf(m_[1] - mn1);

        uint32_t pH[8][2], pL[8][2];
        float sum0 = 0.0f, sum1 = 0.0f;
#pragma unroll
        for (int j = 0; j < 8; j++) {
            float e0 = __expf(s[j][0] - mn0), e1 = __expf(s[j][1] - mn0);
            float e2 = __expf(s[j][2] - mn1), e3 = __expf(s[j][3] - mn1);
            sum0 += e0 + e1;
            sum1 += e2 + e3;
            __nv_bfloat162 h01 = __floats2bfloat162_rn(e0, e1);
            __nv_bfloat162 h23 = __floats2bfloat162_rn(e2, e3);
            pH[j][0] = *(uint32_t*)&h01;
            pH[j][1] = *(uint32_t*)&h23;
            pL[j][0] = packbf2(e0 - __bfloat162float(h01.x), e1 - __bfloat162float(h01.y));
            pL[j][1] = packbf2(e2 - __bfloat162float(h23.x), e3 - __bfloat162float(h23.y));
        }
        sum0 += __shfl_xor_sync(0xffffffffu, sum0, 1);
        sum0 += __shfl_xor_sync(0xffffffffu, sum0, 2);
        sum1 += __shfl_xor_sync(0xffffffffu, sum1, 1);
        sum1 += __shfl_xor_sync(0xffffffffu, sum1, 2);
        l_[0] = l_[0] * al0 + sum0;
        l_[1] = l_[1] * al1 + sum1;
        m_[0] = mn0;
        m_[1] = mn1;
#pragma unroll
        for (int j = 0; j < 8; j++) {
            o[j][0] *= al0; o[j][1] *= al0;
            o[j][2] *= al1; o[j][3] *= al1;
        }

        uint32_t vstg = stg + 2 * KV_BYTES;
#pragma unroll
        for (int kk = 0; kk < 4; ++kk) {
            uint32_t aPh[4] = {pH[2 * kk][0], pH[2 * kk][1],
                               pH[2 * kk + 1][0], pH[2 * kk + 1][1]};
            uint32_t aPl[4] = {pL[2 * kk][0], pL[2 * kk][1],
                               pL[2 * kk + 1][0], pL[2 * kk + 1][1]};
#pragma unroll
            for (int p = 0; p < 4; ++p) {
                uint32_t vh[4], vl[4];
                uint32_t va = vstg + vRel + kk * (16 * FPB) + p * 32;
                ldsm_x4_t(vh, va);
                ldsm_x4_t(vl, va + KV_BYTES);
                mma16816(o[2 * p], aPh, &vh[0]);
                mma16816(o[2 * p + 1], aPh, &vh[2]);
                mma16816(o[2 * p], aPh, &vl[0]);
                mma16816(o[2 * p + 1], aPh, &vl[2]);
                mma16816(o[2 * p], aPl, &vh[0]);
                mma16816(o[2 * p + 1], aPl, &vh[2]);
            }
        }
        __syncthreads();
    }

    float inv0 = 1.0f / l_[0], inv1 = 1.0f / l_[1];
    size_t rbase = (size_t)b * SS + qt * 128 + wid * 16 + g;
#pragma unroll
    for (int j = 0; j < 8; j++) {
        int col = h * DK + 8 * j + 2 * tq;
        float x0 = o[j][0] * inv0, x1 = o[j][1] * inv0;
        float x2 = o[j][2] * inv1, x3 = o[j][3] * inv1;
        __nv_bfloat162 h0 = __floats2bfloat162_rn(x0, x1);
        __nv_bfloat162 l0 = __floats2bfloat162_rn(x0 - __bfloat162float(h0.x),
                                                  x1 - __bfloat162float(h0.y));
        __nv_bfloat162 h1 = __floats2bfloat162_rn(x2, x3);
        __nv_bfloat162 l1 = __floats2bfloat162_rn(x2 - __bfloat162float(h1.x),
                                                  x3 - __bfloat162float(h1.y));
        *(__nv_bfloat162*)(g_ch + rbase * DM + col) = h0;
        *(__nv_bfloat162*)(g_cl + rbase * DM + col) = l0;
        *(__nv_bfloat162*)(g_ch + (rbase + 8) * DM + col) = h1;
        *(__nv_bfloat162*)(g_cl + (rbase + 8) * DM + col) = l1;
    }
}

// ---------------------------------------------------------------------------
extern "C" void kernel_launch(void* const* d_in, const int* in_sizes, int n_in,
                              void* d_out, int out_size) {
    const float* hs = (const float*)d_in[0];
    const float* Wq = (const float*)d_in[1];
    const float* Wk = (const float*)d_in[2];
    const float* Wv = (const float*)d_in[3];
    const float* Wo = (const float*)d_in[4];
    const float* rb = (const float*)d_in[5];

    cudaFuncSetAttribute(flash_kernel,
                         cudaFuncAttributeMaxDynamicSharedMemorySize, FSMEM);
    cudaFuncSetAttribute(gemm_qkv_kernel,
                         cudaFuncAttributeMaxDynamicSharedMemorySize, GSMEM);
    cudaFuncSetAttribute(gemm_out_kernel,
                         cudaFuncAttributeMaxDynamicSharedMemorySize, GSMEM);

    bias_table_kernel<<<NH, 256>>>(rb);
    split_kernel<<<(MTOT * DM / 4) / 256, 256>>>((const float4*)hs);
    tsplit_kernel<<<dim3(32, 32, 4), dim3(32, 8)>>>(Wq, Wk, Wv, Wo);
    gemm_qkv_kernel<<<dim3(MTOT / 256, DM / 128, 3), 256, GSMEM>>>();
    flash_kernel<<<dim3(SS / 128, NH, BB), 256, FSMEM>>>();
    gemm_out_kernel<<<dim3(MTOT / 256, DM / 128), 256, GSMEM>>>((float*)d_out);
}

// round 6
// speedup vs baseline: 3.0693x; 1.0151x over previous
#include <cuda_runtime.h>
#include <cuda_bf16.h>
#include <math.h>
#include <stdint.h>

#define BB 2
#define SS 2048
#define DM 1024
#define NH 16
#define DK 64
#define MTOT (BB * SS)  // 4096

// ---------------- device scratch (allocation-free) ----------------
__device__ float g_bias[NH * (2 * SS - 1)];
__device__ __nv_bfloat16 g_xh[MTOT * DM];
__device__ __nv_bfloat16 g_xl[MTOT * DM];
__device__ __nv_bfloat16 g_wth[4 * DM * DM];
__device__ __nv_bfloat16 g_wtl[4 * DM * DM];
__device__ __nv_bfloat16 g_ch[MTOT * DM];
__device__ __nv_bfloat16 g_cl[MTOT * DM];
__device__ __nv_bfloat16 g_qh[BB * NH * SS * DK];
__device__ __nv_bfloat16 g_ql[BB * NH * SS * DK];
__device__ __nv_bfloat16 g_kh[BB * NH * SS * DK];
__device__ __nv_bfloat16 g_kl[BB * NH * SS * DK];
__device__ __nv_bfloat16 g_vh[BB * NH * SS * DK];
__device__ __nv_bfloat16 g_vl[BB * NH * SS * DK];

// ---------------- PTX helpers (arch-agnostic, sm_80-era) ----------------
__device__ __forceinline__ uint32_t smem_u32(const void* p) {
    uint32_t a;
    asm("{ .reg .u64 t; cvta.to.shared.u64 t, %1; cvt.u32.u64 %0, t; }"
        : "=r"(a) : "l"(p));
    return a;
}
__device__ __forceinline__ void cp16(uint32_t dst, const void* src) {
    uint64_t g = __cvta_generic_to_global(src);
    asm volatile("cp.async.cg.shared.global [%0], [%1], 16;" :: "r"(dst), "l"(g));
}
#define CP_COMMIT() asm volatile("cp.async.commit_group;" ::: "memory")
#define CP_WAIT(n)  asm volatile("cp.async.wait_group %0;" :: "n"(n) : "memory")

__device__ __forceinline__ void ldsm_x4(uint32_t* r, uint32_t addr) {
    asm volatile("ldmatrix.sync.aligned.m8n8.x4.shared.b16 {%0,%1,%2,%3}, [%4];"
                 : "=r"(r[0]), "=r"(r[1]), "=r"(r[2]), "=r"(r[3]) : "r"(addr));
}
__device__ __forceinline__ void ldsm_x4_t(uint32_t* r, uint32_t addr) {
    asm volatile("ldmatrix.sync.aligned.m8n8.x4.trans.shared.b16 {%0,%1,%2,%3}, [%4];"
                 : "=r"(r[0]), "=r"(r[1]), "=r"(r[2]), "=r"(r[3]) : "r"(addr));
}
__device__ __forceinline__ void mma16816(float* c, const uint32_t* a, const uint32_t* b) {
    asm volatile(
        "mma.sync.aligned.m16n8k16.row.col.f32.bf16.bf16.f32 "
        "{%0,%1,%2,%3}, {%4,%5,%6,%7}, {%8,%9}, {%0,%1,%2,%3};"
        : "+f"(c[0]), "+f"(c[1]), "+f"(c[2]), "+f"(c[3])
        : "r"(a[0]), "r"(a[1]), "r"(a[2]), "r"(a[3]), "r"(b[0]), "r"(b[1]));
}
__device__ __forceinline__ uint32_t packbf2(float x0, float x1) {
    __nv_bfloat162 t = __floats2bfloat162_rn(x0, x1);
    return *(uint32_t*)&t;
}

// ---------------------------------------------------------------------------
// Bias table
// ---------------------------------------------------------------------------
__global__ void bias_table_kernel(const float* __restrict__ rel_bias) {
    int h = blockIdx.x;
    for (int idx = threadIdx.x; idx < 2 * SS - 1; idx += blockDim.x) {
        int rel = idx - (SS - 1);
        int base = (rel > 0) ? 16 : 0;
        int rp = rel < 0 ? -rel : rel;
        int bucket;
        if (rp < 8) {
            bucket = rp;
        } else {
            float v = logf((float)rp * 0.125f) / logf(16.0f) * 8.0f;
            int bb = 8 + (int)v;
            bucket = bb < 15 ? bb : 15;
        }
        g_bias[h * (2 * SS - 1) + idx] = rel_bias[(base + bucket) * NH + h];
    }
}

// ---------------------------------------------------------------------------
// Split hidden_states: fp32 -> bf16 hi + bf16 lo
// ---------------------------------------------------------------------------
__global__ void split_kernel(const float4* __restrict__ src) {
    int i = blockIdx.x * blockDim.x + threadIdx.x;
    float4 x = src[i];
    __nv_bfloat162 hA = __floats2bfloat162_rn(x.x, x.y);
    __nv_bfloat162 hB = __floats2bfloat162_rn(x.z, x.w);
    __nv_bfloat162 lA = __floats2bfloat162_rn(x.x - __bfloat162float(hA.x),
                                              x.y - __bfloat162float(hA.y));
    __nv_bfloat162 lB = __floats2bfloat162_rn(x.z - __bfloat162float(hB.x),
                                              x.w - __bfloat162float(hB.y));
    *(__nv_bfloat162*)(g_xh + 4 * i) = hA;
    *(__nv_bfloat162*)(g_xh + 4 * i + 2) = hB;
    *(__nv_bfloat162*)(g_xl + 4 * i) = lA;
    *(__nv_bfloat162*)(g_xl + 4 * i + 2) = lB;
}

// transpose + split weights
__global__ void tsplit_kernel(const float* __restrict__ W0, const float* __restrict__ W1,
                              const float* __restrict__ W2, const float* __restrict__ W3) {
    __shared__ float t[32][33];
    int z = blockIdx.z;
    const float* W = z == 0 ? W0 : z == 1 ? W1 : z == 2 ? W2 : W3;
    __nv_bfloat16* Th = g_wth + (size_t)z * DM * DM;
    __nv_bfloat16* Tl = g_wtl + (size_t)z * DM * DM;
    int k0 = blockIdx.x * 32, n0 = blockIdx.y * 32;
    int tx = threadIdx.x, ty = threadIdx.y;
#pragma unroll
    for (int r = 0; r < 32; r += 8)
        t[ty + r][tx] = W[(size_t)(k0 + ty + r) * DM + n0 + tx];
    __syncthreads();
#pragma unroll
    for (int r = 0; r < 32; r += 8) {
        float x = t[tx][ty + r];
        __nv_bfloat16 h = __float2bfloat16_rn(x);
        size_t o = (size_t)(n0 + ty + r) * DM + k0 + tx;
        Th[o] = h;
        Tl[o] = __float2bfloat16_rn(x - __bfloat162float(h));
    }
}

// ---------------------------------------------------------------------------
// mma.sync bf16x3 GEMM: BM=256, BN=128, BK=32, 8 warps (4x2), warp tile 64x64,
// 3-stage cp.async ring, ONE __syncthreads per chunk, term-major mma order.
// ---------------------------------------------------------------------------
#define LDK 40
#define A_PER (256 * LDK * 2)
#define B_PER (128 * LDK * 2)
#define BOFF (2 * A_PER)
#define STAGE (2 * A_PER + 2 * B_PER)
#define NSTG 3
#define GSMEM (NSTG * STAGE)

__device__ __forceinline__ void gemm_body(
    const __nv_bfloat16* __restrict__ Ah, const __nv_bfloat16* __restrict__ Al,
    const __nv_bfloat16* __restrict__ Bh, const __nv_bfloat16* __restrict__ Bl,
    float* __restrict__ outp, int mode)
{
    extern __shared__ char sm[];
    const uint32_t smb = smem_u32(sm);
    const int tid = threadIdx.x;
    const int wid = tid >> 5, lane = tid & 31;
    const int wm = wid >> 1, wn = wid & 1;
    const int bm = blockIdx.x * 256, bn = blockIdx.y * 128;

    float acc[4][8][4];
#pragma unroll
    for (int i = 0; i < 4; i++)
#pragma unroll
        for (int j = 0; j < 8; j++)
#pragma unroll
            for (int q = 0; q < 4; q++) acc[i][j][q] = 0.0f;

    const uint32_t aRel = (uint32_t)((wm * 64 + (lane & 15)) * LDK + (lane >> 4) * 8) * 2;
    const uint32_t bRel = (uint32_t)BOFF +
        (uint32_t)((wn * 64 + ((lane >> 4) & 1) * 8 + (lane & 7)) * LDK +
                   ((lane >> 3) & 1) * 8) * 2;

    auto load_stage = [&](int c) {
        uint32_t st = smb + (uint32_t)(c % NSTG) * STAGE;
        int k0 = c * 32;
#pragma unroll
        for (int i = 0; i < 4; i++) {
            int e = tid + 256 * i;
            int row = e >> 2, kq = e & 3;
            uint32_t d = st + (uint32_t)(row * LDK + kq * 8) * 2;
            size_t ga = (size_t)(bm + row) * DM + k0 + kq * 8;
            cp16(d, Ah + ga);
            cp16(d + A_PER, Al + ga);
        }
#pragma unroll
        for (int i = 0; i < 2; i++) {
            int e = tid + 256 * i;
            int row = e >> 2, kq = e & 3;
            uint32_t d = st + BOFF + (uint32_t)(row * LDK + kq * 8) * 2;
            size_t gb = (size_t)(bn + row) * DM + k0 + kq * 8;
            cp16(d, Bh + gb);
            cp16(d + B_PER, Bl + gb);
        }
    };

    load_stage(0);
    CP_COMMIT();
    load_stage(1);
    CP_COMMIT();

    for (int c = 0; c < 32; ++c) {
        CP_WAIT(1);
        __syncthreads();   // orders: all warps done reading slot (c-1)%3 before new writes
        if (c + 2 < 32) {
            load_stage(c + 2);
            CP_COMMIT();
        }
        uint32_t st = smb + (uint32_t)(c % NSTG) * STAGE;
        uint32_t aBase = st + aRel, bBase = st + bRel;
#pragma unroll
        for (int ks = 0; ks < 2; ++ks) {
            uint32_t koff = ks * 32;
            uint32_t aH[4][4], aL[4][4], bH[4][4], bL[4][4];
#pragma unroll
            for (int mf = 0; mf < 4; ++mf) {
                ldsm_x4(aH[mf], aBase + koff + mf * (16 * LDK * 2));
                ldsm_x4(aL[mf], aBase + koff + mf * (16 * LDK * 2) + A_PER);
            }
#pragma unroll
            for (int p = 0; p < 4; ++p) {
                ldsm_x4(bH[p], bBase + koff + p * (16 * LDK * 2));
                ldsm_x4(bL[p], bBase + koff + p * (16 * LDK * 2) + B_PER);
            }
            // term HH (32 independent mma)
#pragma unroll
            for (int p = 0; p < 4; ++p)
#pragma unroll
                for (int mf = 0; mf < 4; ++mf) {
                    mma16816(acc[mf][2 * p], aH[mf], &bH[p][0]);
                    mma16816(acc[mf][2 * p + 1], aH[mf], &bH[p][2]);
                }
            // term HL
#pragma unroll
            for (int p = 0; p < 4; ++p)
#pragma unroll
                for (int mf = 0; mf < 4; ++mf) {
                    mma16816(acc[mf][2 * p], aH[mf], &bL[p][0]);
                    mma16816(acc[mf][2 * p + 1], aH[mf], &bL[p][2]);
                }
            // term LH
#pragma unroll
            for (int p = 0; p < 4; ++p)
#pragma unroll
                for (int mf = 0; mf < 4; ++mf) {
                    mma16816(acc[mf][2 * p], aL[mf], &bH[p][0]);
                    mma16816(acc[mf][2 * p + 1], aL[mf], &bH[p][2]);
                }
        }
    }

    const int g = lane >> 2, t2 = (lane & 3) * 2;
#pragma unroll
    for (int mf = 0; mf < 4; ++mf) {
#pragma unroll
        for (int nf = 0; nf < 8; ++nf) {
            int n = bn + wn * 64 + nf * 8 + t2;
            int m0 = bm + wm * 64 + mf * 16 + g;
            int m1 = m0 + 8;
            if (mode == 3) {
                *(float2*)(outp + (size_t)m0 * DM + n) =
                    make_float2(acc[mf][nf][0], acc[mf][nf][1]);
                *(float2*)(outp + (size_t)m1 * DM + n) =
                    make_float2(acc[mf][nf][2], acc[mf][nf][3]);
            } else {
                __nv_bfloat16* Oh = mode == 0 ? g_qh : (mode == 1 ? g_kh : g_vh);
                __nv_bfloat16* Ol = mode == 0 ? g_ql : (mode == 1 ? g_kl : g_vl);
                int hh = n >> 6, d = n & 63;
                size_t o0 = (((size_t)(m0 >> 11) * NH + hh) * SS + (m0 & (SS - 1))) * DK + d;
                size_t o1 = (((size_t)(m1 >> 11) * NH + hh) * SS + (m1 & (SS - 1))) * DK + d;
                float v0 = acc[mf][nf][0], v1 = acc[mf][nf][1];
                float v2 = acc[mf][nf][2], v3 = acc[mf][nf][3];
                __nv_bfloat162 h0 = __floats2bfloat162_rn(v0, v1);
                __nv_bfloat162 l0 = __floats2bfloat162_rn(v0 - __bfloat162float(h0.x),
                                                          v1 - __bfloat162float(h0.y));
                __nv_bfloat162 h1 = __floats2bfloat162_rn(v2, v3);
                __nv_bfloat162 l1 = __floats2bfloat162_rn(v2 - __bfloat162float(h1.x),
                                                          v3 - __bfloat162float(h1.y));
                *(__nv_bfloat162*)(Oh + o0) = h0;
                *(__nv_bfloat162*)(Ol + o0) = l0;
                *(__nv_bfloat162*)(Oh + o1) = h1;
                *(__nv_bfloat162*)(Ol + o1) = l1;
            }
        }
    }
}

__global__ void __launch_bounds__(256, 1) gemm_qkv_kernel() {
    int z = blockIdx.z;
    gemm_body(g_xh, g_xl, g_wth + (size_t)z * DM * DM, g_wtl + (size_t)z * DM * DM,
              nullptr, z);
}
__global__ void __launch_bounds__(256, 1) gemm_out_kernel(float* __restrict__ out) {
    gemm_body(g_ch, g_cl, g_wth + 3ull * DM * DM, g_wtl + 3ull * DM * DM, out, 3);
}

// ---------------------------------------------------------------------------
// Flash attention on mma.sync: BQ=128, BK=64, 8 warps, bf16x3, term-major,
// one __syncthreads per kv tile.
// ---------------------------------------------------------------------------
#define FPB 144
#define Q_BYTES (128 * FPB)
#define KV_BYTES (64 * FPB)
#define STG_OFF (2 * Q_BYTES)
#define STG_SZ (4 * KV_BYTES)
#define BIAS_OFF (STG_OFF + 2 * STG_SZ)
#define FSMEM (BIAS_OFF + 2 * 192 * 4)

__global__ void __launch_bounds__(256) flash_kernel() {
    extern __shared__ char sm[];
    const uint32_t smb = smem_u32(sm);
    const int tid = threadIdx.x, wid = tid >> 5, lane = tid & 31;
    const int g = lane >> 2, tq = lane & 3;
    const int qt = blockIdx.x, h = blockIdx.y, b = blockIdx.z;
    const int bh = b * NH + h;

    const __nv_bfloat16* Qh = g_qh + ((size_t)bh * SS + qt * 128) * DK;
    const __nv_bfloat16* Ql = g_ql + ((size_t)bh * SS + qt * 128) * DK;
    const __nv_bfloat16* Kh = g_kh + (size_t)bh * SS * DK;
    const __nv_bfloat16* Kl = g_kl + (size_t)bh * SS * DK;
    const __nv_bfloat16* Vh = g_vh + (size_t)bh * SS * DK;
    const __nv_bfloat16* Vl = g_vl + (size_t)bh * SS * DK;
    float* bw = (float*)(sm + BIAS_OFF);

#pragma unroll
    for (int i = 0; i < 4; i++) {
        int e = tid + 256 * i;
        int row = e >> 3, qd = e & 7;
        uint32_t d = smb + row * FPB + qd * 16;
        cp16(d, Qh + row * DK + qd * 8);
        cp16(d + Q_BYTES, Ql + row * DK + qd * 8);
    }

    auto load_kv = [&](int c) {
        uint32_t st = smb + STG_OFF + (uint32_t)(c & 1) * STG_SZ;
#pragma unroll
        for (int i = 0; i < 2; i++) {
            int e = tid + 256 * i;
            int row = e >> 3, qd = e & 7;
            uint32_t d = st + row * FPB + qd * 16;
            size_t src = (size_t)(c * 64 + row) * DK + qd * 8;
            cp16(d, Kh + src);
            cp16(d + KV_BYTES, Kl + src);
            cp16(d + 2 * KV_BYTES, Vh + src);
            cp16(d + 3 * KV_BYTES, Vl + src);
        }
    };
    auto load_bias = [&](int c) {
        if (tid < 191) {
            int base = h * (2 * SS - 1) + c * 64 - qt * 128 + 1920;
            bw[(c & 1) * 192 + tid] = g_bias[base + tid];
        }
    };

    load_kv(0);
    CP_COMMIT();
    load_bias(0);

    float m_[2] = {-INFINITY, -INFINITY};
    float l_[2] = {0.0f, 0.0f};
    float o[8][4];
#pragma unroll
    for (int j = 0; j < 8; j++)
#pragma unroll
        for (int q = 0; q < 4; q++) o[j][q] = 0.0f;

    const uint32_t aAddr = smb + (uint32_t)(wid * 16 + (lane & 15)) * FPB + (lane >> 4) * 16;
    const uint32_t bRel = (uint32_t)((((lane >> 4) & 1) * 8 + (lane & 7)) * FPB +
                                     ((lane >> 3) & 1) * 16);
    const uint32_t vRel = (uint32_t)((lane & 15) * FPB + (lane >> 4) * 16);
    const int r0 = wid * 16 + g;

    for (int kt = 0; kt < 32; ++kt) {
        CP_WAIT(0);
        __syncthreads();   // all warps done with slot (kt-1)&1 reads before new writes
        if (kt < 31) {
            load_kv(kt + 1);
            CP_COMMIT();
            load_bias(kt + 1);
        }
        uint32_t stg = smb + STG_OFF + (uint32_t)(kt & 1) * STG_SZ;
        const float* bwc = bw + (kt & 1) * 192;

        // ---- S = Qh Kh^T + Qh Kl^T + Ql Kh^T (term-major) ----
        float s[8][4];
#pragma unroll
        for (int j = 0; j < 8; j++)
#pragma unroll
            for (int q = 0; q < 4; q++) s[j][q] = 0.0f;
#pragma unroll
        for (int kk = 0; kk < 4; ++kk) {
            uint32_t aH[4], aL[4], bH[4][4], bL[4][4];
            ldsm_x4(aH, aAddr + kk * 32);
            ldsm_x4(aL, aAddr + kk * 32 + Q_BYTES);
#pragma unroll
            for (int p = 0; p < 4; ++p) {
                uint32_t ba = stg + bRel + p * (16 * FPB) + kk * 32;
                ldsm_x4(bH[p], ba);
                ldsm_x4(bL[p], ba + KV_BYTES);
            }
#pragma unroll
            for (int p = 0; p < 4; ++p) {
                mma16816(s[2 * p], aH, &bH[p][0]);
                mma16816(s[2 * p + 1], aH, &bH[p][2]);
            }
#pragma unroll
            for (int p = 0; p < 4; ++p) {
                mma16816(s[2 * p], aH, &bL[p][0]);
                mma16816(s[2 * p + 1], aH, &bL[p][2]);
            }
#pragma unroll
            for (int p = 0; p < 4; ++p) {
                mma16816(s[2 * p], aL, &bH[p][0]);
                mma16816(s[2 * p + 1], aL, &bH[p][2]);
            }
        }

        // ---- bias + online softmax ----
        float mx0 = -INFINITY, mx1 = -INFINITY;
#pragma unroll
        for (int j = 0; j < 8; j++) {
            int c = 8 * j + 2 * tq;
            s[j][0] += bwc[c - r0 + 127];
            s[j][1] += bwc[c + 1 - r0 + 127];
            s[j][2] += bwc[c - (r0 + 8) + 127];
            s[j][3] += bwc[c + 1 - (r0 + 8) + 127];
            mx0 = fmaxf(mx0, fmaxf(s[j][0], s[j][1]));
            mx1 = fmaxf(mx1, fmaxf(s[j][2], s[j][3]));
        }
        mx0 = fmaxf(mx0, __shfl_xor_sync(0xffffffffu, mx0, 1));
        mx0 = fmaxf(mx0, __shfl_xor_sync(0xffffffffu, mx0, 2));
        mx1 = fmaxf(mx1, __shfl_xor_sync(0xffffffffu, mx1, 1));
        mx1 = fmaxf(mx1, __shfl_xor_sync(0xffffffffu, mx1, 2));
        float mn0 = fmaxf(m_[0], mx0), mn1 = fmaxf(m_[1], mx1);
        float al0 = __expf(m_[0] - mn0), al1 = __expf(m_[1] - mn1);

        uint32_t pH[8][2], pL[8][2];
        float sum0 = 0.0f, sum1 = 0.0f;
#pragma unroll
        for (int j = 0; j < 8; j++) {
            float e0 = __expf(s[j][0] - mn0), e1 = __expf(s[j][1] - mn0);
            float e2 = __expf(s[j][2] - mn1), e3 = __expf(s[j][3] - mn1);
            sum0 += e0 + e1;
            sum1 += e2 + e3;
            __nv_bfloat162 h01 = __floats2bfloat162_rn(e0, e1);
            __nv_bfloat162 h23 = __floats2bfloat162_rn(e2, e3);
            pH[j][0] = *(uint32_t*)&h01;
            pH[j][1] = *(uint32_t*)&h23;
            pL[j][0] = packbf2(e0 - __bfloat162float(h01.x), e1 - __bfloat162float(h01.y));
            pL[j][1] = packbf2(e2 - __bfloat162float(h23.x), e3 - __bfloat162float(h23.y));
        }
        sum0 += __shfl_xor_sync(0xffffffffu, sum0, 1);
        sum0 += __shfl_xor_sync(0xffffffffu, sum0, 2);
        sum1 += __shfl_xor_sync(0xffffffffu, sum1, 1);
        sum1 += __shfl_xor_sync(0xffffffffu, sum1, 2);
        l_[0] = l_[0] * al0 + sum0;
        l_[1] = l_[1] * al1 + sum1;
        m_[0] = mn0;
        m_[1] = mn1;
#pragma unroll
        for (int j = 0; j < 8; j++) {
            o[j][0] *= al0; o[j][1] *= al0;
            o[j][2] *= al1; o[j][3] *= al1;
        }

        // ---- O += P V (term-major) ----
        uint32_t vstg = stg + 2 * KV_BYTES;
#pragma unroll
        for (int kk = 0; kk < 4; ++kk) {
            uint32_t aPh[4] = {pH[2 * kk][0], pH[2 * kk][1],
                               pH[2 * kk + 1][0], pH[2 * kk + 1][1]};
            uint32_t aPl[4] = {pL[2 * kk][0], pL[2 * kk][1],
                               pL[2 * kk + 1][0], pL[2 * kk + 1][1]};
            uint32_t vh[4][4], vl[4][4];
#pragma unroll
            for (int p = 0; p < 4; ++p) {
                uint32_t va = vstg + vRel + kk * (16 * FPB) + p * 32;
                ldsm_x4_t(vh[p], va);
                ldsm_x4_t(vl[p], va + KV_BYTES);
            }
#pragma unroll
            for (int p = 0; p < 4; ++p) {
                mma16816(o[2 * p], aPh, &vh[p][0]);
                mma16816(o[2 * p + 1], aPh, &vh[p][2]);
            }
#pragma unroll
            for (int p = 0; p < 4; ++p) {
                mma16816(o[2 * p], aPh, &vl[p][0]);
                mma16816(o[2 * p + 1], aPh, &vl[p][2]);
            }
#pragma unroll
            for (int p = 0; p < 4; ++p) {
                mma16816(o[2 * p], aPl, &vh[p][0]);
                mma16816(o[2 * p + 1], aPl, &vh[p][2]);
            }
        }
    }

    float inv0 = 1.0f / l_[0], inv1 = 1.0f / l_[1];
    size_t rbase = (size_t)b * SS + qt * 128 + wid * 16 + g;
#pragma unroll
    for (int j = 0; j < 8; j++) {
        int col = h * DK + 8 * j + 2 * tq;
        float x0 = o[j][0] * inv0, x1 = o[j][1] * inv0;
        float x2 = o[j][2] * inv1, x3 = o[j][3] * inv1;
        __nv_bfloat162 h0 = __floats2bfloat162_rn(x0, x1);
        __nv_bfloat162 l0 = __floats2bfloat162_rn(x0 - __bfloat162float(h0.x),
                                                  x1 - __bfloat162float(h0.y));
        __nv_bfloat162 h1 = __floats2bfloat162_rn(x2, x3);
        __nv_bfloat162 l1 = __floats2bfloat162_rn(x2 - __bfloat162float(h1.x),
                                                  x3 - __bfloat162float(h1.y));
        *(__nv_bfloat162*)(g_ch + rbase * DM + col) = h0;
        *(__nv_bfloat162*)(g_cl + rbase * DM + col) = l0;
        *(__nv_bfloat162*)(g_ch + (rbase + 8) * DM + col) = h1;
        *(__nv_bfloat162*)(g_cl + (rbase + 8) * DM + col) = l1;
    }
}

// ---------------------------------------------------------------------------
extern "C" void kernel_launch(void* const* d_in, const int* in_sizes, int n_in,
                              void* d_out, int out_size) {
    const float* hs = (const float*)d_in[0];
    const float* Wq = (const float*)d_in[1];
    const float* Wk = (const float*)d_in[2];
    const float* Wv = (const float*)d_in[3];
    const float* Wo = (const float*)d_in[4];
    const float* rb = (const float*)d_in[5];

    cudaFuncSetAttribute(flash_kernel,
                         cudaFuncAttributeMaxDynamicSharedMemorySize, FSMEM);
    cudaFuncSetAttribute(gemm_qkv_kernel,
                         cudaFuncAttributeMaxDynamicSharedMemorySize, GSMEM);
    cudaFuncSetAttribute(gemm_out_kernel,
                         cudaFuncAttributeMaxDynamicSharedMemorySize, GSMEM);

    bias_table_kernel<<<NH, 256>>>(rb);
    split_kernel<<<(MTOT * DM / 4) / 256, 256>>>((const float4*)hs);
    tsplit_kernel<<<dim3(32, 32, 4), dim3(32, 8)>>>(Wq, Wk, Wv, Wo);
    gemm_qkv_kernel<<<dim3(MTOT / 256, DM / 128, 3), 256, GSMEM>>>();
    flash_kernel<<<dim3(SS / 128, NH, BB), 256, FSMEM>>>();
    gemm_out_kernel<<<dim3(MTOT / 256, DM / 128), 256, GSMEM>>>((float*)d_out);
}

// round 7
// speedup vs baseline: 3.1314x; 1.0202x over previous
#include <cuda_runtime.h>
#include <cuda_bf16.h>
#include <math.h>
#include <stdint.h>

#define BB 2
#define SS 2048
#define DM 1024
#define NH 16
#define DK 64
#define MTOT (BB * SS)  // 4096

// ---------------- device scratch (allocation-free) ----------------
__device__ float g_bias[NH * (2 * SS - 1)];
__device__ __nv_bfloat16 g_xh[MTOT * DM];
__device__ __nv_bfloat16 g_xl[MTOT * DM];
__device__ __nv_bfloat16 g_wth[4 * DM * DM];
__device__ __nv_bfloat16 g_wtl[4 * DM * DM];
__device__ __nv_bfloat16 g_ch[MTOT * DM];
__device__ __nv_bfloat16 g_cl[MTOT * DM];
__device__ __nv_bfloat16 g_qh[BB * NH * SS * DK];
__device__ __nv_bfloat16 g_ql[BB * NH * SS * DK];
__device__ __nv_bfloat16 g_kh[BB * NH * SS * DK];
__device__ __nv_bfloat16 g_kl[BB * NH * SS * DK];
__device__ __nv_bfloat16 g_vh[BB * NH * SS * DK];
__device__ __nv_bfloat16 g_vl[BB * NH * SS * DK];

// ---------------- PTX helpers (arch-agnostic, sm_80-era) ----------------
__device__ __forceinline__ uint32_t smem_u32(const void* p) {
    uint32_t a;
    asm("{ .reg .u64 t; cvta.to.shared.u64 t, %1; cvt.u32.u64 %0, t; }"
        : "=r"(a) : "l"(p));
    return a;
}
__device__ __forceinline__ void cp16(uint32_t dst, const void* src) {
    uint64_t g = __cvta_generic_to_global(src);
    asm volatile("cp.async.cg.shared.global [%0], [%1], 16;" :: "r"(dst), "l"(g));
}
#define CP_COMMIT() asm volatile("cp.async.commit_group;" ::: "memory")
#define CP_WAIT(n)  asm volatile("cp.async.wait_group %0;" :: "n"(n) : "memory")

__device__ __forceinline__ void ldsm_x4(uint32_t* r, uint32_t addr) {
    asm volatile("ldmatrix.sync.aligned.m8n8.x4.shared.b16 {%0,%1,%2,%3}, [%4];"
                 : "=r"(r[0]), "=r"(r[1]), "=r"(r[2]), "=r"(r[3]) : "r"(addr));
}
__device__ __forceinline__ void ldsm_x4_t(uint32_t* r, uint32_t addr) {
    asm volatile("ldmatrix.sync.aligned.m8n8.x4.trans.shared.b16 {%0,%1,%2,%3}, [%4];"
                 : "=r"(r[0]), "=r"(r[1]), "=r"(r[2]), "=r"(r[3]) : "r"(addr));
}
__device__ __forceinline__ void mma16816(float* c, const uint32_t* a, const uint32_t* b) {
    asm volatile(
        "mma.sync.aligned.m16n8k16.row.col.f32.bf16.bf16.f32 "
        "{%0,%1,%2,%3}, {%4,%5,%6,%7}, {%8,%9}, {%0,%1,%2,%3};"
        : "+f"(c[0]), "+f"(c[1]), "+f"(c[2]), "+f"(c[3])
        : "r"(a[0]), "r"(a[1]), "r"(a[2]), "r"(a[3]), "r"(b[0]), "r"(b[1]));
}
__device__ __forceinline__ uint32_t packbf2(float x0, float x1) {
    __nv_bfloat162 t = __floats2bfloat162_rn(x0, x1);
    return *(uint32_t*)&t;
}

// ---------------------------------------------------------------------------
// Bias table
// ---------------------------------------------------------------------------
__global__ void bias_table_kernel(const float* __restrict__ rel_bias) {
    int h = blockIdx.x;
    for (int idx = threadIdx.x; idx < 2 * SS - 1; idx += blockDim.x) {
        int rel = idx - (SS - 1);
        int base = (rel > 0) ? 16 : 0;
        int rp = rel < 0 ? -rel : rel;
        int bucket;
        if (rp < 8) {
            bucket = rp;
        } else {
            float v = logf((float)rp * 0.125f) / logf(16.0f) * 8.0f;
            int bb = 8 + (int)v;
            bucket = bb < 15 ? bb : 15;
        }
        g_bias[h * (2 * SS - 1) + idx] = rel_bias[(base + bucket) * NH + h];
    }
}

// ---------------------------------------------------------------------------
// Split hidden_states: fp32 -> bf16 hi + bf16 lo
// ---------------------------------------------------------------------------
__global__ void split_kernel(const float4* __restrict__ src) {
    int i = blockIdx.x * blockDim.x + threadIdx.x;
    float4 x = src[i];
    __nv_bfloat162 hA = __floats2bfloat162_rn(x.x, x.y);
    __nv_bfloat162 hB = __floats2bfloat162_rn(x.z, x.w);
    __nv_bfloat162 lA = __floats2bfloat162_rn(x.x - __bfloat162float(hA.x),
                                              x.y - __bfloat162float(hA.y));
    __nv_bfloat162 lB = __floats2bfloat162_rn(x.z - __bfloat162float(hB.x),
                                              x.w - __bfloat162float(hB.y));
    *(__nv_bfloat162*)(g_xh + 4 * i) = hA;
    *(__nv_bfloat162*)(g_xh + 4 * i + 2) = hB;
    *(__nv_bfloat162*)(g_xl + 4 * i) = lA;
    *(__nv_bfloat162*)(g_xl + 4 * i + 2) = lB;
}

// transpose + split weights
__global__ void tsplit_kernel(const float* __restrict__ W0, const float* __restrict__ W1,
                              const float* __restrict__ W2, const float* __restrict__ W3) {
    __shared__ float t[32][33];
    int z = blockIdx.z;
    const float* W = z == 0 ? W0 : z == 1 ? W1 : z == 2 ? W2 : W3;
    __nv_bfloat16* Th = g_wth + (size_t)z * DM * DM;
    __nv_bfloat16* Tl = g_wtl + (size_t)z * DM * DM;
    int k0 = blockIdx.x * 32, n0 = blockIdx.y * 32;
    int tx = threadIdx.x, ty = threadIdx.y;
#pragma unroll
    for (int r = 0; r < 32; r += 8)
        t[ty + r][tx] = W[(size_t)(k0 + ty + r) * DM + n0 + tx];
    __syncthreads();
#pragma unroll
    for (int r = 0; r < 32; r += 8) {
        float x = t[tx][ty + r];
        __nv_bfloat16 h = __float2bfloat16_rn(x);
        size_t o = (size_t)(n0 + ty + r) * DM + k0 + tx;
        Th[o] = h;
        Tl[o] = __float2bfloat16_rn(x - __bfloat162float(h));
    }
}

// ---------------------------------------------------------------------------
// mma.sync bf16x3 GEMM: BM=128, BN=128, BK=32, 8 warps (4x2), warp 32x64,
// 2-stage ring, ONE barrier/chunk, 2 blocks/SM (4 warps/SMSP, independent CTAs)
// ---------------------------------------------------------------------------
#define LDK 40
#define A_PER (128 * LDK * 2)        // 10240
#define B_PER (128 * LDK * 2)        // 10240
#define BOFF (2 * A_PER)             // 20480
#define STAGE (2 * A_PER + 2 * B_PER)  // 40960
#define NSTG 2
#define GSMEM (NSTG * STAGE)         // 81920 (x2 blocks = 160K/SM)

__device__ __forceinline__ void gemm_body(
    const __nv_bfloat16* __restrict__ Ah, const __nv_bfloat16* __restrict__ Al,
    const __nv_bfloat16* __restrict__ Bh, const __nv_bfloat16* __restrict__ Bl,
    float* __restrict__ outp, int mode)
{
    extern __shared__ char sm[];
    const uint32_t smb = smem_u32(sm);
    const int tid = threadIdx.x;
    const int wid = tid >> 5, lane = tid & 31;
    const int wm = wid >> 1, wn = wid & 1;
    const int bm = blockIdx.x * 128, bn = blockIdx.y * 128;

    float acc[2][8][4];
#pragma unroll
    for (int i = 0; i < 2; i++)
#pragma unroll
        for (int j = 0; j < 8; j++)
#pragma unroll
            for (int q = 0; q < 4; q++) acc[i][j][q] = 0.0f;

    const uint32_t aRel = (uint32_t)((wm * 32 + (lane & 15)) * LDK + (lane >> 4) * 8) * 2;
    const uint32_t bRel = (uint32_t)BOFF +
        (uint32_t)((wn * 64 + ((lane >> 4) & 1) * 8 + (lane & 7)) * LDK +
                   ((lane >> 3) & 1) * 8) * 2;

    auto load_stage = [&](int c) {
        uint32_t st = smb + (uint32_t)(c & 1) * STAGE;
        int k0 = c * 32;
#pragma unroll
        for (int i = 0; i < 2; i++) {
            int e = tid + 256 * i;
            int row = e >> 2, kq = e & 3;
            uint32_t d = st + (uint32_t)(row * LDK + kq * 8) * 2;
            size_t ga = (size_t)(bm + row) * DM + k0 + kq * 8;
            size_t gb = (size_t)(bn + row) * DM + k0 + kq * 8;
            cp16(d, Ah + ga);
            cp16(d + A_PER, Al + ga);
            cp16(d + BOFF, Bh + gb);
            cp16(d + BOFF + B_PER, Bl + gb);
        }
    };

    load_stage(0);
    CP_COMMIT();

    for (int c = 0; c < 32; ++c) {
        CP_WAIT(0);         // group c complete
        __syncthreads();    // all warps done reading slot (c-1)&1
        if (c + 1 < 32) {
            load_stage(c + 1);   // writes slot (c+1)&1 — safe per barrier above
            CP_COMMIT();
        }
        uint32_t st = smb + (uint32_t)(c & 1) * STAGE;
        uint32_t aBase = st + aRel, bBase = st + bRel;
#pragma unroll
        for (int ks = 0; ks < 2; ++ks) {
            uint32_t koff = ks * 32;
            uint32_t aH[2][4], aL[2][4];
#pragma unroll
            for (int mf = 0; mf < 2; ++mf) {
                ldsm_x4(aH[mf], aBase + koff + mf * (16 * LDK * 2));
                ldsm_x4(aL[mf], aBase + koff + mf * (16 * LDK * 2) + A_PER);
            }
#pragma unroll
            for (int p = 0; p < 4; ++p) {
                uint32_t bH[4], bL[4];
                uint32_t ba = bBase + koff + p * (16 * LDK * 2);
                ldsm_x4(bH, ba);
                ldsm_x4(bL, ba + B_PER);
                // 12 mma per p; each acc chain touched 3x at distance 4
#pragma unroll
                for (int mf = 0; mf < 2; ++mf) {
                    mma16816(acc[mf][2 * p], aH[mf], &bH[0]);
                    mma16816(acc[mf][2 * p + 1], aH[mf], &bH[2]);
                }
#pragma unroll
                for (int mf = 0; mf < 2; ++mf) {
                    mma16816(acc[mf][2 * p], aH[mf], &bL[0]);
                    mma16816(acc[mf][2 * p + 1], aH[mf], &bL[2]);
                }
#pragma unroll
                for (int mf = 0; mf < 2; ++mf) {
                    mma16816(acc[mf][2 * p], aL[mf], &bH[0]);
                    mma16816(acc[mf][2 * p + 1], aL[mf], &bH[2]);
                }
            }
        }
    }

    const int g = lane >> 2, t2 = (lane & 3) * 2;
#pragma unroll
    for (int mf = 0; mf < 2; ++mf) {
#pragma unroll
        for (int nf = 0; nf < 8; ++nf) {
            int n = bn + wn * 64 + nf * 8 + t2;
            int m0 = bm + wm * 32 + mf * 16 + g;
            int m1 = m0 + 8;
            if (mode == 3) {
                *(float2*)(outp + (size_t)m0 * DM + n) =
                    make_float2(acc[mf][nf][0], acc[mf][nf][1]);
                *(float2*)(outp + (size_t)m1 * DM + n) =
                    make_float2(acc[mf][nf][2], acc[mf][nf][3]);
            } else {
                __nv_bfloat16* Oh = mode == 0 ? g_qh : (mode == 1 ? g_kh : g_vh);
                __nv_bfloat16* Ol = mode == 0 ? g_ql : (mode == 1 ? g_kl : g_vl);
                int hh = n >> 6, d = n & 63;
                size_t o0 = (((size_t)(m0 >> 11) * NH + hh) * SS + (m0 & (SS - 1))) * DK + d;
                size_t o1 = (((size_t)(m1 >> 11) * NH + hh) * SS + (m1 & (SS - 1))) * DK + d;
                float v0 = acc[mf][nf][0], v1 = acc[mf][nf][1];
                float v2 = acc[mf][nf][2], v3 = acc[mf][nf][3];
                __nv_bfloat162 h0 = __floats2bfloat162_rn(v0, v1);
                __nv_bfloat162 l0 = __floats2bfloat162_rn(v0 - __bfloat162float(h0.x),
                                                          v1 - __bfloat162float(h0.y));
                __nv_bfloat162 h1 = __floats2bfloat162_rn(v2, v3);
                __nv_bfloat162 l1 = __floats2bfloat162_rn(v2 - __bfloat162float(h1.x),
                                                          v3 - __bfloat162float(h1.y));
                *(__nv_bfloat162*)(Oh + o0) = h0;
                *(__nv_bfloat162*)(Ol + o0) = l0;
                *(__nv_bfloat162*)(Oh + o1) = h1;
                *(__nv_bfloat162*)(Ol + o1) = l1;
            }
        }
    }
}

__global__ void __launch_bounds__(256, 2) gemm_qkv_kernel() {
    int z = blockIdx.z;
    gemm_body(g_xh, g_xl, g_wth + (size_t)z * DM * DM, g_wtl + (size_t)z * DM * DM,
              nullptr, z);
}
__global__ void __launch_bounds__(256, 2) gemm_out_kernel(float* __restrict__ out) {
    gemm_body(g_ch, g_cl, g_wth + 3ull * DM * DM, g_wtl + 3ull * DM * DM, out, 3);
}

// ---------------------------------------------------------------------------
// Flash attention on mma.sync (byte-identical to round 6).
// ---------------------------------------------------------------------------
#define FPB 144
#define Q_BYTES (128 * FPB)
#define KV_BYTES (64 * FPB)
#define STG_OFF (2 * Q_BYTES)
#define STG_SZ (4 * KV_BYTES)
#define BIAS_OFF (STG_OFF + 2 * STG_SZ)
#define FSMEM (BIAS_OFF + 2 * 192 * 4)

__global__ void __launch_bounds__(256) flash_kernel() {
    extern __shared__ char sm[];
    const uint32_t smb = smem_u32(sm);
    const int tid = threadIdx.x, wid = tid >> 5, lane = tid & 31;
    const int g = lane >> 2, tq = lane & 3;
    const int qt = blockIdx.x, h = blockIdx.y, b = blockIdx.z;
    const int bh = b * NH + h;

    const __nv_bfloat16* Qh = g_qh + ((size_t)bh * SS + qt * 128) * DK;
    const __nv_bfloat16* Ql = g_ql + ((size_t)bh * SS + qt * 128) * DK;
    const __nv_bfloat16* Kh = g_kh + (size_t)bh * SS * DK;
    const __nv_bfloat16* Kl = g_kl + (size_t)bh * SS * DK;
    const __nv_bfloat16* Vh = g_vh + (size_t)bh * SS * DK;
    const __nv_bfloat16* Vl = g_vl + (size_t)bh * SS * DK;
    float* bw = (float*)(sm + BIAS_OFF);

#pragma unroll
    for (int i = 0; i < 4; i++) {
        int e = tid + 256 * i;
        int row = e >> 3, qd = e & 7;
        uint32_t d = smb + row * FPB + qd * 16;
        cp16(d, Qh + row * DK + qd * 8);
        cp16(d + Q_BYTES, Ql + row * DK + qd * 8);
    }

    auto load_kv = [&](int c) {
        uint32_t st = smb + STG_OFF + (uint32_t)(c & 1) * STG_SZ;
#pragma unroll
        for (int i = 0; i < 2; i++) {
            int e = tid + 256 * i;
            int row = e >> 3, qd = e & 7;
            uint32_t d = st + row * FPB + qd * 16;
            size_t src = (size_t)(c * 64 + row) * DK + qd * 8;
            cp16(d, Kh + src);
            cp16(d + KV_BYTES, Kl + src);
            cp16(d + 2 * KV_BYTES, Vh + src);
            cp16(d + 3 * KV_BYTES, Vl + src);
        }
    };
    auto load_bias = [&](int c) {
        if (tid < 191) {
            int base = h * (2 * SS - 1) + c * 64 - qt * 128 + 1920;
            bw[(c & 1) * 192 + tid] = g_bias[base + tid];
        }
    };

    load_kv(0);
    CP_COMMIT();
    load_bias(0);

    float m_[2] = {-INFINITY, -INFINITY};
    float l_[2] = {0.0f, 0.0f};
    float o[8][4];
#pragma unroll
    for (int j = 0; j < 8; j++)
#pragma unroll
        for (int q = 0; q < 4; q++) o[j][q] = 0.0f;

    const uint32_t aAddr = smb + (uint32_t)(wid * 16 + (lane & 15)) * FPB + (lane >> 4) * 16;
    const uint32_t bRel = (uint32_t)((((lane >> 4) & 1) * 8 + (lane & 7)) * FPB +
                                     ((lane >> 3) & 1) * 16);
    const uint32_t vRel = (uint32_t)((lane & 15) * FPB + (lane >> 4) * 16);
    const int r0 = wid * 16 + g;

    for (int kt = 0; kt < 32; ++kt) {
        CP_WAIT(0);
        __syncthreads();
        if (kt < 31) {
            load_kv(kt + 1);
            CP_COMMIT();
            load_bias(kt + 1);
        }
        uint32_t stg = smb + STG_OFF + (uint32_t)(kt & 1) * STG_SZ;
        const float* bwc = bw + (kt & 1) * 192;

        float s[8][4];
#pragma unroll
        for (int j = 0; j < 8; j++)
#pragma unroll
            for (int q = 0; q < 4; q++) s[j][q] = 0.0f;
#pragma unroll
        for (int kk = 0; kk < 4; ++kk) {
            uint32_t aH[4], aL[4], bH[4][4], bL[4][4];
            ldsm_x4(aH, aAddr + kk * 32);
            ldsm_x4(aL, aAddr + kk * 32 + Q_BYTES);
#pragma unroll
            for (int p = 0; p < 4; ++p) {
                uint32_t ba = stg + bRel + p * (16 * FPB) + kk * 32;
                ldsm_x4(bH[p], ba);
                ldsm_x4(bL[p], ba + KV_BYTES);
            }
#pragma unroll
            for (int p = 0; p < 4; ++p) {
                mma16816(s[2 * p], aH, &bH[p][0]);
                mma16816(s[2 * p + 1], aH, &bH[p][2]);
            }
#pragma unroll
            for (int p = 0; p < 4; ++p) {
                mma16816(s[2 * p], aH, &bL[p][0]);
                mma16816(s[2 * p + 1], aH, &bL[p][2]);
            }
#pragma unroll
            for (int p = 0; p < 4; ++p) {
                mma16816(s[2 * p], aL, &bH[p][0]);
                mma16816(s[2 * p + 1], aL, &bH[p][2]);
            }
        }

        float mx0 = -INFINITY, mx1 = -INFINITY;
#pragma unroll
        for (int j = 0; j < 8; j++) {
            int c = 8 * j + 2 * tq;
            s[j][0] += bwc[c - r0 + 127];
            s[j][1] += bwc[c + 1 - r0 + 127];
            s[j][2] += bwc[c - (r0 + 8) + 127];
            s[j][3] += bwc[c + 1 - (r0 + 8) + 127];
            mx0 = fmaxf(mx0, fmaxf(s[j][0], s[j][1]));
            mx1 = fmaxf(mx1, fmaxf(s[j][2], s[j][3]));
        }
        mx0 = fmaxf(mx0, __shfl_xor_sync(0xffffffffu, mx0, 1));
        mx0 = fmaxf(mx0, __shfl_xor_sync(0xffffffffu, mx0, 2));
        mx1 = fmaxf(mx1, __shfl_xor_sync(0xffffffffu, mx1, 1));
        mx1 = fmaxf(mx1, __shfl_xor_sync(0xffffffffu, mx1, 2));
        float mn0 = fmaxf(m_[0], mx0), mn1 = fmaxf(m_[1], mx1);
        float al0 = __expf(m_[0] - mn0), al1 = __expf(m_[1] - mn1);

        uint32_t pH[8][2], pL[8][2];
        float sum0 = 0.0f, sum1 = 0.0f;
#pragma unroll
        for (int j = 0; j < 8; j++) {
            float e0 = __expf(s[j][0] - mn0), e1 = __expf(s[j][1] - mn0);
            float e2 = __expf(s[j][2] - mn1), e3 = __expf(s[j][3] - mn1);
            sum0 += e0 + e1;
            sum1 += e2 + e3;
            __nv_bfloat162 h01 = __floats2bfloat162_rn(e0, e1);
            __nv_bfloat162 h23 = __floats2bfloat162_rn(e2, e3);
            pH[j][0] = *(uint32_t*)&h01;
            pH[j][1] = *(uint32_t*)&h23;
            pL[j][0] = packbf2(e0 - __bfloat162float(h01.x), e1 - __bfloat162float(h01.y));
            pL[j][1] = packbf2(e2 - __bfloat162float(h23.x), e3 - __bfloat162float(h23.y));
        }
        sum0 += __shfl_xor_sync(0xffffffffu, sum0, 1);
        sum0 += __shfl_xor_sync(0xffffffffu, sum0, 2);
        sum1 += __shfl_xor_sync(0xffffffffu, sum1, 1);
        sum1 += __shfl_xor_sync(0xffffffffu, sum1, 2);
        l_[0] = l_[0] * al0 + sum0;
        l_[1] = l_[1] * al1 + sum1;
        m_[0] = mn0;
        m_[1] = mn1;
#pragma unroll
        for (int j = 0; j < 8; j++) {
            o[j][0] *= al0; o[j][1] *= al0;
            o[j][2] *= al1; o[j][3] *= al1;
        }

        uint32_t vstg = stg + 2 * KV_BYTES;
#pragma unroll
        for (int kk = 0; kk < 4; ++kk) {
            uint32_t aPh[4] = {pH[2 * kk][0], pH[2 * kk][1],
                               pH[2 * kk + 1][0], pH[2 * kk + 1][1]};
            uint32_t aPl[4] = {pL[2 * kk][0], pL[2 * kk][1],
                               pL[2 * kk + 1][0], pL[2 * kk + 1][1]};
            uint32_t vh[4][4], vl[4][4];
#pragma unroll
            for (int p = 0; p < 4; ++p) {
                uint32_t va = vstg + vRel + kk * (16 * FPB) + p * 32;
                ldsm_x4_t(vh[p], va);
                ldsm_x4_t(vl[p], va + KV_BYTES);
            }
#pragma unroll
            for (int p = 0; p < 4; ++p) {
                mma16816(o[2 * p], aPh, &vh[p][0]);
                mma16816(o[2 * p + 1], aPh, &vh[p][2]);
            }
#pragma unroll
            for (int p = 0; p < 4; ++p) {
                mma16816(o[2 * p], aPh, &vl[p][0]);
                mma16816(o[2 * p + 1], aPh, &vl[p][2]);
            }
#pragma unroll
            for (int p = 0; p < 4; ++p) {
                mma16816(o[2 * p], aPl, &vh[p][0]);
                mma16816(o[2 * p + 1], aPl, &vh[p][2]);
            }
        }
    }

    float inv0 = 1.0f / l_[0], inv1 = 1.0f / l_[1];
    size_t rbase = (size_t)b * SS + qt * 128 + wid * 16 + g;
#pragma unroll
    for (int j = 0; j < 8; j++) {
        int col = h * DK + 8 * j + 2 * tq;
        float x0 = o[j][0] * inv0, x1 = o[j][1] * inv0;
        float x2 = o[j][2] * inv1, x3 = o[j][3] * inv1;
        __nv_bfloat162 h0 = __floats2bfloat162_rn(x0, x1);
        __nv_bfloat162 l0 = __floats2bfloat162_rn(x0 - __bfloat162float(h0.x),
                                                  x1 - __bfloat162float(h0.y));
        __nv_bfloat162 h1 = __floats2bfloat162_rn(x2, x3);
        __nv_bfloat162 l1 = __floats2bfloat162_rn(x2 - __bfloat162float(h1.x),
                                                  x3 - __bfloat162float(h1.y));
        *(__nv_bfloat162*)(g_ch + rbase * DM + col) = h0;
        *(__nv_bfloat162*)(g_cl + rbase * DM + col) = l0;
        *(__nv_bfloat162*)(g_ch + (rbase + 8) * DM + col) = h1;
        *(__nv_bfloat162*)(g_cl + (rbase + 8) * DM + col) = l1;
    }
}

// ---------------------------------------------------------------------------
extern "C" void kernel_launch(void* const* d_in, const int* in_sizes, int n_in,
                              void* d_out, int out_size) {
    const float* hs = (const float*)d_in[0];
    const float* Wq = (const float*)d_in[1];
    const float* Wk = (const float*)d_in[2];
    const float* Wv = (const float*)d_in[3];
    const float* Wo = (const float*)d_in[4];
    const float* rb = (const float*)d_in[5];

    cudaFuncSetAttribute(flash_kernel,
                         cudaFuncAttributeMaxDynamicSharedMemorySize, FSMEM);
    cudaFuncSetAttribute(gemm_qkv_kernel,
                         cudaFuncAttributeMaxDynamicSharedMemorySize, GSMEM);
    cudaFuncSetAttribute(gemm_out_kernel,
                         cudaFuncAttributeMaxDynamicSharedMemorySize, GSMEM);

    bias_table_kernel<<<NH, 256>>>(rb);
    split_kernel<<<(MTOT * DM / 4) / 256, 256>>>((const float4*)hs);
    tsplit_kernel<<<dim3(32, 32, 4), dim3(32, 8)>>>(Wq, Wk, Wv, Wo);
    gemm_qkv_kernel<<<dim3(MTOT / 128, DM / 128, 3), 256, GSMEM>>>();
    flash_kernel<<<dim3(SS / 128, NH, BB), 256, FSMEM>>>();
    gemm_out_kernel<<<dim3(MTOT / 128, DM / 128), 256, GSMEM>>>((float*)d_out);
}

// round 8
// speedup vs baseline: 3.8545x; 1.2309x over previous
#include <cuda_runtime.h>
#include <cuda_bf16.h>
#include <cuda_fp16.h>
#include <math.h>
#include <stdint.h>

#define BB 2
#define SS 2048
#define DM 1024
#define NH 16
#define DK 64
#define MTOT (BB * SS)  // 4096

// ---------------- device scratch (allocation-free) ----------------
__device__ float g_bias[NH * (2 * SS - 1)];
__device__ __nv_bfloat16 g_xh[MTOT * DM];
__device__ __nv_bfloat16 g_xl[MTOT * DM];
__device__ __nv_bfloat16 g_wth[3 * DM * DM];  // Wq/Wk/Wv ^T hi (K-major)
__device__ __nv_bfloat16 g_wtl[3 * DM * DM];  // lo
__device__ __half        g_wo16[DM * DM];     // Wo^T single fp16
__device__ __half        g_ch[MTOT * DM];     // ctx fp16 hi (exact split)
__device__ __half        g_cl[MTOT * DM];     // ctx fp16 lo
__device__ __nv_bfloat16 g_qh[BB * NH * SS * DK];
__device__ __nv_bfloat16 g_ql[BB * NH * SS * DK];
__device__ __nv_bfloat16 g_kh[BB * NH * SS * DK];
__device__ __nv_bfloat16 g_kl[BB * NH * SS * DK];
__device__ __half        g_v16[BB * NH * SS * DK];  // V single fp16

// ---------------- PTX helpers (arch-agnostic, sm_80-era) ----------------
__device__ __forceinline__ uint32_t smem_u32(const void* p) {
    uint32_t a;
    asm("{ .reg .u64 t; cvta.to.shared.u64 t, %1; cvt.u32.u64 %0, t; }"
        : "=r"(a) : "l"(p));
    return a;
}
__device__ __forceinline__ void cp16(uint32_t dst, const void* src) {
    uint64_t g = __cvta_generic_to_global(src);
    asm volatile("cp.async.cg.shared.global [%0], [%1], 16;" :: "r"(dst), "l"(g));
}
#define CP_COMMIT() asm volatile("cp.async.commit_group;" ::: "memory")
#define CP_WAIT(n)  asm volatile("cp.async.wait_group %0;" :: "n"(n) : "memory")

__device__ __forceinline__ void ldsm_x4(uint32_t* r, uint32_t addr) {
    asm volatile("ldmatrix.sync.aligned.m8n8.x4.shared.b16 {%0,%1,%2,%3}, [%4];"
                 : "=r"(r[0]), "=r"(r[1]), "=r"(r[2]), "=r"(r[3]) : "r"(addr));
}
__device__ __forceinline__ void ldsm_x4_t(uint32_t* r, uint32_t addr) {
    asm volatile("ldmatrix.sync.aligned.m8n8.x4.trans.shared.b16 {%0,%1,%2,%3}, [%4];"
                 : "=r"(r[0]), "=r"(r[1]), "=r"(r[2]), "=r"(r[3]) : "r"(addr));
}
__device__ __forceinline__ void mma16816(float* c, const uint32_t* a, const uint32_t* b) {
    asm volatile(
        "mma.sync.aligned.m16n8k16.row.col.f32.bf16.bf16.f32 "
        "{%0,%1,%2,%3}, {%4,%5,%6,%7}, {%8,%9}, {%0,%1,%2,%3};"
        : "+f"(c[0]), "+f"(c[1]), "+f"(c[2]), "+f"(c[3])
        : "r"(a[0]), "r"(a[1]), "r"(a[2]), "r"(a[3]), "r"(b[0]), "r"(b[1]));
}
__device__ __forceinline__ void mma16816h(float* c, const uint32_t* a, const uint32_t* b) {
    asm volatile(
        "mma.sync.aligned.m16n8k16.row.col.f32.f16.f16.f32 "
        "{%0,%1,%2,%3}, {%4,%5,%6,%7}, {%8,%9}, {%0,%1,%2,%3};"
        : "+f"(c[0]), "+f"(c[1]), "+f"(c[2]), "+f"(c[3])
        : "r"(a[0]), "r"(a[1]), "r"(a[2]), "r"(a[3]), "r"(b[0]), "r"(b[1]));
}

// ---------------------------------------------------------------------------
// Bias table
// ---------------------------------------------------------------------------
__global__ void bias_table_kernel(const float* __restrict__ rel_bias) {
    int h = blockIdx.x;
    for (int idx = threadIdx.x; idx < 2 * SS - 1; idx += blockDim.x) {
        int rel = idx - (SS - 1);
        int base = (rel > 0) ? 16 : 0;
        int rp = rel < 0 ? -rel : rel;
        int bucket;
        if (rp < 8) {
            bucket = rp;
        } else {
            float v = logf((float)rp * 0.125f) / logf(16.0f) * 8.0f;
            int bb = 8 + (int)v;
            bucket = bb < 15 ? bb : 15;
        }
        g_bias[h * (2 * SS - 1) + idx] = rel_bias[(base + bucket) * NH + h];
    }
}

// ---------------------------------------------------------------------------
// Split hidden_states: fp32 -> bf16 hi + bf16 lo
// ---------------------------------------------------------------------------
__global__ void split_kernel(const float4* __restrict__ src) {
    int i = blockIdx.x * blockDim.x + threadIdx.x;
    float4 x = src[i];
    __nv_bfloat162 hA = __floats2bfloat162_rn(x.x, x.y);
    __nv_bfloat162 hB = __floats2bfloat162_rn(x.z, x.w);
    __nv_bfloat162 lA = __floats2bfloat162_rn(x.x - __bfloat162float(hA.x),
                                              x.y - __bfloat162float(hA.y));
    __nv_bfloat162 lB = __floats2bfloat162_rn(x.z - __bfloat162float(hB.x),
                                              x.w - __bfloat162float(hB.y));
    *(__nv_bfloat162*)(g_xh + 4 * i) = hA;
    *(__nv_bfloat162*)(g_xh + 4 * i + 2) = hB;
    *(__nv_bfloat162*)(g_xl + 4 * i) = lA;
    *(__nv_bfloat162*)(g_xl + 4 * i + 2) = lB;
}

// transpose + split weights: z<3 -> bf16 hi/lo; z==3 -> fp16 single (Wo)
__global__ void tsplit_kernel(const float* __restrict__ W0, const float* __restrict__ W1,
                              const float* __restrict__ W2, const float* __restrict__ W3) {
    __shared__ float t[32][33];
    int z = blockIdx.z;
    const float* W = z == 0 ? W0 : z == 1 ? W1 : z == 2 ? W2 : W3;
    int k0 = blockIdx.x * 32, n0 = blockIdx.y * 32;
    int tx = threadIdx.x, ty = threadIdx.y;
#pragma unroll
    for (int r = 0; r < 32; r += 8)
        t[ty + r][tx] = W[(size_t)(k0 + ty + r) * DM + n0 + tx];
    __syncthreads();
#pragma unroll
    for (int r = 0; r < 32; r += 8) {
        float x = t[tx][ty + r];
        size_t o = (size_t)(n0 + ty + r) * DM + k0 + tx;
        if (z < 3) {
            __nv_bfloat16 h = __float2bfloat16_rn(x);
            g_wth[(size_t)z * DM * DM + o] = h;
            g_wtl[(size_t)z * DM * DM + o] =
                __float2bfloat16_rn(x - __bfloat162float(h));
        } else {
            g_wo16[o] = __float2half_rn(x);
        }
    }
}

// ---------------------------------------------------------------------------
// QKV GEMM: bf16x3, BM=BN=128, BK=32, 8 warps, 2-stage ring, 2 blocks/SM.
// ---------------------------------------------------------------------------
#define LDK 40
#define A_PER (128 * LDK * 2)          // 10240
#define B_PER (128 * LDK * 2)
#define BOFF (2 * A_PER)
#define STAGE (2 * A_PER + 2 * B_PER)  // 40960
#define GSMEM (2 * STAGE)              // 81920

__global__ void __launch_bounds__(256, 2) gemm_qkv_kernel() {
    const int mode = blockIdx.z;
    const __nv_bfloat16* Ah = g_xh;
    const __nv_bfloat16* Al = g_xl;
    const __nv_bfloat16* Bh = g_wth + (size_t)mode * DM * DM;
    const __nv_bfloat16* Bl = g_wtl + (size_t)mode * DM * DM;

    extern __shared__ char sm[];
    const uint32_t smb = smem_u32(sm);
    const int tid = threadIdx.x;
    const int wid = tid >> 5, lane = tid & 31;
    const int wm = wid >> 1, wn = wid & 1;
    const int bm = blockIdx.x * 128, bn = blockIdx.y * 128;

    float acc[2][8][4];
#pragma unroll
    for (int i = 0; i < 2; i++)
#pragma unroll
        for (int j = 0; j < 8; j++)
#pragma unroll
            for (int q = 0; q < 4; q++) acc[i][j][q] = 0.0f;

    const uint32_t aRel = (uint32_t)((wm * 32 + (lane & 15)) * LDK + (lane >> 4) * 8) * 2;
    const uint32_t bRel = (uint32_t)BOFF +
        (uint32_t)((wn * 64 + ((lane >> 4) & 1) * 8 + (lane & 7)) * LDK +
                   ((lane >> 3) & 1) * 8) * 2;

    auto load_stage = [&](int c) {
        uint32_t st = smb + (uint32_t)(c & 1) * STAGE;
        int k0 = c * 32;
#pragma unroll
        for (int i = 0; i < 2; i++) {
            int e = tid + 256 * i;
            int row = e >> 2, kq = e & 3;
            uint32_t d = st + (uint32_t)(row * LDK + kq * 8) * 2;
            size_t ga = (size_t)(bm + row) * DM + k0 + kq * 8;
            size_t gb = (size_t)(bn + row) * DM + k0 + kq * 8;
            cp16(d, Ah + ga);
            cp16(d + A_PER, Al + ga);
            cp16(d + BOFF, Bh + gb);
            cp16(d + BOFF + B_PER, Bl + gb);
        }
    };

    load_stage(0);
    CP_COMMIT();

    for (int c = 0; c < 32; ++c) {
        CP_WAIT(0);
        __syncthreads();
        uint32_t st = smb + (uint32_t)(c & 1) * STAGE;
        uint32_t aBase = st + aRel, bBase = st + bRel;
#pragma unroll
        for (int ks = 0; ks < 2; ++ks) {
            uint32_t koff = ks * 32;
            uint32_t aH[2][4], aL[2][4];
#pragma unroll
            for (int mf = 0; mf < 2; ++mf) {
                ldsm_x4(aH[mf], aBase + koff + mf * (16 * LDK * 2));
                ldsm_x4(aL[mf], aBase + koff + mf * (16 * LDK * 2) + A_PER);
            }
#pragma unroll
            for (int p = 0; p < 4; ++p) {
                uint32_t bH[4], bL[4];
                uint32_t ba = bBase + koff + p * (16 * LDK * 2);
                ldsm_x4(bH, ba);
                ldsm_x4(bL, ba + B_PER);
#pragma unroll
                for (int mf = 0; mf < 2; ++mf) {
                    mma16816(acc[mf][2 * p], aH[mf], &bH[0]);
                    mma16816(acc[mf][2 * p + 1], aH[mf], &bH[2]);
                }
#pragma unroll
                for (int mf = 0; mf < 2; ++mf) {
                    mma16816(acc[mf][2 * p], aH[mf], &bL[0]);
                    mma16816(acc[mf][2 * p + 1], aH[mf], &bL[2]);
                }
#pragma unroll
                for (int mf = 0; mf < 2; ++mf) {
                    mma16816(acc[mf][2 * p], aL[mf], &bH[0]);
                    mma16816(acc[mf][2 * p + 1], aL[mf], &bH[2]);
                }
            }
            if (ks == 0 && c + 1 < 32) {   // mid-chunk prefetch (de-burst LSU)
                load_stage(c + 1);
                CP_COMMIT();
            }
        }
    }

    const int g = lane >> 2, t2 = (lane & 3) * 2;
#pragma unroll
    for (int mf = 0; mf < 2; ++mf) {
#pragma unroll
        for (int nf = 0; nf < 8; ++nf) {
            int n = bn + wn * 64 + nf * 8 + t2;
            int m0 = bm + wm * 32 + mf * 16 + g;
            int m1 = m0 + 8;
            int hh = n >> 6, d = n & 63;
            size_t o0 = (((size_t)(m0 >> 11) * NH + hh) * SS + (m0 & (SS - 1))) * DK + d;
            size_t o1 = (((size_t)(m1 >> 11) * NH + hh) * SS + (m1 & (SS - 1))) * DK + d;
            float v0 = acc[mf][nf][0], v1 = acc[mf][nf][1];
            float v2 = acc[mf][nf][2], v3 = acc[mf][nf][3];
            if (mode == 2) {
                *(__half2*)(g_v16 + o0) = __floats2half2_rn(v0, v1);
                *(__half2*)(g_v16 + o1) = __floats2half2_rn(v2, v3);
            } else {
                __nv_bfloat16* Oh = mode == 0 ? g_qh : g_kh;
                __nv_bfloat16* Ol = mode == 0 ? g_ql : g_kl;
                __nv_bfloat162 h0 = __floats2bfloat162_rn(v0, v1);
                __nv_bfloat162 l0 = __floats2bfloat162_rn(v0 - __bfloat162float(h0.x),
                                                          v1 - __bfloat162float(h0.y));
                __nv_bfloat162 h1 = __floats2bfloat162_rn(v2, v3);
                __nv_bfloat162 l1 = __floats2bfloat162_rn(v2 - __bfloat162float(h1.x),
                                                          v3 - __bfloat162float(h1.y));
                *(__nv_bfloat162*)(Oh + o0) = h0;
                *(__nv_bfloat162*)(Ol + o0) = l0;
                *(__nv_bfloat162*)(Oh + o1) = h1;
                *(__nv_bfloat162*)(Ol + o1) = l1;
            }
        }
    }
}

// ---------------------------------------------------------------------------
// Output GEMM: fp16 2-term (ctx split exact, Wo single). BM=BN=128, BK=32.
// ---------------------------------------------------------------------------
#define OBOFF (2 * A_PER)                  // Ah, Al, then Bh
#define OSTAGE (3 * A_PER)                 // 30720
#define OGSMEM (2 * OSTAGE)                // 61440

__global__ void __launch_bounds__(256, 2) gemm_out_kernel(float* __restrict__ outp) {
    const __half* Ah = g_ch;
    const __half* Al = g_cl;
    const __half* Bh = g_wo16;

    extern __shared__ char sm[];
    const uint32_t smb = smem_u32(sm);
    const int tid = threadIdx.x;
    const int wid = tid >> 5, lane = tid & 31;
    const int wm = wid >> 1, wn = wid & 1;
    const int bm = blockIdx.x * 128, bn = blockIdx.y * 128;

    float acc[2][8][4];
#pragma unroll
    for (int i = 0; i < 2; i++)
#pragma unroll
        for (int j = 0; j < 8; j++)
#pragma unroll
            for (int q = 0; q < 4; q++) acc[i][j][q] = 0.0f;

    const uint32_t aRel = (uint32_t)((wm * 32 + (lane & 15)) * LDK + (lane >> 4) * 8) * 2;
    const uint32_t bRel = (uint32_t)OBOFF +
        (uint32_t)((wn * 64 + ((lane >> 4) & 1) * 8 + (lane & 7)) * LDK +
                   ((lane >> 3) & 1) * 8) * 2;

    auto load_stage = [&](int c) {
        uint32_t st = smb + (uint32_t)(c & 1) * OSTAGE;
        int k0 = c * 32;
#pragma unroll
        for (int i = 0; i < 2; i++) {
            int e = tid + 256 * i;
            int row = e >> 2, kq = e & 3;
            uint32_t d = st + (uint32_t)(row * LDK + kq * 8) * 2;
            size_t ga = (size_t)(bm + row) * DM + k0 + kq * 8;
            size_t gb = (size_t)(bn + row) * DM + k0 + kq * 8;
            cp16(d, Ah + ga);
            cp16(d + A_PER, Al + ga);
            cp16(d + OBOFF, Bh + gb);
        }
    };

    load_stage(0);
    CP_COMMIT();

    for (int c = 0; c < 32; ++c) {
        CP_WAIT(0);
        __syncthreads();
        uint32_t st = smb + (uint32_t)(c & 1) * OSTAGE;
        uint32_t aBase = st + aRel, bBase = st + bRel;
#pragma unroll
        for (int ks = 0; ks < 2; ++ks) {
            uint32_t koff = ks * 32;
            uint32_t aH[2][4], aL[2][4];
#pragma unroll
            for (int mf = 0; mf < 2; ++mf) {
                ldsm_x4(aH[mf], aBase + koff + mf * (16 * LDK * 2));
                ldsm_x4(aL[mf], aBase + koff + mf * (16 * LDK * 2) + A_PER);
            }
#pragma unroll
            for (int p = 0; p < 4; ++p) {
                uint32_t bH[4];
                ldsm_x4(bH, bBase + koff + p * (16 * LDK * 2));
#pragma unroll
                for (int mf = 0; mf < 2; ++mf) {
                    mma16816h(acc[mf][2 * p], aH[mf], &bH[0]);
                    mma16816h(acc[mf][2 * p + 1], aH[mf], &bH[2]);
                }
#pragma unroll
                for (int mf = 0; mf < 2; ++mf) {
                    mma16816h(acc[mf][2 * p], aL[mf], &bH[0]);
                    mma16816h(acc[mf][2 * p + 1], aL[mf], &bH[2]);
                }
            }
            if (ks == 0 && c + 1 < 32) {
                load_stage(c + 1);
                CP_COMMIT();
            }
        }
    }

    const int g = lane >> 2, t2 = (lane & 3) * 2;
#pragma unroll
    for (int mf = 0; mf < 2; ++mf) {
#pragma unroll
        for (int nf = 0; nf < 8; ++nf) {
            int n = bn + wn * 64 + nf * 8 + t2;
            int m0 = bm + wm * 32 + mf * 16 + g;
            int m1 = m0 + 8;
            *(float2*)(outp + (size_t)m0 * DM + n) =
                make_float2(acc[mf][nf][0], acc[mf][nf][1]);
            *(float2*)(outp + (size_t)m1 * DM + n) =
                make_float2(acc[mf][nf][2], acc[mf][nf][3]);
        }
    }
}

// ---------------------------------------------------------------------------
// Flash attention: QK bf16x3 (unchanged), PV fp16x2 (P split, V single).
// ---------------------------------------------------------------------------
#define FPB 144
#define Q_BYTES (128 * FPB)
#define KV_BYTES (64 * FPB)
#define STG_OFF (2 * Q_BYTES)
#define STG_SZ (3 * KV_BYTES)            // kh, kl, v16
#define BIAS_OFF (STG_OFF + 2 * STG_SZ)  // 92160
#define FSMEM (BIAS_OFF + 2 * 192 * 4)   // 93696

__global__ void __launch_bounds__(256) flash_kernel() {
    extern __shared__ char sm[];
    const uint32_t smb = smem_u32(sm);
    const int tid = threadIdx.x, wid = tid >> 5, lane = tid & 31;
    const int g = lane >> 2, tq = lane & 3;
    const int qt = blockIdx.x, h = blockIdx.y, b = blockIdx.z;
    const int bh = b * NH + h;

    const __nv_bfloat16* Qh = g_qh + ((size_t)bh * SS + qt * 128) * DK;
    const __nv_bfloat16* Ql = g_ql + ((size_t)bh * SS + qt * 128) * DK;
    const __nv_bfloat16* Kh = g_kh + (size_t)bh * SS * DK;
    const __nv_bfloat16* Kl = g_kl + (size_t)bh * SS * DK;
    const __half* Vg = g_v16 + (size_t)bh * SS * DK;
    float* bw = (float*)(sm + BIAS_OFF);

#pragma unroll
    for (int i = 0; i < 4; i++) {
        int e = tid + 256 * i;
        int row = e >> 3, qd = e & 7;
        uint32_t d = smb + row * FPB + qd * 16;
        cp16(d, Qh + row * DK + qd * 8);
        cp16(d + Q_BYTES, Ql + row * DK + qd * 8);
    }

    auto load_kv = [&](int c) {
        uint32_t st = smb + STG_OFF + (uint32_t)(c & 1) * STG_SZ;
#pragma unroll
        for (int i = 0; i < 2; i++) {
            int e = tid + 256 * i;
            int row = e >> 3, qd = e & 7;
            uint32_t d = st + row * FPB + qd * 16;
            size_t src = (size_t)(c * 64 + row) * DK + qd * 8;
            cp16(d, Kh + src);
            cp16(d + KV_BYTES, Kl + src);
            cp16(d + 2 * KV_BYTES, Vg + src);
        }
    };
    auto load_bias = [&](int c) {
        if (tid < 191) {
            int base = h * (2 * SS - 1) + c * 64 - qt * 128 + 1920;
            bw[(c & 1) * 192 + tid] = g_bias[base + tid];
        }
    };

    load_kv(0);
    CP_COMMIT();
    load_bias(0);

    float m_[2] = {-INFINITY, -INFINITY};
    float l_[2] = {0.0f, 0.0f};
    float o[8][4];
#pragma unroll
    for (int j = 0; j < 8; j++)
#pragma unroll
        for (int q = 0; q < 4; q++) o[j][q] = 0.0f;

    const uint32_t aAddr = smb + (uint32_t)(wid * 16 + (lane & 15)) * FPB + (lane >> 4) * 16;
    const uint32_t bRel = (uint32_t)((((lane >> 4) & 1) * 8 + (lane & 7)) * FPB +
                                     ((lane >> 3) & 1) * 16);
    const uint32_t vRel = (uint32_t)((lane & 15) * FPB + (lane >> 4) * 16);
    const int r0 = wid * 16 + g;

    for (int kt = 0; kt < 32; ++kt) {
        CP_WAIT(0);
        __syncthreads();
        if (kt < 31) {
            load_kv(kt + 1);
            CP_COMMIT();
            load_bias(kt + 1);
        }
        uint32_t stg = smb + STG_OFF + (uint32_t)(kt & 1) * STG_SZ;
        const float* bwc = bw + (kt & 1) * 192;

        // ---- S = Qh Kh^T + Qh Kl^T + Ql Kh^T (bf16x3, term-major) ----
        float s[8][4];
#pragma unroll
        for (int j = 0; j < 8; j++)
#pragma unroll
            for (int q = 0; q < 4; q++) s[j][q] = 0.0f;
#pragma unroll
        for (int kk = 0; kk < 4; ++kk) {
            uint32_t aH[4], aL[4], bH[4][4], bL[4][4];
            ldsm_x4(aH, aAddr + kk * 32);
            ldsm_x4(aL, aAddr + kk * 32 + Q_BYTES);
#pragma unroll
            for (int p = 0; p < 4; ++p) {
                uint32_t ba = stg + bRel + p * (16 * FPB) + kk * 32;
                ldsm_x4(bH[p], ba);
                ldsm_x4(bL[p], ba + KV_BYTES);
            }
#pragma unroll
            for (int p = 0; p < 4; ++p) {
                mma16816(s[2 * p], aH, &bH[p][0]);
                mma16816(s[2 * p + 1], aH, &bH[p][2]);
            }
#pragma unroll
            for (int p = 0; p < 4; ++p) {
                mma16816(s[2 * p], aH, &bL[p][0]);
                mma16816(s[2 * p + 1], aH, &bL[p][2]);
            }
#pragma unroll
            for (int p = 0; p < 4; ++p) {
                mma16816(s[2 * p], aL, &bH[p][0]);
                mma16816(s[2 * p + 1], aL, &bH[p][2]);
            }
        }

        // ---- bias + online softmax ----
        float mx0 = -INFINITY, mx1 = -INFINITY;
#pragma unroll
        for (int j = 0; j < 8; j++) {
            int c = 8 * j + 2 * tq;
            s[j][0] += bwc[c - r0 + 127];
            s[j][1] += bwc[c + 1 - r0 + 127];
            s[j][2] += bwc[c - (r0 + 8) + 127];
            s[j][3] += bwc[c + 1 - (r0 + 8) + 127];
            mx0 = fmaxf(mx0, fmaxf(s[j][0], s[j][1]));
            mx1 = fmaxf(mx1, fmaxf(s[j][2], s[j][3]));
        }
        mx0 = fmaxf(mx0, __shfl_xor_sync(0xffffffffu, mx0, 1));
        mx0 = fmaxf(mx0, __shfl_xor_sync(0xffffffffu, mx0, 2));
        mx1 = fmaxf(mx1, __shfl_xor_sync(0xffffffffu, mx1, 1));
        mx1 = fmaxf(mx1, __shfl_xor_sync(0xffffffffu, mx1, 2));
        float mn0 = fmaxf(m_[0], mx0), mn1 = fmaxf(m_[1], mx1);
        float al0 = __expf(m_[0] - mn0), al1 = __expf(m_[1] - mn1);

        // P split into exact fp16 hi/lo
        uint32_t pH[8][2], pL[8][2];
        float sum0 = 0.0f, sum1 = 0.0f;
#pragma unroll
        for (int j = 0; j < 8; j++) {
            float e0 = __expf(s[j][0] - mn0), e1 = __expf(s[j][1] - mn0);
            float e2 = __expf(s[j][2] - mn1), e3 = __expf(s[j][3] - mn1);
            sum0 += e0 + e1;
            sum1 += e2 + e3;
            __half2 h01 = __floats2half2_rn(e0, e1);
            __half2 h23 = __floats2half2_rn(e2, e3);
            __half2 l01 = __floats2half2_rn(e0 - __low2float(h01),
                                            e1 - __high2float(h01));
            __half2 l23 = __floats2half2_rn(e2 - __low2float(h23),
                                            e3 - __high2float(h23));
            pH[j][0] = *(uint32_t*)&h01;
            pH[j][1] = *(uint32_t*)&h23;
            pL[j][0] = *(uint32_t*)&l01;
            pL[j][1] = *(uint32_t*)&l23;
        }
        sum0 += __shfl_xor_sync(0xffffffffu, sum0, 1);
        sum0 += __shfl_xor_sync(0xffffffffu, sum0, 2);
        sum1 += __shfl_xor_sync(0xffffffffu, sum1, 1);
        sum1 += __shfl_xor_sync(0xffffffffu, sum1, 2);
        l_[0] = l_[0] * al0 + sum0;
        l_[1] = l_[1] * al1 + sum1;
        m_[0] = mn0;
        m_[1] = mn1;
#pragma unroll
        for (int j = 0; j < 8; j++) {
            o[j][0] *= al0; o[j][1] *= al0;
            o[j][2] *= al1; o[j][3] *= al1;
        }

        // ---- O += P V (fp16 x2: Ph*V + Pl*V) ----
        uint32_t vstg = stg + 2 * KV_BYTES;
#pragma unroll
        for (int kk = 0; kk < 4; ++kk) {
            uint32_t aPh[4] = {pH[2 * kk][0], pH[2 * kk][1],
                               pH[2 * kk + 1][0], pH[2 * kk + 1][1]};
            uint32_t aPl[4] = {pL[2 * kk][0], pL[2 * kk][1],
                               pL[2 * kk + 1][0], pL[2 * kk + 1][1]};
            uint32_t vh[4][4];
#pragma unroll
            for (int p = 0; p < 4; ++p)
                ldsm_x4_t(vh[p], vstg + vRel + kk * (16 * FPB) + p * 32);
#pragma unroll
            for (int p = 0; p < 4; ++p) {
                mma16816h(o[2 * p], aPh, &vh[p][0]);
                mma16816h(o[2 * p + 1], aPh, &vh[p][2]);
            }
#pragma unroll
            for (int p = 0; p < 4; ++p) {
                mma16816h(o[2 * p], aPl, &vh[p][0]);
                mma16816h(o[2 * p + 1], aPl, &vh[p][2]);
            }
        }
    }

    // ---- epilogue: ctx = O / l, exact fp16 hi/lo ----
    float inv0 = 1.0f / l_[0], inv1 = 1.0f / l_[1];
    size_t rbase = (size_t)b * SS + qt * 128 + wid * 16 + g;
#pragma unroll
    for (int j = 0; j < 8; j++) {
        int col = h * DK + 8 * j + 2 * tq;
        float x0 = o[j][0] * inv0, x1 = o[j][1] * inv0;
        float x2 = o[j][2] * inv1, x3 = o[j][3] * inv1;
        __half2 h0 = __floats2half2_rn(x0, x1);
        __half2 l0 = __floats2half2_rn(x0 - __low2float(h0), x1 - __high2float(h0));
        __half2 h1 = __floats2half2_rn(x2, x3);
        __half2 l1 = __floats2half2_rn(x2 - __low2float(h1), x3 - __high2float(h1));
        *(__half2*)(g_ch + rbase * DM + col) = h0;
        *(__half2*)(g_cl + rbase * DM + col) = l0;
        *(__half2*)(g_ch + (rbase + 8) * DM + col) = h1;
        *(__half2*)(g_cl + (rbase + 8) * DM + col) = l1;
    }
}

// ---------------------------------------------------------------------------
extern "C" void kernel_launch(void* const* d_in, const int* in_sizes, int n_in,
                              void* d_out, int out_size) {
    const float* hs = (const float*)d_in[0];
    const float* Wq = (const float*)d_in[1];
    const float* Wk = (const float*)d_in[2];
    const float* Wv = (const float*)d_in[3];
    const float* Wo = (const float*)d_in[4];
    const float* rb = (const float*)d_in[5];

    cudaFuncSetAttribute(flash_kernel,
                         cudaFuncAttributeMaxDynamicSharedMemorySize, FSMEM);
    cudaFuncSetAttribute(gemm_qkv_kernel,
                         cudaFuncAttributeMaxDynamicSharedMemorySize, GSMEM);
    cudaFuncSetAttribute(gemm_out_kernel,
                         cudaFuncAttributeMaxDynamicSharedMemorySize, OGSMEM);

    bias_table_kernel<<<NH, 256>>>(rb);
    split_kernel<<<(MTOT * DM / 4) / 256, 256>>>((const float4*)hs);
    tsplit_kernel<<<dim3(32, 32, 4), dim3(32, 8)>>>(Wq, Wk, Wv, Wo);
    gemm_qkv_kernel<<<dim3(MTOT / 128, DM / 128, 3), 256, GSMEM>>>();
    flash_kernel<<<dim3(SS / 128, NH, BB), 256, FSMEM>>>();
    gemm_out_kernel<<<dim3(MTOT / 128, DM / 128), 256, OGSMEM>>>((float*)d_out);
}

// round 9
// speedup vs baseline: 4.2444x; 1.1011x over previous
#include <cuda_runtime.h>
#include <cuda_bf16.h>
#include <cuda_fp16.h>
#include <math.h>
#include <stdint.h>

#define BB 2
#define SS 2048
#define DM 1024
#define NH 16
#define DK 64
#define MTOT (BB * SS)  // 4096

// ---------------- device scratch (allocation-free) ----------------
__device__ float g_bias[NH * (2 * SS - 1)];
__device__ __nv_bfloat16 g_xh[MTOT * DM];     // x bf16 hi/lo (for q,k)
__device__ __nv_bfloat16 g_xl[MTOT * DM];
__device__ __half        g_xh16[MTOT * DM];   // x fp16 hi/lo (for v)
__device__ __half        g_xl16[MTOT * DM];
__device__ __nv_bfloat16 g_wth[2 * DM * DM];  // Wq/Wk ^T hi (K-major)
__device__ __nv_bfloat16 g_wtl[2 * DM * DM];  // lo
__device__ __half        g_wv16[DM * DM];     // Wv^T single fp16
__device__ __half        g_wo16[DM * DM];     // Wo^T single fp16
__device__ __half        g_ch[MTOT * DM];     // ctx fp16 hi (exact split)
__device__ __half        g_cl[MTOT * DM];     // ctx fp16 lo
__device__ __nv_bfloat16 g_qh[BB * NH * SS * DK];
__device__ __nv_bfloat16 g_ql[BB * NH * SS * DK];
__device__ __nv_bfloat16 g_kh[BB * NH * SS * DK];
__device__ __nv_bfloat16 g_kl[BB * NH * SS * DK];
__device__ __half        g_v16[BB * NH * SS * DK];  // V single fp16

// ---------------- PTX helpers (arch-agnostic, sm_80-era) ----------------
__device__ __forceinline__ uint32_t smem_u32(const void* p) {
    uint32_t a;
    asm("{ .reg .u64 t; cvta.to.shared.u64 t, %1; cvt.u32.u64 %0, t; }"
        : "=r"(a) : "l"(p));
    return a;
}
__device__ __forceinline__ void cp16(uint32_t dst, const void* src) {
    uint64_t g = __cvta_generic_to_global(src);
    asm volatile("cp.async.cg.shared.global [%0], [%1], 16;" :: "r"(dst), "l"(g));
}
#define CP_COMMIT() asm volatile("cp.async.commit_group;" ::: "memory")
#define CP_WAIT(n)  asm volatile("cp.async.wait_group %0;" :: "n"(n) : "memory")

__device__ __forceinline__ void ldsm_x4(uint32_t* r, uint32_t addr) {
    asm volatile("ldmatrix.sync.aligned.m8n8.x4.shared.b16 {%0,%1,%2,%3}, [%4];"
                 : "=r"(r[0]), "=r"(r[1]), "=r"(r[2]), "=r"(r[3]) : "r"(addr));
}
__device__ __forceinline__ void ldsm_x4_t(uint32_t* r, uint32_t addr) {
    asm volatile("ldmatrix.sync.aligned.m8n8.x4.trans.shared.b16 {%0,%1,%2,%3}, [%4];"
                 : "=r"(r[0]), "=r"(r[1]), "=r"(r[2]), "=r"(r[3]) : "r"(addr));
}
__device__ __forceinline__ void mma16816(float* c, const uint32_t* a, const uint32_t* b) {
    asm volatile(
        "mma.sync.aligned.m16n8k16.row.col.f32.bf16.bf16.f32 "
        "{%0,%1,%2,%3}, {%4,%5,%6,%7}, {%8,%9}, {%0,%1,%2,%3};"
        : "+f"(c[0]), "+f"(c[1]), "+f"(c[2]), "+f"(c[3])
        : "r"(a[0]), "r"(a[1]), "r"(a[2]), "r"(a[3]), "r"(b[0]), "r"(b[1]));
}
__device__ __forceinline__ void mma16816h(float* c, const uint32_t* a, const uint32_t* b) {
    asm volatile(
        "mma.sync.aligned.m16n8k16.row.col.f32.f16.f16.f32 "
        "{%0,%1,%2,%3}, {%4,%5,%6,%7}, {%8,%9}, {%0,%1,%2,%3};"
        : "+f"(c[0]), "+f"(c[1]), "+f"(c[2]), "+f"(c[3])
        : "r"(a[0]), "r"(a[1]), "r"(a[2]), "r"(a[3]), "r"(b[0]), "r"(b[1]));
}

// ---------------------------------------------------------------------------
// Bias table
// ---------------------------------------------------------------------------
__global__ void bias_table_kernel(const float* __restrict__ rel_bias) {
    int h = blockIdx.x;
    for (int idx = threadIdx.x; idx < 2 * SS - 1; idx += blockDim.x) {
        int rel = idx - (SS - 1);
        int base = (rel > 0) ? 16 : 0;
        int rp = rel < 0 ? -rel : rel;
        int bucket;
        if (rp < 8) {
            bucket = rp;
        } else {
            float v = logf((float)rp * 0.125f) / logf(16.0f) * 8.0f;
            int bb = 8 + (int)v;
            bucket = bb < 15 ? bb : 15;
        }
        g_bias[h * (2 * SS - 1) + idx] = rel_bias[(base + bucket) * NH + h];
    }
}

// ---------------------------------------------------------------------------
// Split hidden_states: fp32 -> bf16 hi+lo (q/k path) AND fp16 hi+lo (v path)
// ---------------------------------------------------------------------------
__global__ void split_kernel(const float4* __restrict__ src) {
    int i = blockIdx.x * blockDim.x + threadIdx.x;
    float4 x = src[i];
    __nv_bfloat162 hA = __floats2bfloat162_rn(x.x, x.y);
    __nv_bfloat162 hB = __floats2bfloat162_rn(x.z, x.w);
    __nv_bfloat162 lA = __floats2bfloat162_rn(x.x - __bfloat162float(hA.x),
                                              x.y - __bfloat162float(hA.y));
    __nv_bfloat162 lB = __floats2bfloat162_rn(x.z - __bfloat162float(hB.x),
                                              x.w - __bfloat162float(hB.y));
    *(__nv_bfloat162*)(g_xh + 4 * i) = hA;
    *(__nv_bfloat162*)(g_xh + 4 * i + 2) = hB;
    *(__nv_bfloat162*)(g_xl + 4 * i) = lA;
    *(__nv_bfloat162*)(g_xl + 4 * i + 2) = lB;

    __half2 h16A = __floats2half2_rn(x.x, x.y);
    __half2 h16B = __floats2half2_rn(x.z, x.w);
    __half2 l16A = __floats2half2_rn(x.x - __low2float(h16A),
                                     x.y - __high2float(h16A));
    __half2 l16B = __floats2half2_rn(x.z - __low2float(h16B),
                                     x.w - __high2float(h16B));
    *(__half2*)(g_xh16 + 4 * i) = h16A;
    *(__half2*)(g_xh16 + 4 * i + 2) = h16B;
    *(__half2*)(g_xl16 + 4 * i) = l16A;
    *(__half2*)(g_xl16 + 4 * i + 2) = l16B;
}

// transpose + split weights: z<2 -> bf16 hi/lo (Wq,Wk); z==2 Wv fp16; z==3 Wo fp16
__global__ void tsplit_kernel(const float* __restrict__ W0, const float* __restrict__ W1,
                              const float* __restrict__ W2, const float* __restrict__ W3) {
    __shared__ float t[32][33];
    int z = blockIdx.z;
    const float* W = z == 0 ? W0 : z == 1 ? W1 : z == 2 ? W2 : W3;
    int k0 = blockIdx.x * 32, n0 = blockIdx.y * 32;
    int tx = threadIdx.x, ty = threadIdx.y;
#pragma unroll
    for (int r = 0; r < 32; r += 8)
        t[ty + r][tx] = W[(size_t)(k0 + ty + r) * DM + n0 + tx];
    __syncthreads();
#pragma unroll
    for (int r = 0; r < 32; r += 8) {
        float x = t[tx][ty + r];
        size_t o = (size_t)(n0 + ty + r) * DM + k0 + tx;
        if (z < 2) {
            __nv_bfloat16 h = __float2bfloat16_rn(x);
            g_wth[(size_t)z * DM * DM + o] = h;
            g_wtl[(size_t)z * DM * DM + o] =
                __float2bfloat16_rn(x - __bfloat162float(h));
        } else if (z == 2) {
            g_wv16[o] = __float2half_rn(x);
        } else {
            g_wo16[o] = __float2half_rn(x);
        }
    }
}

// ---------------------------------------------------------------------------
// QK GEMM: bf16x3, BM=BN=128, BK=32, 8 warps, 2-stage ring, 2 blocks/SM.
// ---------------------------------------------------------------------------
#define LDK 40
#define A_PER (128 * LDK * 2)          // 10240
#define B_PER (128 * LDK * 2)
#define BOFF (2 * A_PER)
#define STAGE (2 * A_PER + 2 * B_PER)  // 40960
#define GSMEM (2 * STAGE)              // 81920

__global__ void __launch_bounds__(256, 2) gemm_qk_kernel() {
    const int mode = blockIdx.z;  // 0 = q, 1 = k
    const __nv_bfloat16* Ah = g_xh;
    const __nv_bfloat16* Al = g_xl;
    const __nv_bfloat16* Bh = g_wth + (size_t)mode * DM * DM;
    const __nv_bfloat16* Bl = g_wtl + (size_t)mode * DM * DM;

    extern __shared__ char sm[];
    const uint32_t smb = smem_u32(sm);
    const int tid = threadIdx.x;
    const int wid = tid >> 5, lane = tid & 31;
    const int wm = wid >> 1, wn = wid & 1;
    const int bm = blockIdx.x * 128, bn = blockIdx.y * 128;

    float acc[2][8][4];
#pragma unroll
    for (int i = 0; i < 2; i++)
#pragma unroll
        for (int j = 0; j < 8; j++)
#pragma unroll
            for (int q = 0; q < 4; q++) acc[i][j][q] = 0.0f;

    const uint32_t aRel = (uint32_t)((wm * 32 + (lane & 15)) * LDK + (lane >> 4) * 8) * 2;
    const uint32_t bRel = (uint32_t)BOFF +
        (uint32_t)((wn * 64 + ((lane >> 4) & 1) * 8 + (lane & 7)) * LDK +
                   ((lane >> 3) & 1) * 8) * 2;

    auto load_stage = [&](int c) {
        uint32_t st = smb + (uint32_t)(c & 1) * STAGE;
        int k0 = c * 32;
#pragma unroll
        for (int i = 0; i < 2; i++) {
            int e = tid + 256 * i;
            int row = e >> 2, kq = e & 3;
            uint32_t d = st + (uint32_t)(row * LDK + kq * 8) * 2;
            size_t ga = (size_t)(bm + row) * DM + k0 + kq * 8;
            size_t gb = (size_t)(bn + row) * DM + k0 + kq * 8;
            cp16(d, Ah + ga);
            cp16(d + A_PER, Al + ga);
            cp16(d + BOFF, Bh + gb);
            cp16(d + BOFF + B_PER, Bl + gb);
        }
    };

    load_stage(0);
    CP_COMMIT();

    for (int c = 0; c < 32; ++c) {
        CP_WAIT(0);
        __syncthreads();
        uint32_t st = smb + (uint32_t)(c & 1) * STAGE;
        uint32_t aBase = st + aRel, bBase = st + bRel;
#pragma unroll
        for (int ks = 0; ks < 2; ++ks) {
            uint32_t koff = ks * 32;
            uint32_t aH[2][4], aL[2][4];
#pragma unroll
            for (int mf = 0; mf < 2; ++mf) {
                ldsm_x4(aH[mf], aBase + koff + mf * (16 * LDK * 2));
                ldsm_x4(aL[mf], aBase + koff + mf * (16 * LDK * 2) + A_PER);
            }
#pragma unroll
            for (int p = 0; p < 4; ++p) {
                uint32_t bH[4], bL[4];
                uint32_t ba = bBase + koff + p * (16 * LDK * 2);
                ldsm_x4(bH, ba);
                ldsm_x4(bL, ba + B_PER);
#pragma unroll
                for (int mf = 0; mf < 2; ++mf) {
                    mma16816(acc[mf][2 * p], aH[mf], &bH[0]);
                    mma16816(acc[mf][2 * p + 1], aH[mf], &bH[2]);
                }
#pragma unroll
                for (int mf = 0; mf < 2; ++mf) {
                    mma16816(acc[mf][2 * p], aH[mf], &bL[0]);
                    mma16816(acc[mf][2 * p + 1], aH[mf], &bL[2]);
                }
#pragma unroll
                for (int mf = 0; mf < 2; ++mf) {
                    mma16816(acc[mf][2 * p], aL[mf], &bH[0]);
                    mma16816(acc[mf][2 * p + 1], aL[mf], &bH[2]);
                }
            }
            if (ks == 0 && c + 1 < 32) {   // mid-chunk prefetch
                load_stage(c + 1);
                CP_COMMIT();
            }
        }
    }

    const int g = lane >> 2, t2 = (lane & 3) * 2;
#pragma unroll
    for (int mf = 0; mf < 2; ++mf) {
#pragma unroll
        for (int nf = 0; nf < 8; ++nf) {
            int n = bn + wn * 64 + nf * 8 + t2;
            int m0 = bm + wm * 32 + mf * 16 + g;
            int m1 = m0 + 8;
            int hh = n >> 6, d = n & 63;
            size_t o0 = (((size_t)(m0 >> 11) * NH + hh) * SS + (m0 & (SS - 1))) * DK + d;
            size_t o1 = (((size_t)(m1 >> 11) * NH + hh) * SS + (m1 & (SS - 1))) * DK + d;
            float v0 = acc[mf][nf][0], v1 = acc[mf][nf][1];
            float v2 = acc[mf][nf][2], v3 = acc[mf][nf][3];
            __nv_bfloat16* Oh = mode == 0 ? g_qh : g_kh;
            __nv_bfloat16* Ol = mode == 0 ? g_ql : g_kl;
            __nv_bfloat162 h0 = __floats2bfloat162_rn(v0, v1);
            __nv_bfloat162 l0 = __floats2bfloat162_rn(v0 - __bfloat162float(h0.x),
                                                      v1 - __bfloat162float(h0.y));
            __nv_bfloat162 h1 = __floats2bfloat162_rn(v2, v3);
            __nv_bfloat162 l1 = __floats2bfloat162_rn(v2 - __bfloat162float(h1.x),
                                                      v3 - __bfloat162float(h1.y));
            *(__nv_bfloat162*)(Oh + o0) = h0;
            *(__nv_bfloat162*)(Ol + o0) = l0;
            *(__nv_bfloat162*)(Oh + o1) = h1;
            *(__nv_bfloat162*)(Ol + o1) = l1;
        }
    }
}

// ---------------------------------------------------------------------------
// fp16 2-term GEMM body (A split hi/lo, B single). Used by V and output GEMMs.
// ---------------------------------------------------------------------------
#define OBOFF (2 * A_PER)                  // Ah, Al, then Bh
#define OSTAGE (3 * A_PER)                 // 30720
#define OGSMEM (2 * OSTAGE)                // 61440

__device__ __forceinline__ void gemm_fp16x2_body(
    const __half* __restrict__ Ah, const __half* __restrict__ Al,
    const __half* __restrict__ Bh, float* __restrict__ outp, int mode)
{   // mode 2: scatter v16;  mode 3: row-major fp32 out
    extern __shared__ char sm[];
    const uint32_t smb = smem_u32(sm);
    const int tid = threadIdx.x;
    const int wid = tid >> 5, lane = tid & 31;
    const int wm = wid >> 1, wn = wid & 1;
    const int bm = blockIdx.x * 128, bn = blockIdx.y * 128;

    float acc[2][8][4];
#pragma unroll
    for (int i = 0; i < 2; i++)
#pragma unroll
        for (int j = 0; j < 8; j++)
#pragma unroll
            for (int q = 0; q < 4; q++) acc[i][j][q] = 0.0f;

    const uint32_t aRel = (uint32_t)((wm * 32 + (lane & 15)) * LDK + (lane >> 4) * 8) * 2;
    const uint32_t bRel = (uint32_t)OBOFF +
        (uint32_t)((wn * 64 + ((lane >> 4) & 1) * 8 + (lane & 7)) * LDK +
                   ((lane >> 3) & 1) * 8) * 2;

    auto load_stage = [&](int c) {
        uint32_t st = smb + (uint32_t)(c & 1) * OSTAGE;
        int k0 = c * 32;
#pragma unroll
        for (int i = 0; i < 2; i++) {
            int e = tid + 256 * i;
            int row = e >> 2, kq = e & 3;
            uint32_t d = st + (uint32_t)(row * LDK + kq * 8) * 2;
            size_t ga = (size_t)(bm + row) * DM + k0 + kq * 8;
            size_t gb = (size_t)(bn + row) * DM + k0 + kq * 8;
            cp16(d, Ah + ga);
            cp16(d + A_PER, Al + ga);
            cp16(d + OBOFF, Bh + gb);
        }
    };

    load_stage(0);
    CP_COMMIT();

    for (int c = 0; c < 32; ++c) {
        CP_WAIT(0);
        __syncthreads();
        uint32_t st = smb + (uint32_t)(c & 1) * OSTAGE;
        uint32_t aBase = st + aRel, bBase = st + bRel;
#pragma unroll
        for (int ks = 0; ks < 2; ++ks) {
            uint32_t koff = ks * 32;
            uint32_t aH[2][4], aL[2][4];
#pragma unroll
            for (int mf = 0; mf < 2; ++mf) {
                ldsm_x4(aH[mf], aBase + koff + mf * (16 * LDK * 2));
                ldsm_x4(aL[mf], aBase + koff + mf * (16 * LDK * 2) + A_PER);
            }
#pragma unroll
            for (int p = 0; p < 4; ++p) {
                uint32_t bH[4];
                ldsm_x4(bH, bBase + koff + p * (16 * LDK * 2));
#pragma unroll
                for (int mf = 0; mf < 2; ++mf) {
                    mma16816h(acc[mf][2 * p], aH[mf], &bH[0]);
                    mma16816h(acc[mf][2 * p + 1], aH[mf], &bH[2]);
                }
#pragma unroll
                for (int mf = 0; mf < 2; ++mf) {
                    mma16816h(acc[mf][2 * p], aL[mf], &bH[0]);
                    mma16816h(acc[mf][2 * p + 1], aL[mf], &bH[2]);
                }
            }
            if (ks == 0 && c + 1 < 32) {
                load_stage(c + 1);
                CP_COMMIT();
            }
        }
    }

    const int g = lane >> 2, t2 = (lane & 3) * 2;
#pragma unroll
    for (int mf = 0; mf < 2; ++mf) {
#pragma unroll
        for (int nf = 0; nf < 8; ++nf) {
            int n = bn + wn * 64 + nf * 8 + t2;
            int m0 = bm + wm * 32 + mf * 16 + g;
            int m1 = m0 + 8;
            if (mode == 3) {
                *(float2*)(outp + (size_t)m0 * DM + n) =
                    make_float2(acc[mf][nf][0], acc[mf][nf][1]);
                *(float2*)(outp + (size_t)m1 * DM + n) =
                    make_float2(acc[mf][nf][2], acc[mf][nf][3]);
            } else {
                int hh = n >> 6, d = n & 63;
                size_t o0 = (((size_t)(m0 >> 11) * NH + hh) * SS + (m0 & (SS - 1))) * DK + d;
                size_t o1 = (((size_t)(m1 >> 11) * NH + hh) * SS + (m1 & (SS - 1))) * DK + d;
                *(__half2*)(g_v16 + o0) = __floats2half2_rn(acc[mf][nf][0], acc[mf][nf][1]);
                *(__half2*)(g_v16 + o1) = __floats2half2_rn(acc[mf][nf][2], acc[mf][nf][3]);
            }
        }
    }
}

__global__ void __launch_bounds__(256, 2) gemm_v_kernel() {
    gemm_fp16x2_body(g_xh16, g_xl16, g_wv16, nullptr, 2);
}
__global__ void __launch_bounds__(256, 2) gemm_out_kernel(float* __restrict__ outp) {
    gemm_fp16x2_body(g_ch, g_cl, g_wo16, outp, 3);
}

// ---------------------------------------------------------------------------
// Flash attention: QK bf16x3, PV fp16 single-term (P single, V single).
// ---------------------------------------------------------------------------
#define FPB 144
#define Q_BYTES (128 * FPB)
#define KV_BYTES (64 * FPB)
#define STG_OFF (2 * Q_BYTES)
#define STG_SZ (3 * KV_BYTES)            // kh, kl, v16
#define BIAS_OFF (STG_OFF + 2 * STG_SZ)  // 92160
#define FSMEM (BIAS_OFF + 2 * 192 * 4)   // 93696

__global__ void __launch_bounds__(256) flash_kernel() {
    extern __shared__ char sm[];
    const uint32_t smb = smem_u32(sm);
    const int tid = threadIdx.x, wid = tid >> 5, lane = tid & 31;
    const int g = lane >> 2, tq = lane & 3;
    const int qt = blockIdx.x, h = blockIdx.y, b = blockIdx.z;
    const int bh = b * NH + h;

    const __nv_bfloat16* Qh = g_qh + ((size_t)bh * SS + qt * 128) * DK;
    const __nv_bfloat16* Ql = g_ql + ((size_t)bh * SS + qt * 128) * DK;
    const __nv_bfloat16* Kh = g_kh + (size_t)bh * SS * DK;
    const __nv_bfloat16* Kl = g_kl + (size_t)bh * SS * DK;
    const __half* Vg = g_v16 + (size_t)bh * SS * DK;
    float* bw = (float*)(sm + BIAS_OFF);

#pragma unroll
    for (int i = 0; i < 4; i++) {
        int e = tid + 256 * i;
        int row = e >> 3, qd = e & 7;
        uint32_t d = smb + row * FPB + qd * 16;
        cp16(d, Qh + row * DK + qd * 8);
        cp16(d + Q_BYTES, Ql + row * DK + qd * 8);
    }

    auto load_kv = [&](int c) {
        uint32_t st = smb + STG_OFF + (uint32_t)(c & 1) * STG_SZ;
#pragma unroll
        for (int i = 0; i < 2; i++) {
            int e = tid + 256 * i;
            int row = e >> 3, qd = e & 7;
            uint32_t d = st + row * FPB + qd * 16;
            size_t src = (size_t)(c * 64 + row) * DK + qd * 8;
            cp16(d, Kh + src);
            cp16(d + KV_BYTES, Kl + src);
            cp16(d + 2 * KV_BYTES, Vg + src);
        }
    };
    auto load_bias = [&](int c) {
        if (tid < 191) {
            int base = h * (2 * SS - 1) + c * 64 - qt * 128 + 1920;
            bw[(c & 1) * 192 + tid] = g_bias[base + tid];
        }
    };

    load_kv(0);
    CP_COMMIT();
    load_bias(0);

    float m_[2] = {-INFINITY, -INFINITY};
    float l_[2] = {0.0f, 0.0f};
    float o[8][4];
#pragma unroll
    for (int j = 0; j < 8; j++)
#pragma unroll
        for (int q = 0; q < 4; q++) o[j][q] = 0.0f;

    const uint32_t aAddr = smb + (uint32_t)(wid * 16 + (lane & 15)) * FPB + (lane >> 4) * 16;
    const uint32_t bRel = (uint32_t)((((lane >> 4) & 1) * 8 + (lane & 7)) * FPB +
                                     ((lane >> 3) & 1) * 16);
    const uint32_t vRel = (uint32_t)((lane & 15) * FPB + (lane >> 4) * 16);
    const int r0 = wid * 16 + g;

    for (int kt = 0; kt < 32; ++kt) {
        CP_WAIT(0);
        __syncthreads();
        if (kt < 31) {
            load_kv(kt + 1);
            CP_COMMIT();
            load_bias(kt + 1);
        }
        uint32_t stg = smb + STG_OFF + (uint32_t)(kt & 1) * STG_SZ;
        const float* bwc = bw + (kt & 1) * 192;

        // ---- S = Qh Kh^T + Qh Kl^T + Ql Kh^T (bf16x3, term-major) ----
        float s[8][4];
#pragma unroll
        for (int j = 0; j < 8; j++)
#pragma unroll
            for (int q = 0; q < 4; q++) s[j][q] = 0.0f;
#pragma unroll
        for (int kk = 0; kk < 4; ++kk) {
            uint32_t aH[4], aL[4], bH[4][4], bL[4][4];
            ldsm_x4(aH, aAddr + kk * 32);
            ldsm_x4(aL, aAddr + kk * 32 + Q_BYTES);
#pragma unroll
            for (int p = 0; p < 4; ++p) {
                uint32_t ba = stg + bRel + p * (16 * FPB) + kk * 32;
                ldsm_x4(bH[p], ba);
                ldsm_x4(bL[p], ba + KV_BYTES);
            }
#pragma unroll
            for (int p = 0; p < 4; ++p) {
                mma16816(s[2 * p], aH, &bH[p][0]);
                mma16816(s[2 * p + 1], aH, &bH[p][2]);
            }
#pragma unroll
            for (int p = 0; p < 4; ++p) {
                mma16816(s[2 * p], aH, &bL[p][0]);
                mma16816(s[2 * p + 1], aH, &bL[p][2]);
            }
#pragma unroll
            for (int p = 0; p < 4; ++p) {
                mma16816(s[2 * p], aL, &bH[p][0]);
                mma16816(s[2 * p + 1], aL, &bH[p][2]);
            }
        }

        // ---- bias + online softmax ----
        float mx0 = -INFINITY, mx1 = -INFINITY;
#pragma unroll
        for (int j = 0; j < 8; j++) {
            int c = 8 * j + 2 * tq;
            s[j][0] += bwc[c - r0 + 127];
            s[j][1] += bwc[c + 1 - r0 + 127];
            s[j][2] += bwc[c - (r0 + 8) + 127];
            s[j][3] += bwc[c + 1 - (r0 + 8) + 127];
            mx0 = fmaxf(mx0, fmaxf(s[j][0], s[j][1]));
            mx1 = fmaxf(mx1, fmaxf(s[j][2], s[j][3]));
        }
        mx0 = fmaxf(mx0, __shfl_xor_sync(0xffffffffu, mx0, 1));
        mx0 = fmaxf(mx0, __shfl_xor_sync(0xffffffffu, mx0, 2));
        mx1 = fmaxf(mx1, __shfl_xor_sync(0xffffffffu, mx1, 1));
        mx1 = fmaxf(mx1, __shfl_xor_sync(0xffffffffu, mx1, 2));
        float mn0 = fmaxf(m_[0], mx0), mn1 = fmaxf(m_[1], mx1);
        float al0 = __expf(m_[0] - mn0), al1 = __expf(m_[1] - mn1);

        // P single fp16
        uint32_t pH[8][2];
        float sum0 = 0.0f, sum1 = 0.0f;
#pragma unroll
        for (int j = 0; j < 8; j++) {
            float e0 = __expf(s[j][0] - mn0), e1 = __expf(s[j][1] - mn0);
            float e2 = __expf(s[j][2] - mn1), e3 = __expf(s[j][3] - mn1);
            sum0 += e0 + e1;
            sum1 += e2 + e3;
            __half2 h01 = __floats2half2_rn(e0, e1);
            __half2 h23 = __floats2half2_rn(e2, e3);
            pH[j][0] = *(uint32_t*)&h01;
            pH[j][1] = *(uint32_t*)&h23;
        }
        sum0 += __shfl_xor_sync(0xffffffffu, sum0, 1);
        sum0 += __shfl_xor_sync(0xffffffffu, sum0, 2);
        sum1 += __shfl_xor_sync(0xffffffffu, sum1, 1);
        sum1 += __shfl_xor_sync(0xffffffffu, sum1, 2);
        l_[0] = l_[0] * al0 + sum0;
        l_[1] = l_[1] * al1 + sum1;
        m_[0] = mn0;
        m_[1] = mn1;
#pragma unroll
        for (int j = 0; j < 8; j++) {
            o[j][0] *= al0; o[j][1] *= al0;
            o[j][2] *= al1; o[j][3] *= al1;
        }

        // ---- O += P V (single fp16 term) ----
        uint32_t vstg = stg + 2 * KV_BYTES;
#pragma unroll
        for (int kk = 0; kk < 4; ++kk) {
            uint32_t aPh[4] = {pH[2 * kk][0], pH[2 * kk][1],
                               pH[2 * kk + 1][0], pH[2 * kk + 1][1]};
            uint32_t vh[4][4];
#pragma unroll
            for (int p = 0; p < 4; ++p)
                ldsm_x4_t(vh[p], vstg + vRel + kk * (16 * FPB) + p * 32);
#pragma unroll
            for (int p = 0; p < 4; ++p) {
                mma16816h(o[2 * p], aPh, &vh[p][0]);
                mma16816h(o[2 * p + 1], aPh, &vh[p][2]);
            }
        }
    }

    // ---- epilogue: ctx = O / l, exact fp16 hi/lo ----
    float inv0 = 1.0f / l_[0], inv1 = 1.0f / l_[1];
    size_t rbase = (size_t)b * SS + qt * 128 + wid * 16 + g;
#pragma unroll
    for (int j = 0; j < 8; j++) {
        int col = h * DK + 8 * j + 2 * tq;
        float x0 = o[j][0] * inv0, x1 = o[j][1] * inv0;
        float x2 = o[j][2] * inv1, x3 = o[j][3] * inv1;
        __half2 h0 = __floats2half2_rn(x0, x1);
        __half2 l0 = __floats2half2_rn(x0 - __low2float(h0), x1 - __high2float(h0));
        __half2 h1 = __floats2half2_rn(x2, x3);
        __half2 l1 = __floats2half2_rn(x2 - __low2float(h1), x3 - __high2float(h1));
        *(__half2*)(g_ch + rbase * DM + col) = h0;
        *(__half2*)(g_cl + rbase * DM + col) = l0;
        *(__half2*)(g_ch + (rbase + 8) * DM + col) = h1;
        *(__half2*)(g_cl + (rbase + 8) * DM + col) = l1;
    }
}

// ---------------------------------------------------------------------------
extern "C" void kernel_launch(void* const* d_in, const int* in_sizes, int n_in,
                              void* d_out, int out_size) {
    const float* hs = (const float*)d_in[0];
    const float* Wq = (const float*)d_in[1];
    const float* Wk = (const float*)d_in[2];
    const float* Wv = (const float*)d_in[3];
    const float* Wo = (const float*)d_in[4];
    const float* rb = (const float*)d_in[5];

    cudaFuncSetAttribute(flash_kernel,
                         cudaFuncAttributeMaxDynamicSharedMemorySize, FSMEM);
    cudaFuncSetAttribute(gemm_qk_kernel,
                         cudaFuncAttributeMaxDynamicSharedMemorySize, GSMEM);
    cudaFuncSetAttribute(gemm_v_kernel,
                         cudaFuncAttributeMaxDynamicSharedMemorySize, OGSMEM);
    cudaFuncSetAttribute(gemm_out_kernel,
                         cudaFuncAttributeMaxDynamicSharedMemorySize, OGSMEM);

    bias_table_kernel<<<NH, 256>>>(rb);
    split_kernel<<<(MTOT * DM / 4) / 256, 256>>>((const float4*)hs);
    tsplit_kernel<<<dim3(32, 32, 4), dim3(32, 8)>>>(Wq, Wk, Wv, Wo);
    gemm_qk_kernel<<<dim3(MTOT / 128, DM / 128, 2), 256, GSMEM>>>();
    gemm_v_kernel<<<dim3(MTOT / 128, DM / 128), 256, OGSMEM>>>();
    flash_kernel<<<dim3(SS / 128, NH, BB), 256, FSMEM>>>();
    gemm_out_kernel<<<dim3(MTOT / 128, DM / 128), 256, OGSMEM>>>((float*)d_out);
}